// round 3
// baseline (speedup 1.0000x reference)
#include <cuda_runtime.h>
#include <math.h>
#include <stdint.h>

// Problem constants
#define NTOK   110592          // 1024 windows * 108 tokens
#define NWIN   1024
#define WTOK   108
#define EDIM   256
#define NHEAD  4
#define HDIM   64

// ---------------- scratch (static device globals; no allocation) -------------
__device__ float g_XN [ (size_t)NTOK * 256 ];   // LN output (reused for LN1 and LN2)
__device__ float g_QKV[ (size_t)NTOK * 768 ];   // qkv
__device__ float g_O  [ (size_t)NTOK * 256 ];   // attention out (heads merged)
__device__ float g_P  [ (size_t)NTOK * 256 ];   // proj out, already W-rolled
__device__ float g_Y  [ (size_t)NTOK * 256 ];   // x + attn branch (residual base)
__device__ float g_H1 [ (size_t)NTOK * 1024 ];  // FC1+GELU out

// ---------------- helpers ----------------------------------------------------
__device__ __forceinline__ float warp_sum(float v){
    #pragma unroll
    for (int o = 16; o; o >>= 1) v += __shfl_xor_sync(0xffffffffu, v, o);
    return v;
}
__device__ __forceinline__ float warp_max(float v){
    #pragma unroll
    for (int o = 16; o; o >>= 1) v = fmaxf(v, __shfl_xor_sync(0xffffffffu, v, o));
    return v;
}

// ---------------- LN1 with shift + window gather ------------------------------
// token t = n*108 + w ; n = b*32 + f ; source frame = (4f + w/27 + 2) mod 128
__global__ void ln1_kernel(const float* __restrict__ x,
                           const float* __restrict__ g,
                           const float* __restrict__ be)
{
    const int warp = threadIdx.x >> 5, lane = threadIdx.x & 31;
    const int t = blockIdx.x * 8 + warp;
    const int n = t / WTOK, w = t - n * WTOK;
    const int b = n >> 5, f = n & 31;
    const int wf = w / 27;
    const int gf = f * 4 + wf;
    const int fr = (gf + 2) & 127;
    const int kp = w - wf * 27;
    const float* src = x + (size_t)((b * 128 + fr) * 27 + kp) * 256;

    float4 v0 = ((const float4*)src)[lane];
    float4 v1 = ((const float4*)src)[lane + 32];
    float s = v0.x+v0.y+v0.z+v0.w + v1.x+v1.y+v1.z+v1.w;
    float q = v0.x*v0.x+v0.y*v0.y+v0.z*v0.z+v0.w*v0.w
            + v1.x*v1.x+v1.y*v1.y+v1.z*v1.z+v1.w*v1.w;
    s = warp_sum(s); q = warp_sum(q);
    const float mean = s * (1.0f/256.0f);
    const float var  = q * (1.0f/256.0f) - mean*mean;
    const float rstd = rsqrtf(var + 1e-5f);

    float* dst = g_XN + (size_t)t * 256;
    const int c0 = lane*4, c1 = 128 + lane*4;
    float4 o0, o1;
    o0.x = (v0.x-mean)*rstd*g[c0+0] + be[c0+0];
    o0.y = (v0.y-mean)*rstd*g[c0+1] + be[c0+1];
    o0.z = (v0.z-mean)*rstd*g[c0+2] + be[c0+2];
    o0.w = (v0.w-mean)*rstd*g[c0+3] + be[c0+3];
    o1.x = (v1.x-mean)*rstd*g[c1+0] + be[c1+0];
    o1.y = (v1.y-mean)*rstd*g[c1+1] + be[c1+1];
    o1.z = (v1.z-mean)*rstd*g[c1+2] + be[c1+2];
    o1.w = (v1.w-mean)*rstd*g[c1+3] + be[c1+3];
    ((float4*)dst)[lane]      = o0;
    ((float4*)dst)[lane + 32] = o1;
}

// ---------------- residual + LN2 ---------------------------------------------
// y = x + P (P already rolled); Y stored, LN(y) -> g_XN
__global__ void res_ln2_kernel(const float* __restrict__ x,
                               const float* __restrict__ g,
                               const float* __restrict__ be)
{
    const int warp = threadIdx.x >> 5, lane = threadIdx.x & 31;
    const int t = blockIdx.x * 8 + warp;
    const float* xs = x   + (size_t)t * 256;
    const float* ps = g_P + (size_t)t * 256;

    float4 a0 = ((const float4*)xs)[lane];
    float4 a1 = ((const float4*)xs)[lane + 32];
    float4 p0 = ((const float4*)ps)[lane];
    float4 p1 = ((const float4*)ps)[lane + 32];
    float4 v0 = make_float4(a0.x+p0.x, a0.y+p0.y, a0.z+p0.z, a0.w+p0.w);
    float4 v1 = make_float4(a1.x+p1.x, a1.y+p1.y, a1.z+p1.z, a1.w+p1.w);

    float s = v0.x+v0.y+v0.z+v0.w + v1.x+v1.y+v1.z+v1.w;
    float q = v0.x*v0.x+v0.y*v0.y+v0.z*v0.z+v0.w*v0.w
            + v1.x*v1.x+v1.y*v1.y+v1.z*v1.z+v1.w*v1.w;
    s = warp_sum(s); q = warp_sum(q);
    const float mean = s * (1.0f/256.0f);
    const float var  = q * (1.0f/256.0f) - mean*mean;
    const float rstd = rsqrtf(var + 1e-5f);

    float* ydst = g_Y  + (size_t)t * 256;
    float* ndst = g_XN + (size_t)t * 256;
    ((float4*)ydst)[lane]      = v0;
    ((float4*)ydst)[lane + 32] = v1;

    const int c0 = lane*4, c1 = 128 + lane*4;
    float4 o0, o1;
    o0.x = (v0.x-mean)*rstd*g[c0+0] + be[c0+0];
    o0.y = (v0.y-mean)*rstd*g[c0+1] + be[c0+1];
    o0.z = (v0.z-mean)*rstd*g[c0+2] + be[c0+2];
    o0.w = (v0.w-mean)*rstd*g[c0+3] + be[c0+3];
    o1.x = (v1.x-mean)*rstd*g[c1+0] + be[c1+0];
    o1.y = (v1.y-mean)*rstd*g[c1+1] + be[c1+1];
    o1.z = (v1.z-mean)*rstd*g[c1+2] + be[c1+2];
    o1.w = (v1.w-mean)*rstd*g[c1+3] + be[c1+3];
    ((float4*)ndst)[lane]      = o0;
    ((float4*)ndst)[lane + 32] = o1;
}

// ---------------- generic NT SGEMM: C[m,n] = sum_k A[m,k] * Bw[n,k] ----------
// EPI: 0 = +bias (QKV)
//      1 = +bias, write row rolled +2 within its 108-token window (PROJ)
//      2 = +bias, exact GELU (FC1)
//      3 = +bias, +Yres residual (FC2 -> final output)
template<int EPI>
__global__ void gemm_kernel(const float* __restrict__ A,
                            const float* __restrict__ Bw,
                            const float* __restrict__ bias,
                            const float* __restrict__ Yres,
                            float* __restrict__ C,
                            int M, int N, int Kd)
{
    __shared__ float As[8][128];
    __shared__ float Bs[8][128];
    const int tid = threadIdx.x;
    const int bn = blockIdx.x, bm = blockIdx.y;
    const int loadRow = tid >> 1;
    const int loadK   = (tid & 1) * 4;
    const float* Ap = A  + (size_t)(bm * 128 + loadRow) * Kd + loadK;
    const float* Bp = Bw + (size_t)(bn * 128 + loadRow) * Kd + loadK;
    const int tx = tid & 15, ty = tid >> 4;

    float acc[8][8];
    #pragma unroll
    for (int i = 0; i < 8; i++)
        #pragma unroll
        for (int j = 0; j < 8; j++) acc[i][j] = 0.0f;

    for (int k0 = 0; k0 < Kd; k0 += 8) {
        float4 a4 = *(const float4*)(Ap + k0);
        float4 b4 = *(const float4*)(Bp + k0);
        As[loadK+0][loadRow] = a4.x; As[loadK+1][loadRow] = a4.y;
        As[loadK+2][loadRow] = a4.z; As[loadK+3][loadRow] = a4.w;
        Bs[loadK+0][loadRow] = b4.x; Bs[loadK+1][loadRow] = b4.y;
        Bs[loadK+2][loadRow] = b4.z; Bs[loadK+3][loadRow] = b4.w;
        __syncthreads();
        #pragma unroll
        for (int kk = 0; kk < 8; kk++) {
            float ar[8], br[8];
            *(float4*)(ar)   = *(const float4*)&As[kk][ty*8];
            *(float4*)(ar+4) = *(const float4*)&As[kk][ty*8+4];
            *(float4*)(br)   = *(const float4*)&Bs[kk][tx*8];
            *(float4*)(br+4) = *(const float4*)&Bs[kk][tx*8+4];
            #pragma unroll
            for (int i = 0; i < 8; i++)
                #pragma unroll
                for (int j = 0; j < 8; j++)
                    acc[i][j] += ar[i] * br[j];
        }
        __syncthreads();
    }

    const int colBase = bn * 128 + tx * 8;
    #pragma unroll
    for (int i = 0; i < 8; i++) {
        const int m = bm * 128 + ty * 8 + i;
        float out[8];
        #pragma unroll
        for (int j = 0; j < 8; j++) {
            float v = acc[i][j] + bias[colBase + j];
            if (EPI == 2) v = 0.5f * v * (1.0f + erff(v * 0.70710678118654752f));
            if (EPI == 3) v += Yres[(size_t)m * N + colBase + j];
            out[j] = v;
        }
        int mout = m;
        if (EPI == 1) {
            const int nw = m / WTOK, w = m - nw * WTOK;
            int w2 = w + 2; if (w2 >= WTOK) w2 -= WTOK;
            mout = nw * WTOK + w2;
        }
        float* dst = C + (size_t)mout * N + colBase;
        *(float4*)(dst)   = *(const float4*)(out);
        *(float4*)(dst+4) = *(const float4*)(out+4);
    }
}

// ---------------- windowed attention -----------------------------------------
// block = (window n, head h); 256 threads (8 warps); warp handles query rows
#define ATTN_SMEM_FLOATS (64*108 + 108*64 + 8*108 + 8*64 + 108)
__global__ void attn_kernel(const float* __restrict__ qkv,
                            const float* __restrict__ eb,
                            float* __restrict__ o)
{
    extern __shared__ float sm[];
    float* kT  = sm;                 // [64][108]  K transposed
    float* vsh = kT  + 64*108;       // [108][64]
    float* psh = vsh + 108*64;       // [8][108]   per-warp probs
    float* qs  = psh + 8*108;        // [8][64]    per-warp q row
    float* rgn = qs  + 8*64;         // [108]      region id per token

    const int n = blockIdx.x, h = blockIdx.y;
    const int tid = threadIdx.x, warp = tid >> 5, lane = tid & 31;
    const int f = n & 31;
    const size_t base = (size_t)n * WTOK * 768;

    for (int idx = tid; idx < 108*64; idx += 256) {
        const int j = idx >> 6, d = idx & 63;
        const float* row = qkv + base + (size_t)j * 768 + h * 64;
        kT[d*108 + j] = row[256 + d];
        vsh[idx]      = row[512 + d];
    }
    for (int w = tid; w < 108; w += 256) {
        const int gf = f * 4 + w / 27;
        rgn[w] = (float)((gf >= 126) ? 2 : ((gf >= 124) ? 1 : 0));
    }
    __syncthreads();

    for (int row = warp; row < WTOK; row += 8) {
        const float* qrow = qkv + base + (size_t)row * 768 + h * 64;
        qs[warp*64 + lane]      = qrow[lane]      * 0.125f;
        qs[warp*64 + lane + 32] = qrow[lane + 32] * 0.125f;
        __syncwarp();

        float s0 = 0.f, s1 = 0.f, s2 = 0.f, s3 = 0.f;
        #pragma unroll 4
        for (int d = 0; d < 64; d++) {
            const float qd = qs[warp*64 + d];
            const float* kr = kT + d*108;
            s0 += qd * kr[lane];
            s1 += qd * kr[lane + 32];
            s2 += qd * kr[lane + 64];
            if (lane < 12) s3 += qd * kr[lane + 96];
        }

        const float rq = rgn[row];
        const float* ebr = eb + row * WTOK;
        float sv[4] = {s0, s1, s2, s3};
        float l[4];
        #pragma unroll
        for (int u = 0; u < 4; u++) {
            const int j = lane + 32*u;
            if (j < WTOK) {
                // attn = s * mask * edge_bias; masked_fill(==0, -1e4); softmax(-attn)
                const float av = (rgn[j] == rq) ? sv[u] * ebr[j] : 0.0f;
                l[u] = (av == 0.0f) ? 10000.0f : -av;
            } else {
                l[u] = -3.0e38f;
            }
        }
        float mx = fmaxf(fmaxf(l[0], l[1]), fmaxf(l[2], l[3]));
        mx = warp_max(mx);
        float p[4], sum = 0.f;
        #pragma unroll
        for (int u = 0; u < 4; u++) { p[u] = expf(l[u] - mx); sum += p[u]; }
        sum = warp_sum(sum);
        const float inv = 1.0f / sum;
        #pragma unroll
        for (int u = 0; u < 4; u++) {
            const int j = lane + 32*u;
            if (j < WTOK) psh[warp*WTOK + j] = p[u] * inv;
        }
        __syncwarp();

        float o1 = 0.f, o2 = 0.f;
        for (int j = 0; j < WTOK; j++) {
            const float pj = psh[warp*WTOK + j];
            o1 += pj * vsh[j*64 + lane];
            o2 += pj * vsh[j*64 + lane + 32];
        }
        float* od = o + ((size_t)n * WTOK + row) * 256 + h * 64;
        od[lane]      = o1;
        od[lane + 32] = o2;
    }
}

// ---------------- launch ------------------------------------------------------
extern "C" void kernel_launch(void* const* d_in, const int* in_sizes, int n_in,
                              void* d_out, int out_size)
{
    const float* x      = (const float*)d_in[0];
    const float* eb     = (const float*)d_in[1];
    const float* w_qkv  = (const float*)d_in[2];
    const float* b_qkv  = (const float*)d_in[3];
    const float* w_proj = (const float*)d_in[4];
    const float* b_proj = (const float*)d_in[5];
    const float* g1     = (const float*)d_in[6];
    const float* be1    = (const float*)d_in[7];
    const float* g2     = (const float*)d_in[8];
    const float* be2    = (const float*)d_in[9];
    const float* w_fc1  = (const float*)d_in[10];
    const float* b_fc1  = (const float*)d_in[11];
    const float* w_fc2  = (const float*)d_in[12];
    const float* b_fc2  = (const float*)d_in[13];
    float* out = (float*)d_out;

    float *XN, *QKV, *O, *P, *Y, *H1;
    cudaGetSymbolAddress((void**)&XN,  g_XN);
    cudaGetSymbolAddress((void**)&QKV, g_QKV);
    cudaGetSymbolAddress((void**)&O,   g_O);
    cudaGetSymbolAddress((void**)&P,   g_P);
    cudaGetSymbolAddress((void**)&Y,   g_Y);
    cudaGetSymbolAddress((void**)&H1,  g_H1);

    const int attnSmem = ATTN_SMEM_FLOATS * (int)sizeof(float);
    cudaFuncSetAttribute(attn_kernel,
                         cudaFuncAttributeMaxDynamicSharedMemorySize, attnSmem);

    // 1) shift + window + LN1
    ln1_kernel<<<NTOK / 8, 256>>>(x, g1, be1);
    // 2) QKV GEMM: [NTOK,256] x [256,768]
    gemm_kernel<0><<<dim3(768/128, NTOK/128), 256>>>(XN, w_qkv, b_qkv, nullptr, QKV,
                                                     NTOK, 768, 256);
    // 3) attention per (window, head)
    attn_kernel<<<dim3(NWIN, NHEAD), 256, attnSmem>>>(QKV, eb, O);
    // 4) proj GEMM + W-roll(+2) written in epilogue
    gemm_kernel<1><<<dim3(256/128, NTOK/128), 256>>>(O, w_proj, b_proj, nullptr, P,
                                                     NTOK, 256, 256);
    // 5) residual + LN2
    res_ln2_kernel<<<NTOK / 8, 256>>>(x, g2, be2);
    // 6) FC1 + GELU
    gemm_kernel<2><<<dim3(1024/128, NTOK/128), 256>>>(XN, w_fc1, b_fc1, nullptr, H1,
                                                      NTOK, 1024, 256);
    // 7) FC2 + residual -> output
    gemm_kernel<3><<<dim3(256/128, NTOK/128), 256>>>(H1, w_fc2, b_fc2, Y, out,
                                                     NTOK, 256, 1024);
}

// round 6
// speedup vs baseline: 2.2319x; 2.2319x over previous
#include <cuda_runtime.h>
#include <math.h>
#include <stdint.h>

// Problem constants
#define NTOK   110592          // 1024 windows * 108 tokens
#define NWIN   1024
#define WTOK   108

// ---------------- scratch (static device globals; no allocation) -------------
__device__ float g_XN [ (size_t)NTOK * 256 ];   // LN output (reused for LN1 and LN2)
__device__ float g_QKV[ (size_t)NTOK * 768 ];   // qkv
__device__ float g_O  [ (size_t)NTOK * 256 ];   // attention out (heads merged)
__device__ float g_P  [ (size_t)NTOK * 256 ];   // proj out, already W-rolled
__device__ float g_Y  [ (size_t)NTOK * 256 ];   // x + attn branch (residual base)
__device__ float g_H1 [ (size_t)NTOK * 1024 ];  // FC1+GELU out

// ---------------- helpers ----------------------------------------------------
__device__ __forceinline__ float warp_sum(float v){
    #pragma unroll
    for (int o = 16; o; o >>= 1) v += __shfl_xor_sync(0xffffffffu, v, o);
    return v;
}
__device__ __forceinline__ float warp_max(float v){
    #pragma unroll
    for (int o = 16; o; o >>= 1) v = fmaxf(v, __shfl_xor_sync(0xffffffffu, v, o));
    return v;
}
__device__ __forceinline__ uint32_t smem_u32(const void* p){
    uint32_t a;
    asm("{ .reg .u64 t; cvta.to.shared.u64 t, %1; cvt.u32.u64 %0, t; }"
        : "=r"(a) : "l"(p));
    return a;
}

// ---------------- LN1 with shift + window gather ------------------------------
__global__ void ln1_kernel(const float* __restrict__ x,
                           const float* __restrict__ g,
                           const float* __restrict__ be)
{
    const int warp = threadIdx.x >> 5, lane = threadIdx.x & 31;
    const int t = blockIdx.x * 8 + warp;
    const int n = t / WTOK, w = t - n * WTOK;
    const int b = n >> 5, f = n & 31;
    const int wf = w / 27;
    const int gf = f * 4 + wf;
    const int fr = (gf + 2) & 127;
    const int kp = w - wf * 27;
    const float* src = x + (size_t)((b * 128 + fr) * 27 + kp) * 256;

    float4 v0 = ((const float4*)src)[lane];
    float4 v1 = ((const float4*)src)[lane + 32];
    float s = v0.x+v0.y+v0.z+v0.w + v1.x+v1.y+v1.z+v1.w;
    float q = v0.x*v0.x+v0.y*v0.y+v0.z*v0.z+v0.w*v0.w
            + v1.x*v1.x+v1.y*v1.y+v1.z*v1.z+v1.w*v1.w;
    s = warp_sum(s); q = warp_sum(q);
    const float mean = s * (1.0f/256.0f);
    const float var  = q * (1.0f/256.0f) - mean*mean;
    const float rstd = rsqrtf(var + 1e-5f);

    float* dst = g_XN + (size_t)t * 256;
    const int c0 = lane*4, c1 = 128 + lane*4;
    float4 o0, o1;
    o0.x = (v0.x-mean)*rstd*g[c0+0] + be[c0+0];
    o0.y = (v0.y-mean)*rstd*g[c0+1] + be[c0+1];
    o0.z = (v0.z-mean)*rstd*g[c0+2] + be[c0+2];
    o0.w = (v0.w-mean)*rstd*g[c0+3] + be[c0+3];
    o1.x = (v1.x-mean)*rstd*g[c1+0] + be[c1+0];
    o1.y = (v1.y-mean)*rstd*g[c1+1] + be[c1+1];
    o1.z = (v1.z-mean)*rstd*g[c1+2] + be[c1+2];
    o1.w = (v1.w-mean)*rstd*g[c1+3] + be[c1+3];
    ((float4*)dst)[lane]      = o0;
    ((float4*)dst)[lane + 32] = o1;
}

// ---------------- residual + LN2 ---------------------------------------------
__global__ void res_ln2_kernel(const float* __restrict__ x,
                               const float* __restrict__ g,
                               const float* __restrict__ be)
{
    const int warp = threadIdx.x >> 5, lane = threadIdx.x & 31;
    const int t = blockIdx.x * 8 + warp;
    const float* xs = x   + (size_t)t * 256;
    const float* ps = g_P + (size_t)t * 256;

    float4 a0 = ((const float4*)xs)[lane];
    float4 a1 = ((const float4*)xs)[lane + 32];
    float4 p0 = ((const float4*)ps)[lane];
    float4 p1 = ((const float4*)ps)[lane + 32];
    float4 v0 = make_float4(a0.x+p0.x, a0.y+p0.y, a0.z+p0.z, a0.w+p0.w);
    float4 v1 = make_float4(a1.x+p1.x, a1.y+p1.y, a1.z+p1.z, a1.w+p1.w);

    float s = v0.x+v0.y+v0.z+v0.w + v1.x+v1.y+v1.z+v1.w;
    float q = v0.x*v0.x+v0.y*v0.y+v0.z*v0.z+v0.w*v0.w
            + v1.x*v1.x+v1.y*v1.y+v1.z*v1.z+v1.w*v1.w;
    s = warp_sum(s); q = warp_sum(q);
    const float mean = s * (1.0f/256.0f);
    const float var  = q * (1.0f/256.0f) - mean*mean;
    const float rstd = rsqrtf(var + 1e-5f);

    float* ydst = g_Y  + (size_t)t * 256;
    float* ndst = g_XN + (size_t)t * 256;
    ((float4*)ydst)[lane]      = v0;
    ((float4*)ydst)[lane + 32] = v1;

    const int c0 = lane*4, c1 = 128 + lane*4;
    float4 o0, o1;
    o0.x = (v0.x-mean)*rstd*g[c0+0] + be[c0+0];
    o0.y = (v0.y-mean)*rstd*g[c0+1] + be[c0+1];
    o0.z = (v0.z-mean)*rstd*g[c0+2] + be[c0+2];
    o0.w = (v0.w-mean)*rstd*g[c0+3] + be[c0+3];
    o1.x = (v1.x-mean)*rstd*g[c1+0] + be[c1+0];
    o1.y = (v1.y-mean)*rstd*g[c1+1] + be[c1+1];
    o1.z = (v1.z-mean)*rstd*g[c1+2] + be[c1+2];
    o1.w = (v1.w-mean)*rstd*g[c1+3] + be[c1+3];
    ((float4*)ndst)[lane]      = o0;
    ((float4*)ndst)[lane + 32] = o1;
}

// ---------------- tf32 mma.sync NT GEMM: C[m,n] = sum_k A[m,k]*Bw[n,k] -------
// Tile 128x128, 256 threads (8 warps as 2x4), warp tile 64x32,
// K in 32-float chunks, cp.async double buffered. smem stride 36 floats.
// EPI: 0 = +bias (QKV) ; 1 = +bias, row-rolled +2 in window (PROJ)
//      2 = +bias, exact GELU (FC1) ; 3 = +bias + Yres residual (FC2 -> out)
#define SSTR  36
#define GSMEM (4 * 128 * SSTR * 4)   // 2 tensors x 2 buffers

__device__ __forceinline__ void cpasync_chunk(float* As, float* Bs,
                                              const float* __restrict__ Ag,
                                              const float* __restrict__ Bg,
                                              int kbase, int tid, int KD)
{
    const int r0 = tid >> 3, q = tid & 7;
    #pragma unroll
    for (int i = 0; i < 4; i++) {
        const int row = r0 + 32*i;
        const uint32_t sa = smem_u32(As + row*SSTR + q*4);
        const uint32_t sb = smem_u32(Bs + row*SSTR + q*4);
        const float* ga = Ag + (size_t)row*KD + kbase + q*4;
        const float* gb = Bg + (size_t)row*KD + kbase + q*4;
        asm volatile("cp.async.cg.shared.global [%0], [%1], 16;" :: "r"(sa), "l"(ga));
        asm volatile("cp.async.cg.shared.global [%0], [%1], 16;" :: "r"(sb), "l"(gb));
    }
}

__device__ __forceinline__ void mma_tf32(float& c0, float& c1, float& c2, float& c3,
                                         float a0, float a1, float a2, float a3,
                                         float b0, float b1)
{
    asm volatile(
        "mma.sync.aligned.m16n8k8.row.col.f32.tf32.tf32.f32 "
        "{%0,%1,%2,%3}, {%4,%5,%6,%7}, {%8,%9}, {%0,%1,%2,%3};"
        : "+f"(c0), "+f"(c1), "+f"(c2), "+f"(c3)
        : "r"(__float_as_uint(a0)), "r"(__float_as_uint(a1)),
          "r"(__float_as_uint(a2)), "r"(__float_as_uint(a3)),
          "r"(__float_as_uint(b0)), "r"(__float_as_uint(b1)));
}

template<int EPI>
__device__ __forceinline__ void epi_store(float* __restrict__ C,
                                          const float* __restrict__ Yres,
                                          int N, int m, int col,
                                          float v0, float v1)
{
    if (EPI == 2) {
        v0 = 0.5f*v0*(1.0f + erff(v0*0.70710678118654752f));
        v1 = 0.5f*v1*(1.0f + erff(v1*0.70710678118654752f));
    }
    if (EPI == 3) {
        const float2 yv = *(const float2*)&Yres[(size_t)m*N + col];
        v0 += yv.x; v1 += yv.y;
    }
    int mout = m;
    if (EPI == 1) {
        const int nw = m / WTOK, w = m - nw * WTOK;
        int w2 = w + 2; if (w2 >= WTOK) w2 -= WTOK;
        mout = nw * WTOK + w2;
    }
    *(float2*)&C[(size_t)mout*N + col] = make_float2(v0, v1);
}

template<int EPI, int KD>
__global__ void __launch_bounds__(256)
tgemm(const float* __restrict__ A, const float* __restrict__ Bw,
      const float* __restrict__ bias, const float* __restrict__ Yres,
      float* __restrict__ C, int N)
{
    extern __shared__ float sm[];
    float* As[2] = { sm,              sm + 2*128*SSTR };
    float* Bs[2] = { sm + 128*SSTR,   sm + 3*128*SSTR };

    const int tid = threadIdx.x;
    const int wid = tid >> 5, lane = tid & 31;
    const int warpM = wid >> 2, warpN = wid & 3;   // 2 x 4
    const int g = lane >> 2, t = lane & 3;
    const int bn = blockIdx.x, bm = blockIdx.y;

    const float* Abase = A  + (size_t)bm * 128 * KD;
    const float* Bbase = Bw + (size_t)bn * 128 * KD;

    float acc[4][4][4];
    #pragma unroll
    for (int i = 0; i < 4; i++)
        #pragma unroll
        for (int j = 0; j < 4; j++)
            #pragma unroll
            for (int q = 0; q < 4; q++) acc[i][j][q] = 0.0f;

    constexpr int NC = KD / 32;
    cpasync_chunk(As[0], Bs[0], Abase, Bbase, 0, tid, KD);
    asm volatile("cp.async.commit_group;" ::: "memory");

    for (int c = 0; c < NC; c++) {
        asm volatile("cp.async.wait_group 0;" ::: "memory");
        __syncthreads();
        if (c + 1 < NC) {
            const int nb = (c + 1) & 1;
            cpasync_chunk(As[nb], Bs[nb], Abase, Bbase, (c+1)*32, tid, KD);
            asm volatile("cp.async.commit_group;" ::: "memory");
        }
        const float* Ap = As[c & 1] + (warpM*64 + g)*SSTR + t;
        const float* Bp = Bs[c & 1] + (warpN*32 + g)*SSTR + t;

        #pragma unroll
        for (int s = 0; s < 4; s++) {
            const int k0 = s * 8;
            float a[4][4], b[4][2];
            #pragma unroll
            for (int mt = 0; mt < 4; mt++) {
                const float* ap = Ap + mt*16*SSTR + k0;
                a[mt][0] = ap[0];
                a[mt][1] = ap[8*SSTR];
                a[mt][2] = ap[4];
                a[mt][3] = ap[8*SSTR + 4];
            }
            #pragma unroll
            for (int nt = 0; nt < 4; nt++) {
                const float* bp = Bp + nt*8*SSTR + k0;
                b[nt][0] = bp[0];
                b[nt][1] = bp[4];
            }
            #pragma unroll
            for (int mt = 0; mt < 4; mt++)
                #pragma unroll
                for (int nt = 0; nt < 4; nt++)
                    mma_tf32(acc[mt][nt][0], acc[mt][nt][1],
                             acc[mt][nt][2], acc[mt][nt][3],
                             a[mt][0], a[mt][1], a[mt][2], a[mt][3],
                             b[nt][0], b[nt][1]);
        }
        __syncthreads();
    }

    // epilogue: bias + EPI, direct global write
    #pragma unroll
    for (int mt = 0; mt < 4; mt++) {
        const int r0 = bm*128 + warpM*64 + mt*16 + g;
        #pragma unroll
        for (int nt = 0; nt < 4; nt++) {
            const int col = bn*128 + warpN*32 + nt*8 + t*2;
            const float2 bv = *(const float2*)&bias[col];
            epi_store<EPI>(C, Yres, N, r0,     col,
                           acc[mt][nt][0] + bv.x, acc[mt][nt][1] + bv.y);
            epi_store<EPI>(C, Yres, N, r0 + 8, col,
                           acc[mt][nt][2] + bv.x, acc[mt][nt][3] + bv.y);
        }
    }
}

// ---------------- windowed attention -----------------------------------------
#define ATTN_SMEM_FLOATS (64*108 + 108*64 + 8*108 + 8*64 + 108)
__global__ void attn_kernel(const float* __restrict__ qkv,
                            const float* __restrict__ eb,
                            float* __restrict__ o)
{
    extern __shared__ float sm[];
    float* kT  = sm;                 // [64][108]  K transposed
    float* vsh = kT  + 64*108;       // [108][64]
    float* psh = vsh + 108*64;       // [8][108]   per-warp probs
    float* qs  = psh + 8*108;        // [8][64]    per-warp q row
    float* rgn = qs  + 8*64;         // [108]      region id per token

    const int n = blockIdx.x, h = blockIdx.y;
    const int tid = threadIdx.x, warp = tid >> 5, lane = tid & 31;
    const int f = n & 31;
    const size_t base = (size_t)n * WTOK * 768;

    for (int idx = tid; idx < 108*64; idx += 256) {
        const int j = idx >> 6, d = idx & 63;
        const float* row = qkv + base + (size_t)j * 768 + h * 64;
        kT[d*108 + j] = row[256 + d];
        vsh[idx]      = row[512 + d];
    }
    for (int w = tid; w < 108; w += 256) {
        const int gf = f * 4 + w / 27;
        rgn[w] = (float)((gf >= 126) ? 2 : ((gf >= 124) ? 1 : 0));
    }
    __syncthreads();

    for (int row = warp; row < WTOK; row += 8) {
        const float* qrow = qkv + base + (size_t)row * 768 + h * 64;
        qs[warp*64 + lane]      = qrow[lane]      * 0.125f;
        qs[warp*64 + lane + 32] = qrow[lane + 32] * 0.125f;
        __syncwarp();

        float s0 = 0.f, s1 = 0.f, s2 = 0.f, s3 = 0.f;
        #pragma unroll 4
        for (int d = 0; d < 64; d++) {
            const float qd = qs[warp*64 + d];
            const float* kr = kT + d*108;
            s0 += qd * kr[lane];
            s1 += qd * kr[lane + 32];
            s2 += qd * kr[lane + 64];
            if (lane < 12) s3 += qd * kr[lane + 96];
        }

        const float rq = rgn[row];
        const float* ebr = eb + row * WTOK;
        float sv[4] = {s0, s1, s2, s3};
        float l[4];
        #pragma unroll
        for (int u = 0; u < 4; u++) {
            const int j = lane + 32*u;
            if (j < WTOK) {
                const float av = (rgn[j] == rq) ? sv[u] * ebr[j] : 0.0f;
                l[u] = (av == 0.0f) ? 10000.0f : -av;
            } else {
                l[u] = -3.0e38f;
            }
        }
        float mx = fmaxf(fmaxf(l[0], l[1]), fmaxf(l[2], l[3]));
        mx = warp_max(mx);
        float p[4], sum = 0.f;
        #pragma unroll
        for (int u = 0; u < 4; u++) { p[u] = expf(l[u] - mx); sum += p[u]; }
        sum = warp_sum(sum);
        const float inv = 1.0f / sum;
        #pragma unroll
        for (int u = 0; u < 4; u++) {
            const int j = lane + 32*u;
            if (j < WTOK) psh[warp*WTOK + j] = p[u] * inv;
        }
        __syncwarp();

        float o1 = 0.f, o2 = 0.f;
        for (int j = 0; j < WTOK; j++) {
            const float pj = psh[warp*WTOK + j];
            o1 += pj * vsh[j*64 + lane];
            o2 += pj * vsh[j*64 + lane + 32];
        }
        float* od = o + ((size_t)n * WTOK + row) * 256 + h * 64;
        od[lane]      = o1;
        od[lane + 32] = o2;
    }
}

// ---------------- launch ------------------------------------------------------
extern "C" void kernel_launch(void* const* d_in, const int* in_sizes, int n_in,
                              void* d_out, int out_size)
{
    const float* x      = (const float*)d_in[0];
    const float* eb     = (const float*)d_in[1];
    const float* w_qkv  = (const float*)d_in[2];
    const float* b_qkv  = (const float*)d_in[3];
    const float* w_proj = (const float*)d_in[4];
    const float* b_proj = (const float*)d_in[5];
    const float* g1     = (const float*)d_in[6];
    const float* be1    = (const float*)d_in[7];
    const float* g2     = (const float*)d_in[8];
    const float* be2    = (const float*)d_in[9];
    const float* w_fc1  = (const float*)d_in[10];
    const float* b_fc1  = (const float*)d_in[11];
    const float* w_fc2  = (const float*)d_in[12];
    const float* b_fc2  = (const float*)d_in[13];
    float* out = (float*)d_out;

    float *XN, *QKV, *O, *P, *Y, *H1;
    cudaGetSymbolAddress((void**)&XN,  g_XN);
    cudaGetSymbolAddress((void**)&QKV, g_QKV);
    cudaGetSymbolAddress((void**)&O,   g_O);
    cudaGetSymbolAddress((void**)&P,   g_P);
    cudaGetSymbolAddress((void**)&Y,   g_Y);
    cudaGetSymbolAddress((void**)&H1,  g_H1);

    const int attnSmem = ATTN_SMEM_FLOATS * (int)sizeof(float);
    cudaFuncSetAttribute(attn_kernel,
                         cudaFuncAttributeMaxDynamicSharedMemorySize, attnSmem);
    cudaFuncSetAttribute(tgemm<0,256>,  cudaFuncAttributeMaxDynamicSharedMemorySize, GSMEM);
    cudaFuncSetAttribute(tgemm<1,256>,  cudaFuncAttributeMaxDynamicSharedMemorySize, GSMEM);
    cudaFuncSetAttribute(tgemm<2,256>,  cudaFuncAttributeMaxDynamicSharedMemorySize, GSMEM);
    cudaFuncSetAttribute(tgemm<3,1024>, cudaFuncAttributeMaxDynamicSharedMemorySize, GSMEM);

    // 1) shift + window + LN1
    ln1_kernel<<<NTOK / 8, 256>>>(x, g1, be1);
    // 2) QKV GEMM: [NTOK,256] x [256,768]   (tf32 mma.sync)
    tgemm<0,256><<<dim3(6, NTOK/128), 256, GSMEM>>>(XN, w_qkv, b_qkv, nullptr, QKV, 768);
    // 3) attention per (window, head)
    attn_kernel<<<dim3(NWIN, 4), 256, attnSmem>>>(QKV, eb, O);
    // 4) proj GEMM + W-roll(+2) in epilogue
    tgemm<1,256><<<dim3(2, NTOK/128), 256, GSMEM>>>(O, w_proj, b_proj, nullptr, P, 256);
    // 5) residual + LN2
    res_ln2_kernel<<<NTOK / 8, 256>>>(x, g2, be2);
    // 6) FC1 + GELU
    tgemm<2,256><<<dim3(8, NTOK/128), 256, GSMEM>>>(XN, w_fc1, b_fc1, nullptr, H1, 1024);
    // 7) FC2 + residual -> output
    tgemm<3,1024><<<dim3(2, NTOK/128), 256, GSMEM>>>(H1, w_fc2, b_fc2, Y, out, 256);
}

// round 7
// speedup vs baseline: 3.1460x; 1.4096x over previous
#include <cuda_runtime.h>
#include <cuda_bf16.h>
#include <math.h>
#include <stdint.h>

typedef __nv_bfloat16 bf16;

// Problem constants
#define NTOK   110592          // 1024 windows * 108 tokens
#define NWIN   1024
#define WTOK   108

// ---------------- scratch (static device globals; no allocation) -------------
__device__ float g_QKV[ (size_t)NTOK * 768 ];   // qkv (fp32, attention input)
__device__ float g_P  [ (size_t)NTOK * 256 ];   // proj out, already W-rolled
__device__ float g_Y  [ (size_t)NTOK * 256 ];   // x + attn branch (residual base)
__device__ bf16  g_XNh[ (size_t)NTOK * 256 ];   // LN out (bf16, GEMM A input)
__device__ bf16  g_Oh [ (size_t)NTOK * 256 ];   // attention out (bf16)
__device__ bf16  g_H1h[ (size_t)NTOK * 1024 ];  // FC1+GELU out (bf16)
__device__ bf16  g_Wq [ 768 * 256 ];
__device__ bf16  g_Wp [ 256 * 256 ];
__device__ bf16  g_W1 [ 1024 * 256 ];
__device__ bf16  g_W2 [ 256 * 1024 ];

// ---------------- helpers ----------------------------------------------------
__device__ __forceinline__ float warp_sum(float v){
    #pragma unroll
    for (int o = 16; o; o >>= 1) v += __shfl_xor_sync(0xffffffffu, v, o);
    return v;
}
__device__ __forceinline__ float warp_max(float v){
    #pragma unroll
    for (int o = 16; o; o >>= 1) v = fmaxf(v, __shfl_xor_sync(0xffffffffu, v, o));
    return v;
}
__device__ __forceinline__ uint32_t smem_u32(const void* p){
    uint32_t a;
    asm("{ .reg .u64 t; cvta.to.shared.u64 t, %1; cvt.u32.u64 %0, t; }"
        : "=r"(a) : "l"(p));
    return a;
}

// ---------------- weight fp32 -> bf16 convert ---------------------------------
__global__ void f2bf_kernel(const float* __restrict__ s, bf16* __restrict__ d, int n)
{
    const int i = (blockIdx.x * 256 + threadIdx.x) * 4;
    if (i < n) {
        float4 v = *(const float4*)(s + i);
        __nv_bfloat162* dp = (__nv_bfloat162*)(d + i);
        dp[0] = __floats2bfloat162_rn(v.x, v.y);
        dp[1] = __floats2bfloat162_rn(v.z, v.w);
    }
}

// ---------------- LN1 with shift + window gather (bf16 out) -------------------
__global__ void ln1_kernel(const float* __restrict__ x,
                           const float* __restrict__ g,
                           const float* __restrict__ be)
{
    const int warp = threadIdx.x >> 5, lane = threadIdx.x & 31;
    const int t = blockIdx.x * 8 + warp;
    const int n = t / WTOK, w = t - n * WTOK;
    const int b = n >> 5, f = n & 31;
    const int wf = w / 27;
    const int gf = f * 4 + wf;
    const int fr = (gf + 2) & 127;
    const int kp = w - wf * 27;
    const float* src = x + (size_t)((b * 128 + fr) * 27 + kp) * 256;

    float4 v0 = ((const float4*)src)[lane];
    float4 v1 = ((const float4*)src)[lane + 32];
    float s = v0.x+v0.y+v0.z+v0.w + v1.x+v1.y+v1.z+v1.w;
    float q = v0.x*v0.x+v0.y*v0.y+v0.z*v0.z+v0.w*v0.w
            + v1.x*v1.x+v1.y*v1.y+v1.z*v1.z+v1.w*v1.w;
    s = warp_sum(s); q = warp_sum(q);
    const float mean = s * (1.0f/256.0f);
    const float var  = q * (1.0f/256.0f) - mean*mean;
    const float rstd = rsqrtf(var + 1e-5f);

    __nv_bfloat162* dst = (__nv_bfloat162*)(g_XNh + (size_t)t * 256);
    const int c0 = lane*4, c1 = 128 + lane*4;
    dst[lane*2]        = __floats2bfloat162_rn((v0.x-mean)*rstd*g[c0+0] + be[c0+0],
                                               (v0.y-mean)*rstd*g[c0+1] + be[c0+1]);
    dst[lane*2+1]      = __floats2bfloat162_rn((v0.z-mean)*rstd*g[c0+2] + be[c0+2],
                                               (v0.w-mean)*rstd*g[c0+3] + be[c0+3]);
    dst[64 + lane*2]   = __floats2bfloat162_rn((v1.x-mean)*rstd*g[c1+0] + be[c1+0],
                                               (v1.y-mean)*rstd*g[c1+1] + be[c1+1]);
    dst[64 + lane*2+1] = __floats2bfloat162_rn((v1.z-mean)*rstd*g[c1+2] + be[c1+2],
                                               (v1.w-mean)*rstd*g[c1+3] + be[c1+3]);
}

// ---------------- residual + LN2 (Y fp32, XN bf16) ----------------------------
__global__ void res_ln2_kernel(const float* __restrict__ x,
                               const float* __restrict__ g,
                               const float* __restrict__ be)
{
    const int warp = threadIdx.x >> 5, lane = threadIdx.x & 31;
    const int t = blockIdx.x * 8 + warp;
    const float* xs = x   + (size_t)t * 256;
    const float* ps = g_P + (size_t)t * 256;

    float4 a0 = ((const float4*)xs)[lane];
    float4 a1 = ((const float4*)xs)[lane + 32];
    float4 p0 = ((const float4*)ps)[lane];
    float4 p1 = ((const float4*)ps)[lane + 32];
    float4 v0 = make_float4(a0.x+p0.x, a0.y+p0.y, a0.z+p0.z, a0.w+p0.w);
    float4 v1 = make_float4(a1.x+p1.x, a1.y+p1.y, a1.z+p1.z, a1.w+p1.w);

    float s = v0.x+v0.y+v0.z+v0.w + v1.x+v1.y+v1.z+v1.w;
    float q = v0.x*v0.x+v0.y*v0.y+v0.z*v0.z+v0.w*v0.w
            + v1.x*v1.x+v1.y*v1.y+v1.z*v1.z+v1.w*v1.w;
    s = warp_sum(s); q = warp_sum(q);
    const float mean = s * (1.0f/256.0f);
    const float var  = q * (1.0f/256.0f) - mean*mean;
    const float rstd = rsqrtf(var + 1e-5f);

    float* ydst = g_Y + (size_t)t * 256;
    ((float4*)ydst)[lane]      = v0;
    ((float4*)ydst)[lane + 32] = v1;

    __nv_bfloat162* ndst = (__nv_bfloat162*)(g_XNh + (size_t)t * 256);
    const int c0 = lane*4, c1 = 128 + lane*4;
    ndst[lane*2]        = __floats2bfloat162_rn((v0.x-mean)*rstd*g[c0+0] + be[c0+0],
                                                (v0.y-mean)*rstd*g[c0+1] + be[c0+1]);
    ndst[lane*2+1]      = __floats2bfloat162_rn((v0.z-mean)*rstd*g[c0+2] + be[c0+2],
                                                (v0.w-mean)*rstd*g[c0+3] + be[c0+3]);
    ndst[64 + lane*2]   = __floats2bfloat162_rn((v1.x-mean)*rstd*g[c1+0] + be[c1+0],
                                                (v1.y-mean)*rstd*g[c1+1] + be[c1+1]);
    ndst[64 + lane*2+1] = __floats2bfloat162_rn((v1.z-mean)*rstd*g[c1+2] + be[c1+2],
                                                (v1.w-mean)*rstd*g[c1+3] + be[c1+3]);
}

// ---------------- bf16 mma.sync NT GEMM: C[m,n] = sum_k A[m,k]*Bw[n,k] -------
// Tile 128x128, 256 threads (8 warps as 2x4), warp tile 64x32.
// K in 64-element chunks (128B rows, XOR-16B-chunk swizzle), cp.async 2-stage.
// Fragments loaded via ldmatrix.x4. mma m16n8k16 bf16 -> fp32.
// EPI: 0 = +bias (QKV, fp32 out) ; 1 = +bias, row-rolled +2 (PROJ, fp32)
//      2 = +bias, exact GELU (FC1, bf16 out) ; 3 = +bias + Yres (FC2, fp32 out)
#define BUFB  16384
#define GSMEM (4*BUFB + 128)

#define LDSM_X4(r0,r1,r2,r3,addr) \
    asm volatile("ldmatrix.sync.aligned.m8n8.x4.shared.b16 {%0,%1,%2,%3}, [%4];" \
        : "=r"(r0), "=r"(r1), "=r"(r2), "=r"(r3) : "r"(addr))

__device__ __forceinline__ void mma_bf16(float& c0, float& c1, float& c2, float& c3,
                                         uint32_t a0, uint32_t a1, uint32_t a2, uint32_t a3,
                                         uint32_t b0, uint32_t b1)
{
    asm volatile(
        "mma.sync.aligned.m16n8k16.row.col.f32.bf16.bf16.f32 "
        "{%0,%1,%2,%3}, {%4,%5,%6,%7}, {%8,%9}, {%0,%1,%2,%3};"
        : "+f"(c0), "+f"(c1), "+f"(c2), "+f"(c3)
        : "r"(a0), "r"(a1), "r"(a2), "r"(a3), "r"(b0), "r"(b1));
}

template<int EPI>
__device__ __forceinline__ void epi_store(void* __restrict__ C,
                                          const float* __restrict__ Yres,
                                          int N, int m, int col,
                                          float v0, float v1)
{
    if (EPI == 2) {
        v0 = 0.5f*v0*(1.0f + erff(v0*0.70710678118654752f));
        v1 = 0.5f*v1*(1.0f + erff(v1*0.70710678118654752f));
        // bf16 output
        *(__nv_bfloat162*)((bf16*)C + (size_t)m*N + col) = __floats2bfloat162_rn(v0, v1);
        return;
    }
    if (EPI == 3) {
        const float2 yv = *(const float2*)&Yres[(size_t)m*N + col];
        v0 += yv.x; v1 += yv.y;
    }
    int mout = m;
    if (EPI == 1) {
        const int nw = m / WTOK, w = m - nw * WTOK;
        int w2 = w + 2; if (w2 >= WTOK) w2 -= WTOK;
        mout = nw * WTOK + w2;
    }
    *(float2*)((float*)C + (size_t)mout*N + col) = make_float2(v0, v1);
}

template<int EPI, int KD>
__global__ void __launch_bounds__(256)
hgemm(const bf16* __restrict__ A, const bf16* __restrict__ Bw,
      const float* __restrict__ bias, const float* __restrict__ Yres,
      void* __restrict__ C, int N)
{
    extern __shared__ char smraw[];
    char* sm = (char*)(((uintptr_t)smraw + 127) & ~(uintptr_t)127);

    const int tid = threadIdx.x;
    const int wid = tid >> 5, lane = tid & 31;
    const int warpM = wid >> 2, warpN = wid & 3;   // 2 x 4
    const int bn = blockIdx.x, bm = blockIdx.y;

    const bf16* Ab = A  + (size_t)bm * 128 * KD;
    const bf16* Bb = Bw + (size_t)bn * 128 * KD;

    const uint32_t smb = smem_u32(sm);

    // ldmatrix per-lane addressing
    const int aRow = (lane & 7) | (((lane >> 3) & 1) << 3);   // 0..15
    const int aK   = (lane >> 4) & 1;                          // 16B-chunk select
    const int bRow = (lane & 7) | (((lane >> 4) & 1) << 3);
    const int bK   = (lane >> 3) & 1;

    float acc[4][4][4];
    #pragma unroll
    for (int i = 0; i < 4; i++)
        #pragma unroll
        for (int j = 0; j < 4; j++)
            #pragma unroll
            for (int q = 0; q < 4; q++) acc[i][j][q] = 0.0f;

    // cp.async loader: 128 rows x 128B per tensor, swizzled 16B chunks
    auto load_chunk = [&](int buf, int kbase){
        const uint32_t sa = smb + buf * 2 * BUFB;
        const uint32_t sb = sa + BUFB;
        #pragma unroll
        for (int i = 0; i < 4; i++) {
            const int idx = tid + 256*i;
            const int row = idx >> 3, q = idx & 7;
            const uint32_t off = row*128 + ((q ^ (row & 7)) << 4);
            const size_t goff = (size_t)row*KD + kbase + q*8;
            asm volatile("cp.async.cg.shared.global [%0], [%1], 16;"
                         :: "r"(sa + off), "l"(Ab + goff));
            asm volatile("cp.async.cg.shared.global [%0], [%1], 16;"
                         :: "r"(sb + off), "l"(Bb + goff));
        }
    };

    constexpr int NC = KD / 64;
    load_chunk(0, 0);
    asm volatile("cp.async.commit_group;" ::: "memory");

    for (int c = 0; c < NC; c++) {
        asm volatile("cp.async.wait_group 0;" ::: "memory");
        __syncthreads();
        if (c + 1 < NC) {
            load_chunk((c+1) & 1, (c+1)*64);
            asm volatile("cp.async.commit_group;" ::: "memory");
        }
        const uint32_t saA = smb + (c & 1) * 2 * BUFB;
        const uint32_t saB = saA + BUFB;

        #pragma unroll
        for (int s = 0; s < 4; s++) {
            const int cch = s * 2;              // 16B-chunk base for this k16
            uint32_t a[4][4];
            #pragma unroll
            for (int mt = 0; mt < 4; mt++) {
                const int row = warpM*64 + mt*16 + aRow;
                const uint32_t off = row*128 + (((cch + aK) ^ (row & 7)) << 4);
                LDSM_X4(a[mt][0], a[mt][1], a[mt][2], a[mt][3], saA + off);
            }
            uint32_t b[4][2];
            #pragma unroll
            for (int p = 0; p < 2; p++) {
                const int row = warpN*32 + p*16 + bRow;
                const uint32_t off = row*128 + (((cch + bK) ^ (row & 7)) << 4);
                LDSM_X4(b[2*p][0], b[2*p][1], b[2*p+1][0], b[2*p+1][1], saB + off);
            }
            #pragma unroll
            for (int mt = 0; mt < 4; mt++)
                #pragma unroll
                for (int nt = 0; nt < 4; nt++)
                    mma_bf16(acc[mt][nt][0], acc[mt][nt][1],
                             acc[mt][nt][2], acc[mt][nt][3],
                             a[mt][0], a[mt][1], a[mt][2], a[mt][3],
                             b[nt][0], b[nt][1]);
        }
        __syncthreads();
    }

    // epilogue: bias + EPI variant, direct global write
    const int g = lane >> 2, t = lane & 3;
    #pragma unroll
    for (int mt = 0; mt < 4; mt++) {
        const int r0 = bm*128 + warpM*64 + mt*16 + g;
        #pragma unroll
        for (int nt = 0; nt < 4; nt++) {
            const int col = bn*128 + warpN*32 + nt*8 + t*2;
            const float2 bv = *(const float2*)&bias[col];
            epi_store<EPI>(C, Yres, N, r0,     col,
                           acc[mt][nt][0] + bv.x, acc[mt][nt][1] + bv.y);
            epi_store<EPI>(C, Yres, N, r0 + 8, col,
                           acc[mt][nt][2] + bv.x, acc[mt][nt][3] + bv.y);
        }
    }
}

// ---------------- windowed attention (fp32 in, bf16 out) ----------------------
#define ATTN_SMEM_FLOATS (64*108 + 108*64 + 8*108 + 8*64 + 108)
__global__ void attn_kernel(const float* __restrict__ qkv,
                            const float* __restrict__ eb,
                            bf16* __restrict__ o)
{
    extern __shared__ float sm[];
    float* kT  = sm;                 // [64][108]  K transposed
    float* vsh = kT  + 64*108;       // [108][64]
    float* psh = vsh + 108*64;       // [8][108]   per-warp probs
    float* qs  = psh + 8*108;        // [8][64]    per-warp q row
    float* rgn = qs  + 8*64;         // [108]      region id per token

    const int n = blockIdx.x, h = blockIdx.y;
    const int tid = threadIdx.x, warp = tid >> 5, lane = tid & 31;
    const int f = n & 31;
    const size_t base = (size_t)n * WTOK * 768;

    for (int idx = tid; idx < 108*64; idx += 256) {
        const int j = idx >> 6, d = idx & 63;
        const float* row = qkv + base + (size_t)j * 768 + h * 64;
        kT[d*108 + j] = row[256 + d];
        vsh[idx]      = row[512 + d];
    }
    for (int w = tid; w < 108; w += 256) {
        const int gf = f * 4 + w / 27;
        rgn[w] = (float)((gf >= 126) ? 2 : ((gf >= 124) ? 1 : 0));
    }
    __syncthreads();

    for (int row = warp; row < WTOK; row += 8) {
        const float* qrow = qkv + base + (size_t)row * 768 + h * 64;
        qs[warp*64 + lane]      = qrow[lane]      * 0.125f;
        qs[warp*64 + lane + 32] = qrow[lane + 32] * 0.125f;
        __syncwarp();

        float s0 = 0.f, s1 = 0.f, s2 = 0.f, s3 = 0.f;
        #pragma unroll 4
        for (int d = 0; d < 64; d++) {
            const float qd = qs[warp*64 + d];
            const float* kr = kT + d*108;
            s0 += qd * kr[lane];
            s1 += qd * kr[lane + 32];
            s2 += qd * kr[lane + 64];
            if (lane < 12) s3 += qd * kr[lane + 96];
        }

        const float rq = rgn[row];
        const float* ebr = eb + row * WTOK;
        float sv[4] = {s0, s1, s2, s3};
        float l[4];
        #pragma unroll
        for (int u = 0; u < 4; u++) {
            const int j = lane + 32*u;
            if (j < WTOK) {
                const float av = (rgn[j] == rq) ? sv[u] * ebr[j] : 0.0f;
                l[u] = (av == 0.0f) ? 10000.0f : -av;
            } else {
                l[u] = -3.0e38f;
            }
        }
        float mx = fmaxf(fmaxf(l[0], l[1]), fmaxf(l[2], l[3]));
        mx = warp_max(mx);
        float p[4], sum = 0.f;
        #pragma unroll
        for (int u = 0; u < 4; u++) { p[u] = expf(l[u] - mx); sum += p[u]; }
        sum = warp_sum(sum);
        const float inv = 1.0f / sum;
        #pragma unroll
        for (int u = 0; u < 4; u++) {
            const int j = lane + 32*u;
            if (j < WTOK) psh[warp*WTOK + j] = p[u] * inv;
        }
        __syncwarp();

        float o1 = 0.f, o2 = 0.f;
        for (int j = 0; j < WTOK; j++) {
            const float pj = psh[warp*WTOK + j];
            o1 += pj * vsh[j*64 + lane];
            o2 += pj * vsh[j*64 + lane + 32];
        }
        bf16* od = o + ((size_t)n * WTOK + row) * 256 + h * 64;
        od[lane]      = __float2bfloat16(o1);
        od[lane + 32] = __float2bfloat16(o2);
    }
}

// ---------------- launch ------------------------------------------------------
extern "C" void kernel_launch(void* const* d_in, const int* in_sizes, int n_in,
                              void* d_out, int out_size)
{
    const float* x      = (const float*)d_in[0];
    const float* eb     = (const float*)d_in[1];
    const float* w_qkv  = (const float*)d_in[2];
    const float* b_qkv  = (const float*)d_in[3];
    const float* w_proj = (const float*)d_in[4];
    const float* b_proj = (const float*)d_in[5];
    const float* g1     = (const float*)d_in[6];
    const float* be1    = (const float*)d_in[7];
    const float* g2     = (const float*)d_in[8];
    const float* be2    = (const float*)d_in[9];
    const float* w_fc1  = (const float*)d_in[10];
    const float* b_fc1  = (const float*)d_in[11];
    const float* w_fc2  = (const float*)d_in[12];
    const float* b_fc2  = (const float*)d_in[13];
    float* out = (float*)d_out;

    float *QKV, *P, *Y;
    bf16 *XNh, *Oh, *H1h, *Wq, *Wp, *W1, *W2;
    cudaGetSymbolAddress((void**)&QKV, g_QKV);
    cudaGetSymbolAddress((void**)&P,   g_P);
    cudaGetSymbolAddress((void**)&Y,   g_Y);
    cudaGetSymbolAddress((void**)&XNh, g_XNh);
    cudaGetSymbolAddress((void**)&Oh,  g_Oh);
    cudaGetSymbolAddress((void**)&H1h, g_H1h);
    cudaGetSymbolAddress((void**)&Wq,  g_Wq);
    cudaGetSymbolAddress((void**)&Wp,  g_Wp);
    cudaGetSymbolAddress((void**)&W1,  g_W1);
    cudaGetSymbolAddress((void**)&W2,  g_W2);

    const int attnSmem = ATTN_SMEM_FLOATS * (int)sizeof(float);
    cudaFuncSetAttribute(attn_kernel,
                         cudaFuncAttributeMaxDynamicSharedMemorySize, attnSmem);
    cudaFuncSetAttribute(hgemm<0,256>,  cudaFuncAttributeMaxDynamicSharedMemorySize, GSMEM);
    cudaFuncSetAttribute(hgemm<1,256>,  cudaFuncAttributeMaxDynamicSharedMemorySize, GSMEM);
    cudaFuncSetAttribute(hgemm<2,256>,  cudaFuncAttributeMaxDynamicSharedMemorySize, GSMEM);
    cudaFuncSetAttribute(hgemm<3,1024>, cudaFuncAttributeMaxDynamicSharedMemorySize, GSMEM);

    // 0) weights fp32 -> bf16
    f2bf_kernel<<<(768*256/4 + 255)/256, 256>>>(w_qkv, Wq, 768*256);
    f2bf_kernel<<<(256*256/4 + 255)/256, 256>>>(w_proj, Wp, 256*256);
    f2bf_kernel<<<(1024*256/4 + 255)/256, 256>>>(w_fc1, W1, 1024*256);
    f2bf_kernel<<<(256*1024/4 + 255)/256, 256>>>(w_fc2, W2, 256*1024);

    // 1) shift + window + LN1 (bf16 out)
    ln1_kernel<<<NTOK / 8, 256>>>(x, g1, be1);
    // 2) QKV GEMM: [NTOK,256] x [256,768] -> fp32
    hgemm<0,256><<<dim3(6, NTOK/128), 256, GSMEM>>>(XNh, Wq, b_qkv, nullptr, QKV, 768);
    // 3) attention per (window, head) -> bf16
    attn_kernel<<<dim3(NWIN, 4), 256, attnSmem>>>(QKV, eb, Oh);
    // 4) proj GEMM + W-roll(+2) in epilogue -> fp32
    hgemm<1,256><<<dim3(2, NTOK/128), 256, GSMEM>>>(Oh, Wp, b_proj, nullptr, P, 256);
    // 5) residual + LN2 (Y fp32, XN bf16)
    res_ln2_kernel<<<NTOK / 8, 256>>>(x, g2, be2);
    // 6) FC1 + GELU -> bf16
    hgemm<2,256><<<dim3(8, NTOK/128), 256, GSMEM>>>(XNh, W1, b_fc1, nullptr, H1h, 1024);
    // 7) FC2 + residual -> fp32 output
    hgemm<3,1024><<<dim3(2, NTOK/128), 256, GSMEM>>>(H1h, W2, b_fc2, Y, out, 256);
}

// round 8
// speedup vs baseline: 5.9332x; 1.8860x over previous
#include <cuda_runtime.h>
#include <cuda_bf16.h>
#include <math.h>
#include <stdint.h>

typedef __nv_bfloat16 bf16;

// Problem constants
#define NTOK   110592          // 1024 windows * 108 tokens
#define NWIN   1024
#define WTOK   108

// ---------------- scratch (static device globals; no allocation) -------------
__device__ float g_QKV[ (size_t)NTOK * 768 ];   // qkv (fp32, attention input)
__device__ float g_P  [ (size_t)NTOK * 256 ];   // proj out, already W-rolled
__device__ float g_Y  [ (size_t)NTOK * 256 ];   // x + attn branch (residual base)
__device__ bf16  g_XNh[ (size_t)NTOK * 256 ];   // LN out (bf16, GEMM A input)
__device__ bf16  g_Oh [ (size_t)NTOK * 256 ];   // attention out (bf16)
__device__ bf16  g_H1h[ (size_t)NTOK * 1024 ];  // FC1+GELU out (bf16)
__device__ bf16  g_Wq [ 768 * 256 ];
__device__ bf16  g_Wp [ 256 * 256 ];
__device__ bf16  g_W1 [ 1024 * 256 ];
__device__ bf16  g_W2 [ 256 * 1024 ];

// ---------------- helpers ----------------------------------------------------
__device__ __forceinline__ float warp_sum(float v){
    #pragma unroll
    for (int o = 16; o; o >>= 1) v += __shfl_xor_sync(0xffffffffu, v, o);
    return v;
}
__device__ __forceinline__ uint32_t smem_u32(const void* p){
    uint32_t a;
    asm("{ .reg .u64 t; cvta.to.shared.u64 t, %1; cvt.u32.u64 %0, t; }"
        : "=r"(a) : "l"(p));
    return a;
}
__device__ __forceinline__ uint32_t pk(float a, float b){
    __nv_bfloat162 t = __floats2bfloat162_rn(a, b);
    return *(uint32_t*)&t;
}

#define LDSM_X4(r0,r1,r2,r3,addr) \
    asm volatile("ldmatrix.sync.aligned.m8n8.x4.shared.b16 {%0,%1,%2,%3}, [%4];" \
        : "=r"(r0), "=r"(r1), "=r"(r2), "=r"(r3) : "r"(addr))
#define LDSM_X4_T(r0,r1,r2,r3,addr) \
    asm volatile("ldmatrix.sync.aligned.m8n8.x4.trans.shared.b16 {%0,%1,%2,%3}, [%4];" \
        : "=r"(r0), "=r"(r1), "=r"(r2), "=r"(r3) : "r"(addr))

__device__ __forceinline__ void mma_bf16(float& c0, float& c1, float& c2, float& c3,
                                         uint32_t a0, uint32_t a1, uint32_t a2, uint32_t a3,
                                         uint32_t b0, uint32_t b1)
{
    asm volatile(
        "mma.sync.aligned.m16n8k16.row.col.f32.bf16.bf16.f32 "
        "{%0,%1,%2,%3}, {%4,%5,%6,%7}, {%8,%9}, {%0,%1,%2,%3};"
        : "+f"(c0), "+f"(c1), "+f"(c2), "+f"(c3)
        : "r"(a0), "r"(a1), "r"(a2), "r"(a3), "r"(b0), "r"(b1));
}

// ---------------- weight fp32 -> bf16 convert ---------------------------------
__global__ void f2bf_kernel(const float* __restrict__ s, bf16* __restrict__ d, int n)
{
    const int i = (blockIdx.x * 256 + threadIdx.x) * 4;
    if (i < n) {
        float4 v = *(const float4*)(s + i);
        __nv_bfloat162* dp = (__nv_bfloat162*)(d + i);
        dp[0] = __floats2bfloat162_rn(v.x, v.y);
        dp[1] = __floats2bfloat162_rn(v.z, v.w);
    }
}

// ---------------- LN1 with shift + window gather (bf16 out) -------------------
__global__ void ln1_kernel(const float* __restrict__ x,
                           const float* __restrict__ g,
                           const float* __restrict__ be)
{
    const int warp = threadIdx.x >> 5, lane = threadIdx.x & 31;
    const int t = blockIdx.x * 8 + warp;
    const int n = t / WTOK, w = t - n * WTOK;
    const int b = n >> 5, f = n & 31;
    const int wf = w / 27;
    const int gf = f * 4 + wf;
    const int fr = (gf + 2) & 127;
    const int kp = w - wf * 27;
    const float* src = x + (size_t)((b * 128 + fr) * 27 + kp) * 256;

    float4 v0 = ((const float4*)src)[lane];
    float4 v1 = ((const float4*)src)[lane + 32];
    float s = v0.x+v0.y+v0.z+v0.w + v1.x+v1.y+v1.z+v1.w;
    float q = v0.x*v0.x+v0.y*v0.y+v0.z*v0.z+v0.w*v0.w
            + v1.x*v1.x+v1.y*v1.y+v1.z*v1.z+v1.w*v1.w;
    s = warp_sum(s); q = warp_sum(q);
    const float mean = s * (1.0f/256.0f);
    const float var  = q * (1.0f/256.0f) - mean*mean;
    const float rstd = rsqrtf(var + 1e-5f);

    __nv_bfloat162* dst = (__nv_bfloat162*)(g_XNh + (size_t)t * 256);
    const int c0 = lane*4, c1 = 128 + lane*4;
    dst[lane*2]        = __floats2bfloat162_rn((v0.x-mean)*rstd*g[c0+0] + be[c0+0],
                                               (v0.y-mean)*rstd*g[c0+1] + be[c0+1]);
    dst[lane*2+1]      = __floats2bfloat162_rn((v0.z-mean)*rstd*g[c0+2] + be[c0+2],
                                               (v0.w-mean)*rstd*g[c0+3] + be[c0+3]);
    dst[64 + lane*2]   = __floats2bfloat162_rn((v1.x-mean)*rstd*g[c1+0] + be[c1+0],
                                               (v1.y-mean)*rstd*g[c1+1] + be[c1+1]);
    dst[64 + lane*2+1] = __floats2bfloat162_rn((v1.z-mean)*rstd*g[c1+2] + be[c1+2],
                                               (v1.w-mean)*rstd*g[c1+3] + be[c1+3]);
}

// ---------------- residual + LN2 (Y fp32, XN bf16) ----------------------------
__global__ void res_ln2_kernel(const float* __restrict__ x,
                               const float* __restrict__ g,
                               const float* __restrict__ be)
{
    const int warp = threadIdx.x >> 5, lane = threadIdx.x & 31;
    const int t = blockIdx.x * 8 + warp;
    const float* xs = x   + (size_t)t * 256;
    const float* ps = g_P + (size_t)t * 256;

    float4 a0 = ((const float4*)xs)[lane];
    float4 a1 = ((const float4*)xs)[lane + 32];
    float4 p0 = ((const float4*)ps)[lane];
    float4 p1 = ((const float4*)ps)[lane + 32];
    float4 v0 = make_float4(a0.x+p0.x, a0.y+p0.y, a0.z+p0.z, a0.w+p0.w);
    float4 v1 = make_float4(a1.x+p1.x, a1.y+p1.y, a1.z+p1.z, a1.w+p1.w);

    float s = v0.x+v0.y+v0.z+v0.w + v1.x+v1.y+v1.z+v1.w;
    float q = v0.x*v0.x+v0.y*v0.y+v0.z*v0.z+v0.w*v0.w
            + v1.x*v1.x+v1.y*v1.y+v1.z*v1.z+v1.w*v1.w;
    s = warp_sum(s); q = warp_sum(q);
    const float mean = s * (1.0f/256.0f);
    const float var  = q * (1.0f/256.0f) - mean*mean;
    const float rstd = rsqrtf(var + 1e-5f);

    float* ydst = g_Y + (size_t)t * 256;
    ((float4*)ydst)[lane]      = v0;
    ((float4*)ydst)[lane + 32] = v1;

    __nv_bfloat162* ndst = (__nv_bfloat162*)(g_XNh + (size_t)t * 256);
    const int c0 = lane*4, c1 = 128 + lane*4;
    ndst[lane*2]        = __floats2bfloat162_rn((v0.x-mean)*rstd*g[c0+0] + be[c0+0],
                                                (v0.y-mean)*rstd*g[c0+1] + be[c0+1]);
    ndst[lane*2+1]      = __floats2bfloat162_rn((v0.z-mean)*rstd*g[c0+2] + be[c0+2],
                                                (v0.w-mean)*rstd*g[c0+3] + be[c0+3]);
    ndst[64 + lane*2]   = __floats2bfloat162_rn((v1.x-mean)*rstd*g[c1+0] + be[c1+0],
                                                (v1.y-mean)*rstd*g[c1+1] + be[c1+1]);
    ndst[64 + lane*2+1] = __floats2bfloat162_rn((v1.z-mean)*rstd*g[c1+2] + be[c1+2],
                                                (v1.w-mean)*rstd*g[c1+3] + be[c1+3]);
}

// ---------------- bf16 mma.sync NT GEMM (unchanged from round 7) -------------
#define BUFB  16384
#define GSMEM (4*BUFB + 128)

template<int EPI>
__device__ __forceinline__ void epi_store(void* __restrict__ C,
                                          const float* __restrict__ Yres,
                                          int N, int m, int col,
                                          float v0, float v1)
{
    if (EPI == 2) {
        v0 = 0.5f*v0*(1.0f + erff(v0*0.70710678118654752f));
        v1 = 0.5f*v1*(1.0f + erff(v1*0.70710678118654752f));
        *(__nv_bfloat162*)((bf16*)C + (size_t)m*N + col) = __floats2bfloat162_rn(v0, v1);
        return;
    }
    if (EPI == 3) {
        const float2 yv = *(const float2*)&Yres[(size_t)m*N + col];
        v0 += yv.x; v1 += yv.y;
    }
    int mout = m;
    if (EPI == 1) {
        const int nw = m / WTOK, w = m - nw * WTOK;
        int w2 = w + 2; if (w2 >= WTOK) w2 -= WTOK;
        mout = nw * WTOK + w2;
    }
    *(float2*)((float*)C + (size_t)mout*N + col) = make_float2(v0, v1);
}

template<int EPI, int KD>
__global__ void __launch_bounds__(256)
hgemm(const bf16* __restrict__ A, const bf16* __restrict__ Bw,
      const float* __restrict__ bias, const float* __restrict__ Yres,
      void* __restrict__ C, int N)
{
    extern __shared__ char smraw[];
    char* sm = (char*)(((uintptr_t)smraw + 127) & ~(uintptr_t)127);

    const int tid = threadIdx.x;
    const int wid = tid >> 5, lane = tid & 31;
    const int warpM = wid >> 2, warpN = wid & 3;   // 2 x 4
    const int bn = blockIdx.x, bm = blockIdx.y;

    const bf16* Ab = A  + (size_t)bm * 128 * KD;
    const bf16* Bb = Bw + (size_t)bn * 128 * KD;

    const uint32_t smb = smem_u32(sm);

    const int aRow = (lane & 7) | (((lane >> 3) & 1) << 3);
    const int aK   = (lane >> 4) & 1;
    const int bRow = (lane & 7) | (((lane >> 4) & 1) << 3);
    const int bK   = (lane >> 3) & 1;

    float acc[4][4][4];
    #pragma unroll
    for (int i = 0; i < 4; i++)
        #pragma unroll
        for (int j = 0; j < 4; j++)
            #pragma unroll
            for (int q = 0; q < 4; q++) acc[i][j][q] = 0.0f;

    auto load_chunk = [&](int buf, int kbase){
        const uint32_t sa = smb + buf * 2 * BUFB;
        const uint32_t sb = sa + BUFB;
        #pragma unroll
        for (int i = 0; i < 4; i++) {
            const int idx = tid + 256*i;
            const int row = idx >> 3, q = idx & 7;
            const uint32_t off = row*128 + ((q ^ (row & 7)) << 4);
            const size_t goff = (size_t)row*KD + kbase + q*8;
            asm volatile("cp.async.cg.shared.global [%0], [%1], 16;"
                         :: "r"(sa + off), "l"(Ab + goff));
            asm volatile("cp.async.cg.shared.global [%0], [%1], 16;"
                         :: "r"(sb + off), "l"(Bb + goff));
        }
    };

    constexpr int NC = KD / 64;
    load_chunk(0, 0);
    asm volatile("cp.async.commit_group;" ::: "memory");

    for (int c = 0; c < NC; c++) {
        asm volatile("cp.async.wait_group 0;" ::: "memory");
        __syncthreads();
        if (c + 1 < NC) {
            load_chunk((c+1) & 1, (c+1)*64);
            asm volatile("cp.async.commit_group;" ::: "memory");
        }
        const uint32_t saA = smb + (c & 1) * 2 * BUFB;
        const uint32_t saB = saA + BUFB;

        #pragma unroll
        for (int s = 0; s < 4; s++) {
            const int cch = s * 2;
            uint32_t a[4][4];
            #pragma unroll
            for (int mt = 0; mt < 4; mt++) {
                const int row = warpM*64 + mt*16 + aRow;
                const uint32_t off = row*128 + (((cch + aK) ^ (row & 7)) << 4);
                LDSM_X4(a[mt][0], a[mt][1], a[mt][2], a[mt][3], saA + off);
            }
            uint32_t b[4][2];
            #pragma unroll
            for (int p = 0; p < 2; p++) {
                const int row = warpN*32 + p*16 + bRow;
                const uint32_t off = row*128 + (((cch + bK) ^ (row & 7)) << 4);
                LDSM_X4(b[2*p][0], b[2*p][1], b[2*p+1][0], b[2*p+1][1], saB + off);
            }
            #pragma unroll
            for (int mt = 0; mt < 4; mt++)
                #pragma unroll
                for (int nt = 0; nt < 4; nt++)
                    mma_bf16(acc[mt][nt][0], acc[mt][nt][1],
                             acc[mt][nt][2], acc[mt][nt][3],
                             a[mt][0], a[mt][1], a[mt][2], a[mt][3],
                             b[nt][0], b[nt][1]);
        }
        __syncthreads();
    }

    const int g = lane >> 2, t = lane & 3;
    #pragma unroll
    for (int mt = 0; mt < 4; mt++) {
        const int r0 = bm*128 + warpM*64 + mt*16 + g;
        #pragma unroll
        for (int nt = 0; nt < 4; nt++) {
            const int col = bn*128 + warpN*32 + nt*8 + t*2;
            const float2 bv = *(const float2*)&bias[col];
            epi_store<EPI>(C, Yres, N, r0,     col,
                           acc[mt][nt][0] + bv.x, acc[mt][nt][1] + bv.y);
            epi_store<EPI>(C, Yres, N, r0 + 8, col,
                           acc[mt][nt][2] + bv.x, acc[mt][nt][3] + bv.y);
        }
    }
}

// ---------------- tensor-core windowed attention ------------------------------
// Block = (window, head), 128 threads (4 warps). Padded W: 112 = 7 m16 tiles.
// smem: Q/K/V bf16 112x64 (128B rows, XOR swizzle), P bf16 112x128 (256B rows).
#define SMQ 0
#define SMK 14336
#define SMV 28672
#define SMP 43008
#define SMRGN 71680
#define ATTN_SMEM (71680 + 512)

__global__ void __launch_bounds__(128)
attn_kernel(const float* __restrict__ qkv,
            const float* __restrict__ eb,
            bf16* __restrict__ o)
{
    extern __shared__ char smraw[];
    const uint32_t smb = smem_u32(smraw);
    int* rgn = (int*)(smraw + SMRGN);

    const int n = blockIdx.x, h = blockIdx.y;
    const int tid = threadIdx.x, warp = tid >> 5, lane = tid & 31;
    const int f = n & 31;
    const size_t base = (size_t)n * WTOK * 768;

    // load Q (scaled), K, V -> swizzled bf16 smem; zero pad rows 108..111
    for (int idx = tid; idx < 112*8; idx += 128) {
        const int row = idx >> 3, q = idx & 7;
        const uint32_t off = row*128 + ((q ^ (row & 7)) << 4);
        uint4 uq = {0,0,0,0}, uk = {0,0,0,0}, uv = {0,0,0,0};
        if (row < WTOK) {
            const float* rp = qkv + base + (size_t)row * 768 + h*64 + q*8;
            float4 a = *(const float4*)(rp);
            float4 b = *(const float4*)(rp + 4);
            uq = make_uint4(pk(a.x*0.125f, a.y*0.125f), pk(a.z*0.125f, a.w*0.125f),
                            pk(b.x*0.125f, b.y*0.125f), pk(b.z*0.125f, b.w*0.125f));
            a = *(const float4*)(rp + 256); b = *(const float4*)(rp + 260);
            uk = make_uint4(pk(a.x,a.y), pk(a.z,a.w), pk(b.x,b.y), pk(b.z,b.w));
            a = *(const float4*)(rp + 512); b = *(const float4*)(rp + 516);
            uv = make_uint4(pk(a.x,a.y), pk(a.z,a.w), pk(b.x,b.y), pk(b.z,b.w));
        }
        *(uint4*)(smraw + SMQ + off) = uq;
        *(uint4*)(smraw + SMK + off) = uk;
        *(uint4*)(smraw + SMV + off) = uv;
    }
    for (int w = tid; w < 112; w += 128) {
        if (w < WTOK) {
            const int gf = f * 4 + w / 27;
            rgn[w] = (gf >= 126) ? 2 : ((gf >= 124) ? 1 : 0);
        } else rgn[w] = -1;
    }
    __syncthreads();

    const int aRow = (lane & 7) | (((lane >> 3) & 1) << 3);
    const int aK   = (lane >> 4) & 1;
    const int bRow = (lane & 7) | (((lane >> 4) & 1) << 3);
    const int bK   = (lane >> 3) & 1;
    const int g = lane >> 2, t4 = lane & 3;

    for (int mt = warp; mt < 7; mt += 4) {
        // ---- S = Q @ K^T ----
        float sacc[14][4];
        #pragma unroll
        for (int nt = 0; nt < 14; nt++)
            #pragma unroll
            for (int q = 0; q < 4; q++) sacc[nt][q] = 0.0f;

        #pragma unroll
        for (int s = 0; s < 4; s++) {
            const int cch = 2*s;
            uint32_t a0,a1,a2,a3;
            {
                const int row = mt*16 + aRow;
                const uint32_t off = row*128 + (((cch + aK) ^ (row & 7)) << 4);
                LDSM_X4(a0,a1,a2,a3, smb + SMQ + off);
            }
            uint32_t bq[14][2];
            #pragma unroll
            for (int p = 0; p < 7; p++) {
                const int row = p*16 + bRow;
                const uint32_t off = row*128 + (((cch + bK) ^ (row & 7)) << 4);
                LDSM_X4(bq[2*p][0], bq[2*p][1], bq[2*p+1][0], bq[2*p+1][1],
                        smb + SMK + off);
            }
            #pragma unroll
            for (int nt = 0; nt < 14; nt++)
                mma_bf16(sacc[nt][0], sacc[nt][1], sacc[nt][2], sacc[nt][3],
                         a0,a1,a2,a3, bq[nt][0], bq[nt][1]);
        }

        // ---- softmax (reference quirks) ----
        const int r0 = mt*16 + g, r1 = r0 + 8;
        const int rq0 = rgn[r0], rq1 = rgn[r1];
        #pragma unroll
        for (int nt = 0; nt < 14; nt++) {
            const int j0 = nt*8 + t4*2;
            const bool jc = j0 < WTOK;
            float2 e0 = make_float2(0.f,0.f), e1 = make_float2(0.f,0.f);
            if (jc)              e0 = *(const float2*)(eb + r0*WTOK + j0);
            if (jc && r1 < WTOK) e1 = *(const float2*)(eb + r1*WTOK + j0);
            const int rj0 = rgn[j0], rj1 = rgn[j0+1];
            float av;
            av = (rj0==rq0) ? sacc[nt][0]*e0.x : 0.f;
            sacc[nt][0] = jc ? ((av==0.f) ? 10000.0f : -av) : -3.0e38f;
            av = (rj1==rq0) ? sacc[nt][1]*e0.y : 0.f;
            sacc[nt][1] = jc ? ((av==0.f) ? 10000.0f : -av) : -3.0e38f;
            av = (rj0==rq1) ? sacc[nt][2]*e1.x : 0.f;
            sacc[nt][2] = jc ? ((av==0.f) ? 10000.0f : -av) : -3.0e38f;
            av = (rj1==rq1) ? sacc[nt][3]*e1.y : 0.f;
            sacc[nt][3] = jc ? ((av==0.f) ? 10000.0f : -av) : -3.0e38f;
        }
        float m0 = -3.0e38f, m1 = -3.0e38f;
        #pragma unroll
        for (int nt = 0; nt < 14; nt++) {
            m0 = fmaxf(m0, fmaxf(sacc[nt][0], sacc[nt][1]));
            m1 = fmaxf(m1, fmaxf(sacc[nt][2], sacc[nt][3]));
        }
        #pragma unroll
        for (int ofs = 1; ofs <= 2; ofs <<= 1) {
            m0 = fmaxf(m0, __shfl_xor_sync(0xffffffffu, m0, ofs));
            m1 = fmaxf(m1, __shfl_xor_sync(0xffffffffu, m1, ofs));
        }
        float s0 = 0.f, s1 = 0.f;
        #pragma unroll
        for (int nt = 0; nt < 14; nt++) {
            sacc[nt][0] = expf(sacc[nt][0] - m0); s0 += sacc[nt][0];
            sacc[nt][1] = expf(sacc[nt][1] - m0); s0 += sacc[nt][1];
            sacc[nt][2] = expf(sacc[nt][2] - m1); s1 += sacc[nt][2];
            sacc[nt][3] = expf(sacc[nt][3] - m1); s1 += sacc[nt][3];
        }
        #pragma unroll
        for (int ofs = 1; ofs <= 2; ofs <<= 1) {
            s0 += __shfl_xor_sync(0xffffffffu, s0, ofs);
            s1 += __shfl_xor_sync(0xffffffffu, s1, ofs);
        }
        const float i0 = 1.0f / s0, i1 = 1.0f / s1;

        // store P (bf16) -- pad cols are exactly 0 via exp(-3e38 - m) = 0
        #pragma unroll
        for (int nt = 0; nt < 14; nt++) {
            const uint32_t chi = (uint32_t)(nt >> 3) << 7;
            const uint32_t a0off = r0*256 + chi + ((((uint32_t)nt & 7) ^ (r0 & 7)) << 4) + t4*4;
            const uint32_t a1off = r1*256 + chi + ((((uint32_t)nt & 7) ^ (r1 & 7)) << 4) + t4*4;
            *(uint32_t*)(smraw + SMP + a0off) = pk(sacc[nt][0]*i0, sacc[nt][1]*i0);
            *(uint32_t*)(smraw + SMP + a1off) = pk(sacc[nt][2]*i1, sacc[nt][3]*i1);
        }
        __syncwarp();

        // ---- O = P @ V ----
        float oacc[8][4];
        #pragma unroll
        for (int nt = 0; nt < 8; nt++)
            #pragma unroll
            for (int q = 0; q < 4; q++) oacc[nt][q] = 0.0f;

        #pragma unroll
        for (int sp = 0; sp < 7; sp++) {
            uint32_t a0,a1,a2,a3;
            {
                const int row = mt*16 + aRow;
                const int c = 2*sp + aK;
                const uint32_t off = row*256 + ((uint32_t)(c >> 3) << 7)
                                   + ((((uint32_t)c & 7) ^ (row & 7)) << 4);
                LDSM_X4(a0,a1,a2,a3, smb + SMP + off);
            }
            uint32_t bv[8][2];
            #pragma unroll
            for (int ntp = 0; ntp < 4; ntp++) {
                const int vrow = sp*16 + (lane & 7) + 8*((lane >> 3) & 1);
                const int ch = ntp*2 + ((lane >> 4) & 1);
                const uint32_t off = vrow*128 + (((uint32_t)ch ^ (vrow & 7)) << 4);
                LDSM_X4_T(bv[2*ntp][0], bv[2*ntp][1], bv[2*ntp+1][0], bv[2*ntp+1][1],
                          smb + SMV + off);
            }
            #pragma unroll
            for (int nt = 0; nt < 8; nt++)
                mma_bf16(oacc[nt][0], oacc[nt][1], oacc[nt][2], oacc[nt][3],
                         a0,a1,a2,a3, bv[nt][0], bv[nt][1]);
        }

        // ---- write O (bf16) ----
        bf16* ob = o + ((size_t)n * WTOK) * 256 + h*64;
        #pragma unroll
        for (int nt = 0; nt < 8; nt++) {
            const int col = nt*8 + t4*2;
            *(uint32_t*)(ob + (size_t)r0*256 + col) = pk(oacc[nt][0], oacc[nt][1]);
            if (r1 < WTOK)
                *(uint32_t*)(ob + (size_t)r1*256 + col) = pk(oacc[nt][2], oacc[nt][3]);
        }
    }
}

// ---------------- launch ------------------------------------------------------
extern "C" void kernel_launch(void* const* d_in, const int* in_sizes, int n_in,
                              void* d_out, int out_size)
{
    const float* x      = (const float*)d_in[0];
    const float* eb     = (const float*)d_in[1];
    const float* w_qkv  = (const float*)d_in[2];
    const float* b_qkv  = (const float*)d_in[3];
    const float* w_proj = (const float*)d_in[4];
    const float* b_proj = (const float*)d_in[5];
    const float* g1     = (const float*)d_in[6];
    const float* be1    = (const float*)d_in[7];
    const float* g2     = (const float*)d_in[8];
    const float* be2    = (const float*)d_in[9];
    const float* w_fc1  = (const float*)d_in[10];
    const float* b_fc1  = (const float*)d_in[11];
    const float* w_fc2  = (const float*)d_in[12];
    const float* b_fc2  = (const float*)d_in[13];
    float* out = (float*)d_out;

    float *QKV, *P, *Y;
    bf16 *XNh, *Oh, *H1h, *Wq, *Wp, *W1, *W2;
    cudaGetSymbolAddress((void**)&QKV, g_QKV);
    cudaGetSymbolAddress((void**)&P,   g_P);
    cudaGetSymbolAddress((void**)&Y,   g_Y);
    cudaGetSymbolAddress((void**)&XNh, g_XNh);
    cudaGetSymbolAddress((void**)&Oh,  g_Oh);
    cudaGetSymbolAddress((void**)&H1h, g_H1h);
    cudaGetSymbolAddress((void**)&Wq,  g_Wq);
    cudaGetSymbolAddress((void**)&Wp,  g_Wp);
    cudaGetSymbolAddress((void**)&W1,  g_W1);
    cudaGetSymbolAddress((void**)&W2,  g_W2);

    cudaFuncSetAttribute(attn_kernel,
                         cudaFuncAttributeMaxDynamicSharedMemorySize, ATTN_SMEM);
    cudaFuncSetAttribute(hgemm<0,256>,  cudaFuncAttributeMaxDynamicSharedMemorySize, GSMEM);
    cudaFuncSetAttribute(hgemm<1,256>,  cudaFuncAttributeMaxDynamicSharedMemorySize, GSMEM);
    cudaFuncSetAttribute(hgemm<2,256>,  cudaFuncAttributeMaxDynamicSharedMemorySize, GSMEM);
    cudaFuncSetAttribute(hgemm<3,1024>, cudaFuncAttributeMaxDynamicSharedMemorySize, GSMEM);

    // 0) weights fp32 -> bf16
    f2bf_kernel<<<(768*256/4 + 255)/256, 256>>>(w_qkv, Wq, 768*256);
    f2bf_kernel<<<(256*256/4 + 255)/256, 256>>>(w_proj, Wp, 256*256);
    f2bf_kernel<<<(1024*256/4 + 255)/256, 256>>>(w_fc1, W1, 1024*256);
    f2bf_kernel<<<(256*1024/4 + 255)/256, 256>>>(w_fc2, W2, 256*1024);

    // 1) shift + window + LN1 (bf16 out)
    ln1_kernel<<<NTOK / 8, 256>>>(x, g1, be1);
    // 2) QKV GEMM
    hgemm<0,256><<<dim3(6, NTOK/128), 256, GSMEM>>>(XNh, Wq, b_qkv, nullptr, QKV, 768);
    // 3) attention (tensor cores)
    attn_kernel<<<dim3(NWIN, 4), 128, ATTN_SMEM>>>(QKV, eb, Oh);
    // 4) proj GEMM + W-roll(+2)
    hgemm<1,256><<<dim3(2, NTOK/128), 256, GSMEM>>>(Oh, Wp, b_proj, nullptr, P, 256);
    // 5) residual + LN2
    res_ln2_kernel<<<NTOK / 8, 256>>>(x, g2, be2);
    // 6) FC1 + GELU
    hgemm<2,256><<<dim3(8, NTOK/128), 256, GSMEM>>>(XNh, W1, b_fc1, nullptr, H1h, 1024);
    // 7) FC2 + residual -> output
    hgemm<3,1024><<<dim3(2, NTOK/128), 256, GSMEM>>>(H1h, W2, b_fc2, Y, out, 256);
}

// round 11
// speedup vs baseline: 6.1265x; 1.0326x over previous
#include <cuda_runtime.h>
#include <cuda_bf16.h>
#include <math.h>
#include <stdint.h>

typedef __nv_bfloat16 bf16;

// Problem constants
#define NTOK   110592          // 1024 windows * 108 tokens
#define NWIN   1024
#define WTOK   108

// ---------------- scratch (static device globals; no allocation) -------------
__device__ bf16  g_QKVh[ (size_t)NTOK * 768 ];  // qkv (bf16, q pre-scaled)
__device__ float g_P  [ (size_t)NTOK * 256 ];   // proj out, already W-rolled
__device__ float g_Y  [ (size_t)NTOK * 256 ];   // x + attn branch (residual base)
__device__ bf16  g_XNh[ (size_t)NTOK * 256 ];   // LN out (bf16, GEMM A input)
__device__ bf16  g_Oh [ (size_t)NTOK * 256 ];   // attention out (bf16)
__device__ bf16  g_H1h[ (size_t)NTOK * 1024 ];  // FC1+GELU out (bf16)
__device__ bf16  g_Wq [ 768 * 256 ];
__device__ bf16  g_Wp [ 256 * 256 ];
__device__ bf16  g_W1 [ 1024 * 256 ];
__device__ bf16  g_W2 [ 256 * 1024 ];

// ---------------- helpers ----------------------------------------------------
__device__ __forceinline__ float warp_sum(float v){
    #pragma unroll
    for (int o = 16; o; o >>= 1) v += __shfl_xor_sync(0xffffffffu, v, o);
    return v;
}
__device__ __forceinline__ uint32_t smem_u32(const void* p){
    uint32_t a;
    asm("{ .reg .u64 t; cvta.to.shared.u64 t, %1; cvt.u32.u64 %0, t; }"
        : "=r"(a) : "l"(p));
    return a;
}
__device__ __forceinline__ uint32_t pk(float a, float b){
    __nv_bfloat162 t = __floats2bfloat162_rn(a, b);
    return *(uint32_t*)&t;
}

#define LDSM_X4(r0,r1,r2,r3,addr) \
    asm volatile("ldmatrix.sync.aligned.m8n8.x4.shared.b16 {%0,%1,%2,%3}, [%4];" \
        : "=r"(r0), "=r"(r1), "=r"(r2), "=r"(r3) : "r"(addr))
#define LDSM_X4_T(r0,r1,r2,r3,addr) \
    asm volatile("ldmatrix.sync.aligned.m8n8.x4.trans.shared.b16 {%0,%1,%2,%3}, [%4];" \
        : "=r"(r0), "=r"(r1), "=r"(r2), "=r"(r3) : "r"(addr))

__device__ __forceinline__ void mma_bf16(float& c0, float& c1, float& c2, float& c3,
                                         uint32_t a0, uint32_t a1, uint32_t a2, uint32_t a3,
                                         uint32_t b0, uint32_t b1)
{
    asm volatile(
        "mma.sync.aligned.m16n8k16.row.col.f32.bf16.bf16.f32 "
        "{%0,%1,%2,%3}, {%4,%5,%6,%7}, {%8,%9}, {%0,%1,%2,%3};"
        : "+f"(c0), "+f"(c1), "+f"(c2), "+f"(c3)
        : "r"(a0), "r"(a1), "r"(a2), "r"(a3), "r"(b0), "r"(b1));
}

// ---------------- merged weight fp32 -> bf16 convert --------------------------
#define WQ_N (768*256)
#define WP_N (256*256)
#define W1_N (1024*256)
#define W2_N (256*1024)
__global__ void f2bf_all(const float* __restrict__ wq, const float* __restrict__ wp,
                         const float* __restrict__ w1, const float* __restrict__ w2)
{
    int i = (blockIdx.x * 256 + threadIdx.x) * 4;
    const float* s; bf16* d;
    if (i < WQ_N)                       { s = wq + i;  d = g_Wq + i; }
    else if ((i -= WQ_N) < WP_N)        { s = wp + i;  d = g_Wp + i; }
    else if ((i -= WP_N) < W1_N)        { s = w1 + i;  d = g_W1 + i; }
    else if ((i -= W1_N) < W2_N)        { s = w2 + i;  d = g_W2 + i; }
    else return;
    float4 v = *(const float4*)s;
    __nv_bfloat162* dp = (__nv_bfloat162*)d;
    dp[0] = __floats2bfloat162_rn(v.x, v.y);
    dp[1] = __floats2bfloat162_rn(v.z, v.w);
}

// ---------------- LN1 with shift + window gather (bf16 out) -------------------
__global__ void ln1_kernel(const float* __restrict__ x,
                           const float* __restrict__ g,
                           const float* __restrict__ be)
{
    const int warp = threadIdx.x >> 5, lane = threadIdx.x & 31;
    const int t = blockIdx.x * 8 + warp;
    const int n = t / WTOK, w = t - n * WTOK;
    const int b = n >> 5, f = n & 31;
    const int wf = w / 27;
    const int gf = f * 4 + wf;
    const int fr = (gf + 2) & 127;
    const int kp = w - wf * 27;
    const float* src = x + (size_t)((b * 128 + fr) * 27 + kp) * 256;

    float4 v0 = ((const float4*)src)[lane];
    float4 v1 = ((const float4*)src)[lane + 32];
    float s = v0.x+v0.y+v0.z+v0.w + v1.x+v1.y+v1.z+v1.w;
    float q = v0.x*v0.x+v0.y*v0.y+v0.z*v0.z+v0.w*v0.w
            + v1.x*v1.x+v1.y*v1.y+v1.z*v1.z+v1.w*v1.w;
    s = warp_sum(s); q = warp_sum(q);
    const float mean = s * (1.0f/256.0f);
    const float var  = q * (1.0f/256.0f) - mean*mean;
    const float rstd = rsqrtf(var + 1e-5f);

    __nv_bfloat162* dst = (__nv_bfloat162*)(g_XNh + (size_t)t * 256);
    const int c0 = lane*4, c1 = 128 + lane*4;
    dst[lane*2]        = __floats2bfloat162_rn((v0.x-mean)*rstd*g[c0+0] + be[c0+0],
                                               (v0.y-mean)*rstd*g[c0+1] + be[c0+1]);
    dst[lane*2+1]      = __floats2bfloat162_rn((v0.z-mean)*rstd*g[c0+2] + be[c0+2],
                                               (v0.w-mean)*rstd*g[c0+3] + be[c0+3]);
    dst[64 + lane*2]   = __floats2bfloat162_rn((v1.x-mean)*rstd*g[c1+0] + be[c1+0],
                                               (v1.y-mean)*rstd*g[c1+1] + be[c1+1]);
    dst[64 + lane*2+1] = __floats2bfloat162_rn((v1.z-mean)*rstd*g[c1+2] + be[c1+2],
                                               (v1.w-mean)*rstd*g[c1+3] + be[c1+3]);
}

// ---------------- residual + LN2 (Y fp32, XN bf16) ----------------------------
__global__ void res_ln2_kernel(const float* __restrict__ x,
                               const float* __restrict__ g,
                               const float* __restrict__ be)
{
    const int warp = threadIdx.x >> 5, lane = threadIdx.x & 31;
    const int t = blockIdx.x * 8 + warp;
    const float* xs = x   + (size_t)t * 256;
    const float* ps = g_P + (size_t)t * 256;

    float4 a0 = ((const float4*)xs)[lane];
    float4 a1 = ((const float4*)xs)[lane + 32];
    float4 p0 = ((const float4*)ps)[lane];
    float4 p1 = ((const float4*)ps)[lane + 32];
    float4 v0 = make_float4(a0.x+p0.x, a0.y+p0.y, a0.z+p0.z, a0.w+p0.w);
    float4 v1 = make_float4(a1.x+p1.x, a1.y+p1.y, a1.z+p1.z, a1.w+p1.w);

    float s = v0.x+v0.y+v0.z+v0.w + v1.x+v1.y+v1.z+v1.w;
    float q = v0.x*v0.x+v0.y*v0.y+v0.z*v0.z+v0.w*v0.w
            + v1.x*v1.x+v1.y*v1.y+v1.z*v1.z+v1.w*v1.w;
    s = warp_sum(s); q = warp_sum(q);
    const float mean = s * (1.0f/256.0f);
    const float var  = q * (1.0f/256.0f) - mean*mean;
    const float rstd = rsqrtf(var + 1e-5f);

    float* ydst = g_Y + (size_t)t * 256;
    ((float4*)ydst)[lane]      = v0;
    ((float4*)ydst)[lane + 32] = v1;

    __nv_bfloat162* ndst = (__nv_bfloat162*)(g_XNh + (size_t)t * 256);
    const int c0 = lane*4, c1 = 128 + lane*4;
    ndst[lane*2]        = __floats2bfloat162_rn((v0.x-mean)*rstd*g[c0+0] + be[c0+0],
                                                (v0.y-mean)*rstd*g[c0+1] + be[c0+1]);
    ndst[lane*2+1]      = __floats2bfloat162_rn((v0.z-mean)*rstd*g[c0+2] + be[c0+2],
                                                (v0.w-mean)*rstd*g[c0+3] + be[c0+3]);
    ndst[64 + lane*2]   = __floats2bfloat162_rn((v1.x-mean)*rstd*g[c1+0] + be[c1+0],
                                                (v1.y-mean)*rstd*g[c1+1] + be[c1+1]);
    ndst[64 + lane*2+1] = __floats2bfloat162_rn((v1.z-mean)*rstd*g[c1+2] + be[c1+2],
                                                (v1.w-mean)*rstd*g[c1+3] + be[c1+3]);
}

// ---------------- bf16 mma.sync NT GEMM, 3-stage cp.async pipeline -----------
// EPI: 0 = +bias, *0.125 for cols<256, bf16 out (QKV)
//      1 = +bias, row-rolled +2 in window, fp32 out (PROJ)
//      2 = +bias, exact GELU, bf16 out (FC1)
//      3 = +bias + Yres residual, fp32 out (FC2 -> final)
#define BUFB  16384
#define STGB  (2*BUFB)
#define GSMEM (3*STGB + 128)

template<int EPI>
__device__ __forceinline__ void epi_store(void* __restrict__ C,
                                          const float* __restrict__ Yres,
                                          int N, int m, int col,
                                          float v0, float v1)
{
    if (EPI == 0) {
        const float sc = (col < 256) ? 0.125f : 1.0f;
        *(__nv_bfloat162*)((bf16*)C + (size_t)m*N + col) =
            __floats2bfloat162_rn(v0*sc, v1*sc);
        return;
    }
    if (EPI == 2) {
        v0 = 0.5f*v0*(1.0f + erff(v0*0.70710678118654752f));
        v1 = 0.5f*v1*(1.0f + erff(v1*0.70710678118654752f));
        *(__nv_bfloat162*)((bf16*)C + (size_t)m*N + col) = __floats2bfloat162_rn(v0, v1);
        return;
    }
    if (EPI == 3) {
        const float2 yv = *(const float2*)&Yres[(size_t)m*N + col];
        v0 += yv.x; v1 += yv.y;
    }
    int mout = m;
    if (EPI == 1) {
        const int nw = m / WTOK, w = m - nw * WTOK;
        int w2 = w + 2; if (w2 >= WTOK) w2 -= WTOK;
        mout = nw * WTOK + w2;
    }
    *(float2*)((float*)C + (size_t)mout*N + col) = make_float2(v0, v1);
}

template<int EPI, int KD>
__global__ void __launch_bounds__(256)
hgemm(const bf16* __restrict__ A, const bf16* __restrict__ Bw,
      const float* __restrict__ bias, const float* __restrict__ Yres,
      void* __restrict__ C, int N)
{
    extern __shared__ char smraw[];
    char* sm = (char*)(((uintptr_t)smraw + 127) & ~(uintptr_t)127);

    const int tid = threadIdx.x;
    const int wid = tid >> 5, lane = tid & 31;
    const int warpM = wid >> 2, warpN = wid & 3;   // 2 x 4
    const int bn = blockIdx.x, bm = blockIdx.y;

    const bf16* Ab = A  + (size_t)bm * 128 * KD;
    const bf16* Bb = Bw + (size_t)bn * 128 * KD;

    const uint32_t smb = smem_u32(sm);

    const int aRow = (lane & 7) | (((lane >> 3) & 1) << 3);
    const int aK   = (lane >> 4) & 1;
    const int bRow = (lane & 7) | (((lane >> 4) & 1) << 3);
    const int bK   = (lane >> 3) & 1;

    float acc[4][4][4];
    #pragma unroll
    for (int i = 0; i < 4; i++)
        #pragma unroll
        for (int j = 0; j < 4; j++)
            #pragma unroll
            for (int q = 0; q < 4; q++) acc[i][j][q] = 0.0f;

    auto load_chunk = [&](int buf, int kbase){
        const uint32_t sa = smb + buf * STGB;
        const uint32_t sb = sa + BUFB;
        #pragma unroll
        for (int i = 0; i < 4; i++) {
            const int idx = tid + 256*i;
            const int row = idx >> 3, q = idx & 7;
            const uint32_t off = row*128 + ((q ^ (row & 7)) << 4);
            const size_t goff = (size_t)row*KD + kbase + q*8;
            asm volatile("cp.async.cg.shared.global [%0], [%1], 16;"
                         :: "r"(sa + off), "l"(Ab + goff));
            asm volatile("cp.async.cg.shared.global [%0], [%1], 16;"
                         :: "r"(sb + off), "l"(Bb + goff));
        }
        asm volatile("cp.async.commit_group;" ::: "memory");
    };

    constexpr int NC = KD / 64;
    load_chunk(0, 0);
    if (NC > 1) load_chunk(1, 64);

    for (int c = 0; c < NC; c++) {
        if (c + 1 < NC) asm volatile("cp.async.wait_group 1;" ::: "memory");
        else            asm volatile("cp.async.wait_group 0;" ::: "memory");
        __syncthreads();
        if (c + 2 < NC) load_chunk((c + 2) % 3, (c + 2) * 64);

        const uint32_t saA = smb + (c % 3) * STGB;
        const uint32_t saB = saA + BUFB;

        #pragma unroll
        for (int s = 0; s < 4; s++) {
            const int cch = s * 2;
            uint32_t a[4][4];
            #pragma unroll
            for (int mt = 0; mt < 4; mt++) {
                const int row = warpM*64 + mt*16 + aRow;
                const uint32_t off = row*128 + (((cch + aK) ^ (row & 7)) << 4);
                LDSM_X4(a[mt][0], a[mt][1], a[mt][2], a[mt][3], saA + off);
            }
            uint32_t b[4][2];
            #pragma unroll
            for (int p = 0; p < 2; p++) {
                const int row = warpN*32 + p*16 + bRow;
                const uint32_t off = row*128 + (((cch + bK) ^ (row & 7)) << 4);
                LDSM_X4(b[2*p][0], b[2*p][1], b[2*p+1][0], b[2*p+1][1], saB + off);
            }
            #pragma unroll
            for (int mt = 0; mt < 4; mt++)
                #pragma unroll
                for (int nt = 0; nt < 4; nt++)
                    mma_bf16(acc[mt][nt][0], acc[mt][nt][1],
                             acc[mt][nt][2], acc[mt][nt][3],
                             a[mt][0], a[mt][1], a[mt][2], a[mt][3],
                             b[nt][0], b[nt][1]);
        }
    }

    const int g = lane >> 2, t = lane & 3;
    #pragma unroll
    for (int mt = 0; mt < 4; mt++) {
        const int r0 = bm*128 + warpM*64 + mt*16 + g;
        #pragma unroll
        for (int nt = 0; nt < 4; nt++) {
            const int col = bn*128 + warpN*32 + nt*8 + t*2;
            const float2 bv = *(const float2*)&bias[col];
            epi_store<EPI>(C, Yres, N, r0,     col,
                           acc[mt][nt][0] + bv.x, acc[mt][nt][1] + bv.y);
            epi_store<EPI>(C, Yres, N, r0 + 8, col,
                           acc[mt][nt][2] + bv.x, acc[mt][nt][3] + bv.y);
        }
    }
}

// ---------------- tensor-core windowed attention (bf16 QKV in) ----------------
// Block = (window, head), 128 threads (4 warps). Padded W: 112 = 7 m16 tiles.
#define SMQ 0
#define SMK 14336
#define SMV 28672
#define SMP 43008
#define SMRGN 71680
#define ATTN_SMEM (71680 + 512)

__global__ void __launch_bounds__(128)
attn_kernel(const bf16* __restrict__ qkv,
            const float* __restrict__ eb,
            bf16* __restrict__ o)
{
    extern __shared__ char smraw[];
    const uint32_t smb = smem_u32(smraw);
    int* rgn = (int*)(smraw + SMRGN);

    const int n = blockIdx.x, h = blockIdx.y;
    const int tid = threadIdx.x, warp = tid >> 5, lane = tid & 31;
    const int f = n & 31;
    const size_t base = (size_t)n * WTOK * 768;

    // load Q(prescaled)/K/V bf16 -> swizzled smem; zero pad rows 108..111
    for (int idx = tid; idx < 112*8; idx += 128) {
        const int row = idx >> 3, q = idx & 7;
        const uint32_t off = row*128 + ((q ^ (row & 7)) << 4);
        uint4 uq = {0,0,0,0}, uk = {0,0,0,0}, uv = {0,0,0,0};
        if (row < WTOK) {
            const bf16* rp = qkv + base + (size_t)row * 768 + h*64 + q*8;
            uq = *(const uint4*)(rp);
            uk = *(const uint4*)(rp + 256);
            uv = *(const uint4*)(rp + 512);
        }
        *(uint4*)(smraw + SMQ + off) = uq;
        *(uint4*)(smraw + SMK + off) = uk;
        *(uint4*)(smraw + SMV + off) = uv;
    }
    for (int w = tid; w < 112; w += 128) {
        if (w < WTOK) {
            const int gf = f * 4 + w / 27;
            rgn[w] = (gf >= 126) ? 2 : ((gf >= 124) ? 1 : 0);
        } else rgn[w] = -1;
    }
    __syncthreads();

    const int aRow = (lane & 7) | (((lane >> 3) & 1) << 3);
    const int aK   = (lane >> 4) & 1;
    const int bRow = (lane & 7) | (((lane >> 4) & 1) << 3);
    const int bK   = (lane >> 3) & 1;
    const int g = lane >> 2, t4 = lane & 3;

    for (int mt = warp; mt < 7; mt += 4) {
        // ---- S = Q @ K^T ----
        float sacc[14][4];
        #pragma unroll
        for (int nt = 0; nt < 14; nt++)
            #pragma unroll
            for (int q = 0; q < 4; q++) sacc[nt][q] = 0.0f;

        #pragma unroll
        for (int s = 0; s < 4; s++) {
            const int cch = 2*s;
            uint32_t a0,a1,a2,a3;
            {
                const int row = mt*16 + aRow;
                const uint32_t off = row*128 + (((cch + aK) ^ (row & 7)) << 4);
                LDSM_X4(a0,a1,a2,a3, smb + SMQ + off);
            }
            uint32_t bq[14][2];
            #pragma unroll
            for (int p = 0; p < 7; p++) {
                const int row = p*16 + bRow;
                const uint32_t off = row*128 + (((cch + bK) ^ (row & 7)) << 4);
                LDSM_X4(bq[2*p][0], bq[2*p][1], bq[2*p+1][0], bq[2*p+1][1],
                        smb + SMK + off);
            }
            #pragma unroll
            for (int nt = 0; nt < 14; nt++)
                mma_bf16(sacc[nt][0], sacc[nt][1], sacc[nt][2], sacc[nt][3],
                         a0,a1,a2,a3, bq[nt][0], bq[nt][1]);
        }

        // ---- softmax (reference quirks) ----
        const int r0 = mt*16 + g, r1 = r0 + 8;
        const int rq0 = rgn[r0], rq1 = rgn[r1];
        #pragma unroll
        for (int nt = 0; nt < 14; nt++) {
            const int j0 = nt*8 + t4*2;
            const bool jc = j0 < WTOK;
            float2 e0 = make_float2(0.f,0.f), e1 = make_float2(0.f,0.f);
            if (jc)              e0 = *(const float2*)(eb + r0*WTOK + j0);
            if (jc && r1 < WTOK) e1 = *(const float2*)(eb + r1*WTOK + j0);
            const int rj0 = rgn[j0], rj1 = rgn[j0+1];
            float av;
            av = (rj0==rq0) ? sacc[nt][0]*e0.x : 0.f;
            sacc[nt][0] = jc ? ((av==0.f) ? 10000.0f : -av) : -3.0e38f;
            av = (rj1==rq0) ? sacc[nt][1]*e0.y : 0.f;
            sacc[nt][1] = jc ? ((av==0.f) ? 10000.0f : -av) : -3.0e38f;
            av = (rj0==rq1) ? sacc[nt][2]*e1.x : 0.f;
            sacc[nt][2] = jc ? ((av==0.f) ? 10000.0f : -av) : -3.0e38f;
            av = (rj1==rq1) ? sacc[nt][3]*e1.y : 0.f;
            sacc[nt][3] = jc ? ((av==0.f) ? 10000.0f : -av) : -3.0e38f;
        }
        float m0 = -3.0e38f, m1 = -3.0e38f;
        #pragma unroll
        for (int nt = 0; nt < 14; nt++) {
            m0 = fmaxf(m0, fmaxf(sacc[nt][0], sacc[nt][1]));
            m1 = fmaxf(m1, fmaxf(sacc[nt][2], sacc[nt][3]));
        }
        #pragma unroll
        for (int ofs = 1; ofs <= 2; ofs <<= 1) {
            m0 = fmaxf(m0, __shfl_xor_sync(0xffffffffu, m0, ofs));
            m1 = fmaxf(m1, __shfl_xor_sync(0xffffffffu, m1, ofs));
        }
        float s0 = 0.f, s1 = 0.f;
        #pragma unroll
        for (int nt = 0; nt < 14; nt++) {
            sacc[nt][0] = expf(sacc[nt][0] - m0); s0 += sacc[nt][0];
            sacc[nt][1] = expf(sacc[nt][1] - m0); s0 += sacc[nt][1];
            sacc[nt][2] = expf(sacc[nt][2] - m1); s1 += sacc[nt][2];
            sacc[nt][3] = expf(sacc[nt][3] - m1); s1 += sacc[nt][3];
        }
        #pragma unroll
        for (int ofs = 1; ofs <= 2; ofs <<= 1) {
            s0 += __shfl_xor_sync(0xffffffffu, s0, ofs);
            s1 += __shfl_xor_sync(0xffffffffu, s1, ofs);
        }
        const float i0 = 1.0f / s0, i1 = 1.0f / s1;

        // store P (bf16) -- pad cols exactly 0 via exp(-3e38 - m) = 0
        #pragma unroll
        for (int nt = 0; nt < 14; nt++) {
            const uint32_t chi = (uint32_t)(nt >> 3) << 7;
            const uint32_t a0off = r0*256 + chi + ((((uint32_t)nt & 7) ^ (r0 & 7)) << 4) + t4*4;
            const uint32_t a1off = r1*256 + chi + ((((uint32_t)nt & 7) ^ (r1 & 7)) << 4) + t4*4;
            *(uint32_t*)(smraw + SMP + a0off) = pk(sacc[nt][0]*i0, sacc[nt][1]*i0);
            *(uint32_t*)(smraw + SMP + a1off) = pk(sacc[nt][2]*i1, sacc[nt][3]*i1);
        }
        __syncwarp();

        // ---- O = P @ V ----
        float oacc[8][4];
        #pragma unroll
        for (int nt = 0; nt < 8; nt++)
            #pragma unroll
            for (int q = 0; q < 4; q++) oacc[nt][q] = 0.0f;

        #pragma unroll
        for (int sp = 0; sp < 7; sp++) {
            uint32_t a0,a1,a2,a3;
            {
                const int row = mt*16 + aRow;
                const int c = 2*sp + aK;
                const uint32_t off = row*256 + ((uint32_t)(c >> 3) << 7)
                                   + ((((uint32_t)c & 7) ^ (row & 7)) << 4);
                LDSM_X4(a0,a1,a2,a3, smb + SMP + off);
            }
            uint32_t bv[8][2];
            #pragma unroll
            for (int ntp = 0; ntp < 4; ntp++) {
                const int vrow = sp*16 + (lane & 7) + 8*((lane >> 3) & 1);
                const int ch = ntp*2 + ((lane >> 4) & 1);
                const uint32_t off = vrow*128 + (((uint32_t)ch ^ (vrow & 7)) << 4);
                LDSM_X4_T(bv[2*ntp][0], bv[2*ntp][1], bv[2*ntp+1][0], bv[2*ntp+1][1],
                          smb + SMV + off);
            }
            #pragma unroll
            for (int nt = 0; nt < 8; nt++)
                mma_bf16(oacc[nt][0], oacc[nt][1], oacc[nt][2], oacc[nt][3],
                         a0,a1,a2,a3, bv[nt][0], bv[nt][1]);
        }

        // ---- write O (bf16) ----
        bf16* ob = o + ((size_t)n * WTOK) * 256 + h*64;
        #pragma unroll
        for (int nt = 0; nt < 8; nt++) {
            const int col = nt*8 + t4*2;
            *(uint32_t*)(ob + (size_t)r0*256 + col) = pk(oacc[nt][0], oacc[nt][1]);
            if (r1 < WTOK)
                *(uint32_t*)(ob + (size_t)r1*256 + col) = pk(oacc[nt][2], oacc[nt][3]);
        }
    }
}

// ---------------- launch ------------------------------------------------------
extern "C" void kernel_launch(void* const* d_in, const int* in_sizes, int n_in,
                              void* d_out, int out_size)
{
    const float* x      = (const float*)d_in[0];
    const float* eb     = (const float*)d_in[1];
    const float* w_qkv  = (const float*)d_in[2];
    const float* b_qkv  = (const float*)d_in[3];
    const float* w_proj = (const float*)d_in[4];
    const float* b_proj = (const float*)d_in[5];
    const float* g1     = (const float*)d_in[6];
    const float* be1    = (const float*)d_in[7];
    const float* g2     = (const float*)d_in[8];
    const float* be2    = (const float*)d_in[9];
    const float* w_fc1  = (const float*)d_in[10];
    const float* b_fc1  = (const float*)d_in[11];
    const float* w_fc2  = (const float*)d_in[12];
    const float* b_fc2  = (const float*)d_in[13];
    float* out = (float*)d_out;

    float *P, *Y;
    bf16 *QKVh, *XNh, *Oh, *H1h, *Wq, *Wp, *W1, *W2;
    cudaGetSymbolAddress((void**)&QKVh, g_QKVh);
    cudaGetSymbolAddress((void**)&P,   g_P);
    cudaGetSymbolAddress((void**)&Y,   g_Y);
    cudaGetSymbolAddress((void**)&XNh, g_XNh);
    cudaGetSymbolAddress((void**)&Oh,  g_Oh);
    cudaGetSymbolAddress((void**)&H1h, g_H1h);
    cudaGetSymbolAddress((void**)&Wq,  g_Wq);
    cudaGetSymbolAddress((void**)&Wp,  g_Wp);
    cudaGetSymbolAddress((void**)&W1,  g_W1);
    cudaGetSymbolAddress((void**)&W2,  g_W2);

    cudaFuncSetAttribute(attn_kernel,
                         cudaFuncAttributeMaxDynamicSharedMemorySize, ATTN_SMEM);
    cudaFuncSetAttribute(hgemm<0,256>,  cudaFuncAttributeMaxDynamicSharedMemorySize, GSMEM);
    cudaFuncSetAttribute(hgemm<1,256>,  cudaFuncAttributeMaxDynamicSharedMemorySize, GSMEM);
    cudaFuncSetAttribute(hgemm<2,256>,  cudaFuncAttributeMaxDynamicSharedMemorySize, GSMEM);
    cudaFuncSetAttribute(hgemm<3,1024>, cudaFuncAttributeMaxDynamicSharedMemorySize, GSMEM);

    // 0) weights fp32 -> bf16 (single merged launch)
    f2bf_all<<<(WQ_N + WP_N + W1_N + W2_N) / 4 / 256, 256>>>(w_qkv, w_proj, w_fc1, w_fc2);

    // 1) shift + window + LN1 (bf16 out)
    ln1_kernel<<<NTOK / 8, 256>>>(x, g1, be1);
    // 2) QKV GEMM -> bf16 (q pre-scaled by 0.125 in epilogue)
    hgemm<0,256><<<dim3(6, NTOK/128), 256, GSMEM>>>(XNh, Wq, b_qkv, nullptr, QKVh, 768);
    // 3) attention (tensor cores)
    attn_kernel<<<dim3(NWIN, 4), 128, ATTN_SMEM>>>(QKVh, eb, Oh);
    // 4) proj GEMM + W-roll(+2)
    hgemm<1,256><<<dim3(2, NTOK/128), 256, GSMEM>>>(Oh, Wp, b_proj, nullptr, P, 256);
    // 5) residual + LN2
    res_ln2_kernel<<<NTOK / 8, 256>>>(x, g2, be2);
    // 6) FC1 + GELU
    hgemm<2,256><<<dim3(8, NTOK/128), 256, GSMEM>>>(XNh, W1, b_fc1, nullptr, H1h, 1024);
    // 7) FC2 + residual -> output
    hgemm<3,1024><<<dim3(2, NTOK/128), 256, GSMEM>>>(H1h, W2, b_fc2, Y, out, 256);
}

// round 12
// speedup vs baseline: 6.2679x; 1.0231x over previous
#include <cuda_runtime.h>
#include <cuda_bf16.h>
#include <math.h>
#include <stdint.h>

typedef __nv_bfloat16 bf16;

// Problem constants
#define NTOK   110592          // 1024 windows * 108 tokens
#define NWIN   1024
#define WTOK   108

// ---------------- scratch (static device globals; no allocation) -------------
__device__ bf16  g_QKVh[ (size_t)NTOK * 768 ];  // qkv (bf16, q pre-scaled)
__device__ float g_Y  [ (size_t)NTOK * 256 ];   // x + attn branch (residual base)
__device__ bf16  g_XNh[ (size_t)NTOK * 256 ];   // LN out (bf16, GEMM A input)
__device__ bf16  g_Oh [ (size_t)NTOK * 256 ];   // attention out (bf16)
__device__ bf16  g_H1h[ (size_t)NTOK * 1024 ];  // FC1+GELU out (bf16)
__device__ bf16  g_Wq [ 768 * 256 ];
__device__ bf16  g_Wp [ 256 * 256 ];
__device__ bf16  g_W1 [ 1024 * 256 ];
__device__ bf16  g_W2 [ 256 * 1024 ];

// ---------------- helpers ----------------------------------------------------
__device__ __forceinline__ float warp_sum(float v){
    #pragma unroll
    for (int o = 16; o; o >>= 1) v += __shfl_xor_sync(0xffffffffu, v, o);
    return v;
}
__device__ __forceinline__ uint32_t smem_u32(const void* p){
    uint32_t a;
    asm("{ .reg .u64 t; cvta.to.shared.u64 t, %1; cvt.u32.u64 %0, t; }"
        : "=r"(a) : "l"(p));
    return a;
}
__device__ __forceinline__ uint32_t pk(float a, float b){
    __nv_bfloat162 t = __floats2bfloat162_rn(a, b);
    return *(uint32_t*)&t;
}

#define LDSM_X4(r0,r1,r2,r3,addr) \
    asm volatile("ldmatrix.sync.aligned.m8n8.x4.shared.b16 {%0,%1,%2,%3}, [%4];" \
        : "=r"(r0), "=r"(r1), "=r"(r2), "=r"(r3) : "r"(addr))
#define LDSM_X4_T(r0,r1,r2,r3,addr) \
    asm volatile("ldmatrix.sync.aligned.m8n8.x4.trans.shared.b16 {%0,%1,%2,%3}, [%4];" \
        : "=r"(r0), "=r"(r1), "=r"(r2), "=r"(r3) : "r"(addr))

__device__ __forceinline__ void mma_bf16(float& c0, float& c1, float& c2, float& c3,
                                         uint32_t a0, uint32_t a1, uint32_t a2, uint32_t a3,
                                         uint32_t b0, uint32_t b1)
{
    asm volatile(
        "mma.sync.aligned.m16n8k16.row.col.f32.bf16.bf16.f32 "
        "{%0,%1,%2,%3}, {%4,%5,%6,%7}, {%8,%9}, {%0,%1,%2,%3};"
        : "+f"(c0), "+f"(c1), "+f"(c2), "+f"(c3)
        : "r"(a0), "r"(a1), "r"(a2), "r"(a3), "r"(b0), "r"(b1));
}

// ---------------- merged weight fp32 -> bf16 convert --------------------------
#define WQ_N (768*256)
#define WP_N (256*256)
#define W1_N (1024*256)
#define W2_N (256*1024)
__global__ void f2bf_all(const float* __restrict__ wq, const float* __restrict__ wp,
                         const float* __restrict__ w1, const float* __restrict__ w2)
{
    int i = (blockIdx.x * 256 + threadIdx.x) * 4;
    const float* s; bf16* d;
    if (i < WQ_N)                       { s = wq + i;  d = g_Wq + i; }
    else if ((i -= WQ_N) < WP_N)        { s = wp + i;  d = g_Wp + i; }
    else if ((i -= WP_N) < W1_N)        { s = w1 + i;  d = g_W1 + i; }
    else if ((i -= W1_N) < W2_N)        { s = w2 + i;  d = g_W2 + i; }
    else return;
    float4 v = *(const float4*)s;
    __nv_bfloat162* dp = (__nv_bfloat162*)d;
    dp[0] = __floats2bfloat162_rn(v.x, v.y);
    dp[1] = __floats2bfloat162_rn(v.z, v.w);
}

// ---------------- LN1 with shift + window gather (bf16 out) -------------------
__global__ void ln1_kernel(const float* __restrict__ x,
                           const float* __restrict__ g,
                           const float* __restrict__ be)
{
    const int warp = threadIdx.x >> 5, lane = threadIdx.x & 31;
    const int t = blockIdx.x * 8 + warp;
    const int n = t / WTOK, w = t - n * WTOK;
    const int b = n >> 5, f = n & 31;
    const int wf = w / 27;
    const int gf = f * 4 + wf;
    const int fr = (gf + 2) & 127;
    const int kp = w - wf * 27;
    const float* src = x + (size_t)((b * 128 + fr) * 27 + kp) * 256;

    float4 v0 = ((const float4*)src)[lane];
    float4 v1 = ((const float4*)src)[lane + 32];
    float s = v0.x+v0.y+v0.z+v0.w + v1.x+v1.y+v1.z+v1.w;
    float q = v0.x*v0.x+v0.y*v0.y+v0.z*v0.z+v0.w*v0.w
            + v1.x*v1.x+v1.y*v1.y+v1.z*v1.z+v1.w*v1.w;
    s = warp_sum(s); q = warp_sum(q);
    const float mean = s * (1.0f/256.0f);
    const float var  = q * (1.0f/256.0f) - mean*mean;
    const float rstd = rsqrtf(var + 1e-5f);

    __nv_bfloat162* dst = (__nv_bfloat162*)(g_XNh + (size_t)t * 256);
    const int c0 = lane*4, c1 = 128 + lane*4;
    dst[lane*2]        = __floats2bfloat162_rn((v0.x-mean)*rstd*g[c0+0] + be[c0+0],
                                               (v0.y-mean)*rstd*g[c0+1] + be[c0+1]);
    dst[lane*2+1]      = __floats2bfloat162_rn((v0.z-mean)*rstd*g[c0+2] + be[c0+2],
                                               (v0.w-mean)*rstd*g[c0+3] + be[c0+3]);
    dst[64 + lane*2]   = __floats2bfloat162_rn((v1.x-mean)*rstd*g[c1+0] + be[c1+0],
                                               (v1.y-mean)*rstd*g[c1+1] + be[c1+1]);
    dst[64 + lane*2+1] = __floats2bfloat162_rn((v1.z-mean)*rstd*g[c1+2] + be[c1+2],
                                               (v1.w-mean)*rstd*g[c1+3] + be[c1+3]);
}

// ---------------- bf16 mma.sync NT GEMM, 3-stage cp.async pipeline -----------
// EPI: 0 = +bias, *0.125 for cols<256, bf16 out (QKV)
//      2 = +bias, exact GELU, bf16 out (FC1)
//      3 = +bias + Yres residual, fp32 out (FC2 -> final)
#define BUFB  16384
#define STGB  (2*BUFB)
#define GSMEM (3*STGB + 128)

template<int EPI>
__device__ __forceinline__ void epi_store(void* __restrict__ C,
                                          const float* __restrict__ Yres,
                                          int N, int m, int col,
                                          float v0, float v1)
{
    if (EPI == 0) {
        const float sc = (col < 256) ? 0.125f : 1.0f;
        *(__nv_bfloat162*)((bf16*)C + (size_t)m*N + col) =
            __floats2bfloat162_rn(v0*sc, v1*sc);
        return;
    }
    if (EPI == 2) {
        v0 = 0.5f*v0*(1.0f + erff(v0*0.70710678118654752f));
        v1 = 0.5f*v1*(1.0f + erff(v1*0.70710678118654752f));
        *(__nv_bfloat162*)((bf16*)C + (size_t)m*N + col) = __floats2bfloat162_rn(v0, v1);
        return;
    }
    if (EPI == 3) {
        const float2 yv = *(const float2*)&Yres[(size_t)m*N + col];
        v0 += yv.x; v1 += yv.y;
    }
    *(float2*)((float*)C + (size_t)m*N + col) = make_float2(v0, v1);
}

template<int EPI, int KD>
__global__ void __launch_bounds__(256)
hgemm(const bf16* __restrict__ A, const bf16* __restrict__ Bw,
      const float* __restrict__ bias, const float* __restrict__ Yres,
      void* __restrict__ C, int N)
{
    extern __shared__ char smraw[];
    char* sm = (char*)(((uintptr_t)smraw + 127) & ~(uintptr_t)127);

    const int tid = threadIdx.x;
    const int wid = tid >> 5, lane = tid & 31;
    const int warpM = wid >> 2, warpN = wid & 3;   // 2 x 4
    const int bn = blockIdx.x, bm = blockIdx.y;

    const bf16* Ab = A  + (size_t)bm * 128 * KD;
    const bf16* Bb = Bw + (size_t)bn * 128 * KD;

    const uint32_t smb = smem_u32(sm);

    const int aRow = (lane & 7) | (((lane >> 3) & 1) << 3);
    const int aK   = (lane >> 4) & 1;
    const int bRow = (lane & 7) | (((lane >> 4) & 1) << 3);
    const int bK   = (lane >> 3) & 1;

    float acc[4][4][4];
    #pragma unroll
    for (int i = 0; i < 4; i++)
        #pragma unroll
        for (int j = 0; j < 4; j++)
            #pragma unroll
            for (int q = 0; q < 4; q++) acc[i][j][q] = 0.0f;

    auto load_chunk = [&](int buf, int kbase){
        const uint32_t sa = smb + buf * STGB;
        const uint32_t sb = sa + BUFB;
        #pragma unroll
        for (int i = 0; i < 4; i++) {
            const int idx = tid + 256*i;
            const int row = idx >> 3, q = idx & 7;
            const uint32_t off = row*128 + ((q ^ (row & 7)) << 4);
            const size_t goff = (size_t)row*KD + kbase + q*8;
            asm volatile("cp.async.cg.shared.global [%0], [%1], 16;"
                         :: "r"(sa + off), "l"(Ab + goff));
            asm volatile("cp.async.cg.shared.global [%0], [%1], 16;"
                         :: "r"(sb + off), "l"(Bb + goff));
        }
        asm volatile("cp.async.commit_group;" ::: "memory");
    };

    constexpr int NC = KD / 64;
    load_chunk(0, 0);
    if (NC > 1) load_chunk(1, 64);

    for (int c = 0; c < NC; c++) {
        if (c + 1 < NC) asm volatile("cp.async.wait_group 1;" ::: "memory");
        else            asm volatile("cp.async.wait_group 0;" ::: "memory");
        __syncthreads();
        if (c + 2 < NC) load_chunk((c + 2) % 3, (c + 2) * 64);

        const uint32_t saA = smb + (c % 3) * STGB;
        const uint32_t saB = saA + BUFB;

        #pragma unroll
        for (int s = 0; s < 4; s++) {
            const int cch = s * 2;
            uint32_t a[4][4];
            #pragma unroll
            for (int mt = 0; mt < 4; mt++) {
                const int row = warpM*64 + mt*16 + aRow;
                const uint32_t off = row*128 + (((cch + aK) ^ (row & 7)) << 4);
                LDSM_X4(a[mt][0], a[mt][1], a[mt][2], a[mt][3], saA + off);
            }
            uint32_t b[4][2];
            #pragma unroll
            for (int p = 0; p < 2; p++) {
                const int row = warpN*32 + p*16 + bRow;
                const uint32_t off = row*128 + (((cch + bK) ^ (row & 7)) << 4);
                LDSM_X4(b[2*p][0], b[2*p][1], b[2*p+1][0], b[2*p+1][1], saB + off);
            }
            #pragma unroll
            for (int mt = 0; mt < 4; mt++)
                #pragma unroll
                for (int nt = 0; nt < 4; nt++)
                    mma_bf16(acc[mt][nt][0], acc[mt][nt][1],
                             acc[mt][nt][2], acc[mt][nt][3],
                             a[mt][0], a[mt][1], a[mt][2], a[mt][3],
                             b[nt][0], b[nt][1]);
        }
    }

    const int g = lane >> 2, t = lane & 3;
    #pragma unroll
    for (int mt = 0; mt < 4; mt++) {
        const int r0 = bm*128 + warpM*64 + mt*16 + g;
        #pragma unroll
        for (int nt = 0; nt < 4; nt++) {
            const int col = bn*128 + warpN*32 + nt*8 + t*2;
            const float2 bv = *(const float2*)&bias[col];
            epi_store<EPI>(C, Yres, N, r0,     col,
                           acc[mt][nt][0] + bv.x, acc[mt][nt][1] + bv.y);
            epi_store<EPI>(C, Yres, N, r0 + 8, col,
                           acc[mt][nt][2] + bv.x, acc[mt][nt][3] + bv.y);
        }
    }
}

// ---------------- fused proj GEMM + roll + residual + LN2 ---------------------
// CTA 128(M) x 256(N=full), 512 threads, 16 warps (2x8) of 64x32 warp tiles.
// K = 256. Epilogue: v+bias -> roll(+2) dest -> y = x[mout]+v -> per-row LN2.
#define PSTG   49152                  // (128+256) rows * 128B per stage
#define PSUMS  (3*PSTG)               // float sums[128][8][2] = 8KB
#define PSMEM  (PSUMS + 8192 + 128)

__global__ void __launch_bounds__(512)
proj_ln2(const bf16* __restrict__ A, const bf16* __restrict__ Bw,
         const float* __restrict__ bias, const float* __restrict__ x,
         float* __restrict__ Y, bf16* __restrict__ XNh,
         const float* __restrict__ g2, const float* __restrict__ be2)
{
    extern __shared__ char smraw[];
    char* sm = (char*)(((uintptr_t)smraw + 127) & ~(uintptr_t)127);
    const uint32_t smb = smem_u32(sm);
    float* sums = (float*)(sm + PSUMS);

    const int tid = threadIdx.x;
    const int wid = tid >> 5, lane = tid & 31;
    const int warpM = wid >> 3, warpN = wid & 7;   // 2 x 8
    const int bm = blockIdx.x;
    constexpr int KD = 256;

    const bf16* Ab = A + (size_t)bm * 128 * KD;

    const int aRow = (lane & 7) | (((lane >> 3) & 1) << 3);
    const int aK   = (lane >> 4) & 1;
    const int bRow = (lane & 7) | (((lane >> 4) & 1) << 3);
    const int bK   = (lane >> 3) & 1;

    float acc[4][4][4];
    #pragma unroll
    for (int i = 0; i < 4; i++)
        #pragma unroll
        for (int j = 0; j < 4; j++)
            #pragma unroll
            for (int q = 0; q < 4; q++) acc[i][j][q] = 0.0f;

    auto load_chunk = [&](int buf, int kbase){
        const uint32_t sa = smb + buf * PSTG;
        #pragma unroll
        for (int i = 0; i < 6; i++) {          // 384 rows * 8 chunks / 512 thr
            const int idx = tid + 512*i;
            const int row = idx >> 3, q = idx & 7;
            if (row < 128) {
                const uint32_t off = row*128 + ((q ^ (row & 7)) << 4);
                asm volatile("cp.async.cg.shared.global [%0], [%1], 16;"
                             :: "r"(sa + off), "l"(Ab + (size_t)row*KD + kbase + q*8));
            } else {
                const int br = row - 128;
                const uint32_t off = 16384 + br*128 + ((q ^ (br & 7)) << 4);
                asm volatile("cp.async.cg.shared.global [%0], [%1], 16;"
                             :: "r"(sa + off), "l"(Bw + (size_t)br*KD + kbase + q*8));
            }
        }
        asm volatile("cp.async.commit_group;" ::: "memory");
    };

    load_chunk(0, 0);
    load_chunk(1, 64);

    for (int c = 0; c < 4; c++) {
        if (c < 3) asm volatile("cp.async.wait_group 1;" ::: "memory");
        else       asm volatile("cp.async.wait_group 0;" ::: "memory");
        __syncthreads();
        if (c + 2 < 4) load_chunk((c + 2) % 3, (c + 2) * 64);

        const uint32_t saA = smb + (c % 3) * PSTG;
        const uint32_t saB = saA + 16384;

        #pragma unroll
        for (int s = 0; s < 4; s++) {
            const int cch = s * 2;
            uint32_t a[4][4];
            #pragma unroll
            for (int mt = 0; mt < 4; mt++) {
                const int row = warpM*64 + mt*16 + aRow;
                const uint32_t off = row*128 + (((cch + aK) ^ (row & 7)) << 4);
                LDSM_X4(a[mt][0], a[mt][1], a[mt][2], a[mt][3], saA + off);
            }
            uint32_t b[4][2];
            #pragma unroll
            for (int p = 0; p < 2; p++) {
                const int row = warpN*32 + p*16 + bRow;
                const uint32_t off = row*128 + (((cch + bK) ^ (row & 7)) << 4);
                LDSM_X4(b[2*p][0], b[2*p][1], b[2*p+1][0], b[2*p+1][1], saB + off);
            }
            #pragma unroll
            for (int mt = 0; mt < 4; mt++)
                #pragma unroll
                for (int nt = 0; nt < 4; nt++)
                    mma_bf16(acc[mt][nt][0], acc[mt][nt][1],
                             acc[mt][nt][2], acc[mt][nt][3],
                             a[mt][0], a[mt][1], a[mt][2], a[mt][3],
                             b[nt][0], b[nt][1]);
        }
    }

    // ---- epilogue: bias + roll + residual, partial row sums ----
    const int g = lane >> 2, t4 = lane & 3;
    int mo[4][2];
    #pragma unroll
    for (int mt = 0; mt < 4; mt++) {
        const int lr0 = warpM*64 + mt*16 + g;
        #pragma unroll
        for (int half = 0; half < 2; half++) {
            const int m = bm*128 + lr0 + half*8;
            const int nw = m / WTOK, w = m - nw * WTOK;
            int w2 = w + 2; if (w2 >= WTOK) w2 -= WTOK;
            mo[mt][half] = nw * WTOK + w2;
        }
        float s0 = 0.f, q0 = 0.f, s1 = 0.f, q1 = 0.f;
        #pragma unroll
        for (int nt = 0; nt < 4; nt++) {
            const int col = warpN*32 + nt*8 + t4*2;
            const float2 bv = *(const float2*)&bias[col];
            const float2 x0 = *(const float2*)&x[(size_t)mo[mt][0]*256 + col];
            const float2 x1 = *(const float2*)&x[(size_t)mo[mt][1]*256 + col];
            float y00 = acc[mt][nt][0] + bv.x + x0.x;
            float y01 = acc[mt][nt][1] + bv.y + x0.y;
            float y10 = acc[mt][nt][2] + bv.x + x1.x;
            float y11 = acc[mt][nt][3] + bv.y + x1.y;
            acc[mt][nt][0] = y00; acc[mt][nt][1] = y01;
            acc[mt][nt][2] = y10; acc[mt][nt][3] = y11;
            s0 += y00 + y01; q0 += y00*y00 + y01*y01;
            s1 += y10 + y11; q1 += y10*y10 + y11*y11;
        }
        #pragma unroll
        for (int ofs = 1; ofs <= 2; ofs <<= 1) {
            s0 += __shfl_xor_sync(0xffffffffu, s0, ofs);
            q0 += __shfl_xor_sync(0xffffffffu, q0, ofs);
            s1 += __shfl_xor_sync(0xffffffffu, s1, ofs);
            q1 += __shfl_xor_sync(0xffffffffu, q1, ofs);
        }
        if (t4 == 0) {
            sums[(lr0*8     + warpN)*2    ] = s0;
            sums[(lr0*8     + warpN)*2 + 1] = q0;
            sums[((lr0+8)*8 + warpN)*2    ] = s1;
            sums[((lr0+8)*8 + warpN)*2 + 1] = q1;
        }
    }
    __syncthreads();

    // ---- finish LN per row, write Y + XNh ----
    #pragma unroll
    for (int mt = 0; mt < 4; mt++) {
        const int lr0 = warpM*64 + mt*16 + g;
        float s0 = 0.f, q0 = 0.f, s1 = 0.f, q1 = 0.f;
        #pragma unroll
        for (int wn = 0; wn < 8; wn++) {
            s0 += sums[(lr0*8     + wn)*2    ];
            q0 += sums[(lr0*8     + wn)*2 + 1];
            s1 += sums[((lr0+8)*8 + wn)*2    ];
            q1 += sums[((lr0+8)*8 + wn)*2 + 1];
        }
        const float mean0 = s0 * (1.0f/256.0f);
        const float var0  = q0 * (1.0f/256.0f) - mean0*mean0;
        const float rs0   = rsqrtf(var0 + 1e-5f);
        const float mean1 = s1 * (1.0f/256.0f);
        const float var1  = q1 * (1.0f/256.0f) - mean1*mean1;
        const float rs1   = rsqrtf(var1 + 1e-5f);
        #pragma unroll
        for (int nt = 0; nt < 4; nt++) {
            const int col = warpN*32 + nt*8 + t4*2;
            const float2 gv = *(const float2*)&g2[col];
            const float2 bv = *(const float2*)&be2[col];
            const float y00 = acc[mt][nt][0], y01 = acc[mt][nt][1];
            const float y10 = acc[mt][nt][2], y11 = acc[mt][nt][3];
            *(float2*)&Y[(size_t)mo[mt][0]*256 + col] = make_float2(y00, y01);
            *(float2*)&Y[(size_t)mo[mt][1]*256 + col] = make_float2(y10, y11);
            *(uint32_t*)(XNh + (size_t)mo[mt][0]*256 + col) =
                pk((y00-mean0)*rs0*gv.x + bv.x, (y01-mean0)*rs0*gv.y + bv.y);
            *(uint32_t*)(XNh + (size_t)mo[mt][1]*256 + col) =
                pk((y10-mean1)*rs1*gv.x + bv.x, (y11-mean1)*rs1*gv.y + bv.y);
        }
    }
}

// ---------------- tensor-core windowed attention (256 thr, 8 warps) -----------
// Block = (window, head). Padded W: 112 = 7 m16 tiles; warp w handles tile w (<7).
#define SMQ 0
#define SMK 14336
#define SMV 28672
#define SMP 43008
#define SMRGN 71680
#define ATTN_SMEM (71680 + 512)

__global__ void __launch_bounds__(256)
attn_kernel(const bf16* __restrict__ qkv,
            const float* __restrict__ eb,
            bf16* __restrict__ o)
{
    extern __shared__ char smraw[];
    const uint32_t smb = smem_u32(smraw);
    int* rgn = (int*)(smraw + SMRGN);

    const int n = blockIdx.x, h = blockIdx.y;
    const int tid = threadIdx.x, warp = tid >> 5, lane = tid & 31;
    const int f = n & 31;
    const size_t base = (size_t)n * WTOK * 768;

    // load Q(prescaled)/K/V bf16 -> swizzled smem; zero pad rows 108..111
    for (int idx = tid; idx < 112*8; idx += 256) {
        const int row = idx >> 3, q = idx & 7;
        const uint32_t off = row*128 + ((q ^ (row & 7)) << 4);
        uint4 uq = {0,0,0,0}, uk = {0,0,0,0}, uv = {0,0,0,0};
        if (row < WTOK) {
            const bf16* rp = qkv + base + (size_t)row * 768 + h*64 + q*8;
            uq = *(const uint4*)(rp);
            uk = *(const uint4*)(rp + 256);
            uv = *(const uint4*)(rp + 512);
        }
        *(uint4*)(smraw + SMQ + off) = uq;
        *(uint4*)(smraw + SMK + off) = uk;
        *(uint4*)(smraw + SMV + off) = uv;
    }
    for (int w = tid; w < 112; w += 256) {
        if (w < WTOK) {
            const int gf = f * 4 + w / 27;
            rgn[w] = (gf >= 126) ? 2 : ((gf >= 124) ? 1 : 0);
        } else rgn[w] = -1;
    }
    __syncthreads();

    const int aRow = (lane & 7) | (((lane >> 3) & 1) << 3);
    const int aK   = (lane >> 4) & 1;
    const int bRow = (lane & 7) | (((lane >> 4) & 1) << 3);
    const int bK   = (lane >> 3) & 1;
    const int g = lane >> 2, t4 = lane & 3;

    const int mt = warp;
    if (mt < 7) {
        // ---- S = Q @ K^T ----
        float sacc[14][4];
        #pragma unroll
        for (int nt = 0; nt < 14; nt++)
            #pragma unroll
            for (int q = 0; q < 4; q++) sacc[nt][q] = 0.0f;

        #pragma unroll
        for (int s = 0; s < 4; s++) {
            const int cch = 2*s;
            uint32_t a0,a1,a2,a3;
            {
                const int row = mt*16 + aRow;
                const uint32_t off = row*128 + (((cch + aK) ^ (row & 7)) << 4);
                LDSM_X4(a0,a1,a2,a3, smb + SMQ + off);
            }
            uint32_t bq[14][2];
            #pragma unroll
            for (int p = 0; p < 7; p++) {
                const int row = p*16 + bRow;
                const uint32_t off = row*128 + (((cch + bK) ^ (row & 7)) << 4);
                LDSM_X4(bq[2*p][0], bq[2*p][1], bq[2*p+1][0], bq[2*p+1][1],
                        smb + SMK + off);
            }
            #pragma unroll
            for (int nt = 0; nt < 14; nt++)
                mma_bf16(sacc[nt][0], sacc[nt][1], sacc[nt][2], sacc[nt][3],
                         a0,a1,a2,a3, bq[nt][0], bq[nt][1]);
        }

        // ---- softmax (reference quirks) ----
        const int r0 = mt*16 + g, r1 = r0 + 8;
        const int rq0 = rgn[r0], rq1 = rgn[r1];
        #pragma unroll
        for (int nt = 0; nt < 14; nt++) {
            const int j0 = nt*8 + t4*2;
            const bool jc = j0 < WTOK;
            float2 e0 = make_float2(0.f,0.f), e1 = make_float2(0.f,0.f);
            if (jc)              e0 = *(const float2*)(eb + r0*WTOK + j0);
            if (jc && r1 < WTOK) e1 = *(const float2*)(eb + r1*WTOK + j0);
            const int rj0 = rgn[j0], rj1 = rgn[j0+1];
            float av;
            av = (rj0==rq0) ? sacc[nt][0]*e0.x : 0.f;
            sacc[nt][0] = jc ? ((av==0.f) ? 10000.0f : -av) : -3.0e38f;
            av = (rj1==rq0) ? sacc[nt][1]*e0.y : 0.f;
            sacc[nt][1] = jc ? ((av==0.f) ? 10000.0f : -av) : -3.0e38f;
            av = (rj0==rq1) ? sacc[nt][2]*e1.x : 0.f;
            sacc[nt][2] = jc ? ((av==0.f) ? 10000.0f : -av) : -3.0e38f;
            av = (rj1==rq1) ? sacc[nt][3]*e1.y : 0.f;
            sacc[nt][3] = jc ? ((av==0.f) ? 10000.0f : -av) : -3.0e38f;
        }
        float m0 = -3.0e38f, m1 = -3.0e38f;
        #pragma unroll
        for (int nt = 0; nt < 14; nt++) {
            m0 = fmaxf(m0, fmaxf(sacc[nt][0], sacc[nt][1]));
            m1 = fmaxf(m1, fmaxf(sacc[nt][2], sacc[nt][3]));
        }
        #pragma unroll
        for (int ofs = 1; ofs <= 2; ofs <<= 1) {
            m0 = fmaxf(m0, __shfl_xor_sync(0xffffffffu, m0, ofs));
            m1 = fmaxf(m1, __shfl_xor_sync(0xffffffffu, m1, ofs));
        }
        float s0 = 0.f, s1 = 0.f;
        #pragma unroll
        for (int nt = 0; nt < 14; nt++) {
            sacc[nt][0] = expf(sacc[nt][0] - m0); s0 += sacc[nt][0];
            sacc[nt][1] = expf(sacc[nt][1] - m0); s0 += sacc[nt][1];
            sacc[nt][2] = expf(sacc[nt][2] - m1); s1 += sacc[nt][2];
            sacc[nt][3] = expf(sacc[nt][3] - m1); s1 += sacc[nt][3];
        }
        #pragma unroll
        for (int ofs = 1; ofs <= 2; ofs <<= 1) {
            s0 += __shfl_xor_sync(0xffffffffu, s0, ofs);
            s1 += __shfl_xor_sync(0xffffffffu, s1, ofs);
        }
        const float i0 = 1.0f / s0, i1 = 1.0f / s1;

        // store P (bf16) -- pad cols exactly 0 via exp(-3e38 - m) = 0
        #pragma unroll
        for (int nt = 0; nt < 14; nt++) {
            const uint32_t chi = (uint32_t)(nt >> 3) << 7;
            const uint32_t a0off = r0*256 + chi + ((((uint32_t)nt & 7) ^ (r0 & 7)) << 4) + t4*4;
            const uint32_t a1off = r1*256 + chi + ((((uint32_t)nt & 7) ^ (r1 & 7)) << 4) + t4*4;
            *(uint32_t*)(smraw + SMP + a0off) = pk(sacc[nt][0]*i0, sacc[nt][1]*i0);
            *(uint32_t*)(smraw + SMP + a1off) = pk(sacc[nt][2]*i1, sacc[nt][3]*i1);
        }
        __syncwarp();

        // ---- O = P @ V ----
        float oacc[8][4];
        #pragma unroll
        for (int nt = 0; nt < 8; nt++)
            #pragma unroll
            for (int q = 0; q < 4; q++) oacc[nt][q] = 0.0f;

        #pragma unroll
        for (int sp = 0; sp < 7; sp++) {
            uint32_t a0,a1,a2,a3;
            {
                const int row = mt*16 + aRow;
                const int c = 2*sp + aK;
                const uint32_t off = row*256 + ((uint32_t)(c >> 3) << 7)
                                   + ((((uint32_t)c & 7) ^ (row & 7)) << 4);
                LDSM_X4(a0,a1,a2,a3, smb + SMP + off);
            }
            uint32_t bv[8][2];
            #pragma unroll
            for (int ntp = 0; ntp < 4; ntp++) {
                const int vrow = sp*16 + (lane & 7) + 8*((lane >> 3) & 1);
                const int ch = ntp*2 + ((lane >> 4) & 1);
                const uint32_t off = vrow*128 + (((uint32_t)ch ^ (vrow & 7)) << 4);
                LDSM_X4_T(bv[2*ntp][0], bv[2*ntp][1], bv[2*ntp+1][0], bv[2*ntp+1][1],
                          smb + SMV + off);
            }
            #pragma unroll
            for (int nt = 0; nt < 8; nt++)
                mma_bf16(oacc[nt][0], oacc[nt][1], oacc[nt][2], oacc[nt][3],
                         a0,a1,a2,a3, bv[nt][0], bv[nt][1]);
        }

        // ---- write O (bf16) ----
        bf16* ob = o + ((size_t)n * WTOK) * 256 + h*64;
        #pragma unroll
        for (int nt = 0; nt < 8; nt++) {
            const int col = nt*8 + t4*2;
            *(uint32_t*)(ob + (size_t)r0*256 + col) = pk(oacc[nt][0], oacc[nt][1]);
            if (r1 < WTOK)
                *(uint32_t*)(ob + (size_t)r1*256 + col) = pk(oacc[nt][2], oacc[nt][3]);
        }
    }
}

// ---------------- launch ------------------------------------------------------
extern "C" void kernel_launch(void* const* d_in, const int* in_sizes, int n_in,
                              void* d_out, int out_size)
{
    const float* x      = (const float*)d_in[0];
    const float* eb     = (const float*)d_in[1];
    const float* w_qkv  = (const float*)d_in[2];
    const float* b_qkv  = (const float*)d_in[3];
    const float* w_proj = (const float*)d_in[4];
    const float* b_proj = (const float*)d_in[5];
    const float* g1     = (const float*)d_in[6];
    const float* be1    = (const float*)d_in[7];
    const float* g2     = (const float*)d_in[8];
    const float* be2    = (const float*)d_in[9];
    const float* w_fc1  = (const float*)d_in[10];
    const float* b_fc1  = (const float*)d_in[11];
    const float* w_fc2  = (const float*)d_in[12];
    const float* b_fc2  = (const float*)d_in[13];
    float* out = (float*)d_out;

    float *Y;
    bf16 *QKVh, *XNh, *Oh, *H1h, *Wq, *Wp, *W1, *W2;
    cudaGetSymbolAddress((void**)&QKVh, g_QKVh);
    cudaGetSymbolAddress((void**)&Y,   g_Y);
    cudaGetSymbolAddress((void**)&XNh, g_XNh);
    cudaGetSymbolAddress((void**)&Oh,  g_Oh);
    cudaGetSymbolAddress((void**)&H1h, g_H1h);
    cudaGetSymbolAddress((void**)&Wq,  g_Wq);
    cudaGetSymbolAddress((void**)&Wp,  g_Wp);
    cudaGetSymbolAddress((void**)&W1,  g_W1);
    cudaGetSymbolAddress((void**)&W2,  g_W2);

    cudaFuncSetAttribute(attn_kernel,
                         cudaFuncAttributeMaxDynamicSharedMemorySize, ATTN_SMEM);
    cudaFuncSetAttribute(proj_ln2,
                         cudaFuncAttributeMaxDynamicSharedMemorySize, PSMEM);
    cudaFuncSetAttribute(hgemm<0,256>,  cudaFuncAttributeMaxDynamicSharedMemorySize, GSMEM);
    cudaFuncSetAttribute(hgemm<2,256>,  cudaFuncAttributeMaxDynamicSharedMemorySize, GSMEM);
    cudaFuncSetAttribute(hgemm<3,1024>, cudaFuncAttributeMaxDynamicSharedMemorySize, GSMEM);

    // 0) weights fp32 -> bf16 (single merged launch)
    f2bf_all<<<(WQ_N + WP_N + W1_N + W2_N) / 4 / 256, 256>>>(w_qkv, w_proj, w_fc1, w_fc2);

    // 1) shift + window + LN1 (bf16 out)
    ln1_kernel<<<NTOK / 8, 256>>>(x, g1, be1);
    // 2) QKV GEMM -> bf16 (q pre-scaled by 0.125 in epilogue)
    hgemm<0,256><<<dim3(6, NTOK/128), 256, GSMEM>>>(XNh, Wq, b_qkv, nullptr, QKVh, 768);
    // 3) attention (tensor cores, 8 warps)
    attn_kernel<<<dim3(NWIN, 4), 256, ATTN_SMEM>>>(QKVh, eb, Oh);
    // 4) fused proj + roll + residual + LN2 -> Y (fp32), XNh (bf16)
    proj_ln2<<<NTOK/128, 512, PSMEM>>>(Oh, Wp, b_proj, x, Y, XNh, g2, be2);
    // 5) FC1 + GELU
    hgemm<2,256><<<dim3(8, NTOK/128), 256, GSMEM>>>(XNh, W1, b_fc1, nullptr, H1h, 1024);
    // 6) FC2 + residual -> output
    hgemm<3,1024><<<dim3(2, NTOK/128), 256, GSMEM>>>(H1h, W2, b_fc2, Y, out, 256);
}

// round 14
// speedup vs baseline: 6.3820x; 1.0182x over previous
#include <cuda_runtime.h>
#include <cuda_bf16.h>
#include <math.h>
#include <stdint.h>

typedef __nv_bfloat16 bf16;

// Problem constants
#define NTOK   110592          // 1024 windows * 108 tokens
#define NWIN   1024
#define WTOK   108

// ---------------- scratch (static device globals; no allocation) -------------
__device__ bf16  g_QKVh[ (size_t)NTOK * 768 ];  // qkv (bf16, q pre-scaled)
__device__ float g_Y  [ (size_t)NTOK * 256 ];   // x + attn branch (residual base)
__device__ bf16  g_XNh[ (size_t)NTOK * 256 ];   // LN out (bf16, GEMM A input)
__device__ bf16  g_Oh [ (size_t)NTOK * 256 ];   // attention out (bf16)
__device__ bf16  g_H1h[ (size_t)NTOK * 1024 ];  // FC1+GELU out (bf16)
__device__ bf16  g_Wq [ 768 * 256 ];
__device__ bf16  g_Wp [ 256 * 256 ];
__device__ bf16  g_W1 [ 1024 * 256 ];
__device__ bf16  g_W2 [ 256 * 1024 ];

// ---------------- helpers ----------------------------------------------------
__device__ __forceinline__ float warp_sum(float v){
    #pragma unroll
    for (int o = 16; o; o >>= 1) v += __shfl_xor_sync(0xffffffffu, v, o);
    return v;
}
__device__ __forceinline__ uint32_t smem_u32(const void* p){
    uint32_t a;
    asm("{ .reg .u64 t; cvta.to.shared.u64 t, %1; cvt.u32.u64 %0, t; }"
        : "=r"(a) : "l"(p));
    return a;
}
__device__ __forceinline__ uint32_t pk(float a, float b){
    __nv_bfloat162 t = __floats2bfloat162_rn(a, b);
    return *(uint32_t*)&t;
}

#define LDSM_X4(r0,r1,r2,r3,addr) \
    asm volatile("ldmatrix.sync.aligned.m8n8.x4.shared.b16 {%0,%1,%2,%3}, [%4];" \
        : "=r"(r0), "=r"(r1), "=r"(r2), "=r"(r3) : "r"(addr))
#define LDSM_X4_T(r0,r1,r2,r3,addr) \
    asm volatile("ldmatrix.sync.aligned.m8n8.x4.trans.shared.b16 {%0,%1,%2,%3}, [%4];" \
        : "=r"(r0), "=r"(r1), "=r"(r2), "=r"(r3) : "r"(addr))

__device__ __forceinline__ void mma_bf16(float& c0, float& c1, float& c2, float& c3,
                                         uint32_t a0, uint32_t a1, uint32_t a2, uint32_t a3,
                                         uint32_t b0, uint32_t b1)
{
    asm volatile(
        "mma.sync.aligned.m16n8k16.row.col.f32.bf16.bf16.f32 "
        "{%0,%1,%2,%3}, {%4,%5,%6,%7}, {%8,%9}, {%0,%1,%2,%3};"
        : "+f"(c0), "+f"(c1), "+f"(c2), "+f"(c3)
        : "r"(a0), "r"(a1), "r"(a2), "r"(a3), "r"(b0), "r"(b1));
}

// ---------------- merged weight fp32 -> bf16 convert --------------------------
#define WQ_N (768*256)
#define WP_N (256*256)
#define W1_N (1024*256)
#define W2_N (256*1024)
__global__ void f2bf_all(const float* __restrict__ wq, const float* __restrict__ wp,
                         const float* __restrict__ w1, const float* __restrict__ w2)
{
    int i = (blockIdx.x * 256 + threadIdx.x) * 4;
    const float* s; bf16* d;
    if (i < WQ_N)                       { s = wq + i;  d = g_Wq + i; }
    else if ((i -= WQ_N) < WP_N)        { s = wp + i;  d = g_Wp + i; }
    else if ((i -= WP_N) < W1_N)        { s = w1 + i;  d = g_W1 + i; }
    else if ((i -= W1_N) < W2_N)        { s = w2 + i;  d = g_W2 + i; }
    else return;
    float4 v = *(const float4*)s;
    __nv_bfloat162* dp = (__nv_bfloat162*)d;
    dp[0] = __floats2bfloat162_rn(v.x, v.y);
    dp[1] = __floats2bfloat162_rn(v.z, v.w);
}

// ---------------- LN1 with shift + window gather (bf16 out) -------------------
__global__ void ln1_kernel(const float* __restrict__ x,
                           const float* __restrict__ g,
                           const float* __restrict__ be)
{
    const int warp = threadIdx.x >> 5, lane = threadIdx.x & 31;
    const int t = blockIdx.x * 8 + warp;
    const int n = t / WTOK, w = t - n * WTOK;
    const int b = n >> 5, f = n & 31;
    const int wf = w / 27;
    const int gf = f * 4 + wf;
    const int fr = (gf + 2) & 127;
    const int kp = w - wf * 27;
    const float* src = x + (size_t)((b * 128 + fr) * 27 + kp) * 256;

    float4 v0 = ((const float4*)src)[lane];
    float4 v1 = ((const float4*)src)[lane + 32];
    float s = v0.x+v0.y+v0.z+v0.w + v1.x+v1.y+v1.z+v1.w;
    float q = v0.x*v0.x+v0.y*v0.y+v0.z*v0.z+v0.w*v0.w
            + v1.x*v1.x+v1.y*v1.y+v1.z*v1.z+v1.w*v1.w;
    s = warp_sum(s); q = warp_sum(q);
    const float mean = s * (1.0f/256.0f);
    const float var  = q * (1.0f/256.0f) - mean*mean;
    const float rstd = rsqrtf(var + 1e-5f);

    __nv_bfloat162* dst = (__nv_bfloat162*)(g_XNh + (size_t)t * 256);
    const int c0 = lane*4, c1 = 128 + lane*4;
    dst[lane*2]        = __floats2bfloat162_rn((v0.x-mean)*rstd*g[c0+0] + be[c0+0],
                                               (v0.y-mean)*rstd*g[c0+1] + be[c0+1]);
    dst[lane*2+1]      = __floats2bfloat162_rn((v0.z-mean)*rstd*g[c0+2] + be[c0+2],
                                               (v0.w-mean)*rstd*g[c0+3] + be[c0+3]);
    dst[64 + lane*2]   = __floats2bfloat162_rn((v1.x-mean)*rstd*g[c1+0] + be[c1+0],
                                               (v1.y-mean)*rstd*g[c1+1] + be[c1+1]);
    dst[64 + lane*2+1] = __floats2bfloat162_rn((v1.z-mean)*rstd*g[c1+2] + be[c1+2],
                                               (v1.w-mean)*rstd*g[c1+3] + be[c1+3]);
}

// ---------------- bf16 mma.sync NT GEMM, 3-stage cp.async pipeline -----------
// EPI: 0 = +bias, *0.125 for cols<256, bf16 out (QKV)
//      2 = +bias, exact GELU, bf16 out (FC1)
//      3 = +bias + Yres residual, fp32 out (FC2 -> final)
#define BUFB  16384
#define STGB  (2*BUFB)
#define GSMEM (3*STGB + 128)

template<int EPI>
__device__ __forceinline__ void epi_store(void* __restrict__ C,
                                          const float* __restrict__ Yres,
                                          int N, int m, int col,
                                          float v0, float v1)
{
    if (EPI == 0) {
        const float sc = (col < 256) ? 0.125f : 1.0f;
        *(__nv_bfloat162*)((bf16*)C + (size_t)m*N + col) =
            __floats2bfloat162_rn(v0*sc, v1*sc);
        return;
    }
    if (EPI == 2) {
        v0 = 0.5f*v0*(1.0f + erff(v0*0.70710678118654752f));
        v1 = 0.5f*v1*(1.0f + erff(v1*0.70710678118654752f));
        *(__nv_bfloat162*)((bf16*)C + (size_t)m*N + col) = __floats2bfloat162_rn(v0, v1);
        return;
    }
    if (EPI == 3) {
        const float2 yv = *(const float2*)&Yres[(size_t)m*N + col];
        v0 += yv.x; v1 += yv.y;
    }
    *(float2*)((float*)C + (size_t)m*N + col) = make_float2(v0, v1);
}

template<int EPI, int KD>
__global__ void __launch_bounds__(256)
hgemm(const bf16* __restrict__ A, const bf16* __restrict__ Bw,
      const float* __restrict__ bias, const float* __restrict__ Yres,
      void* __restrict__ C, int N)
{
    extern __shared__ char smraw[];
    char* sm = (char*)(((uintptr_t)smraw + 127) & ~(uintptr_t)127);

    const int tid = threadIdx.x;
    const int wid = tid >> 5, lane = tid & 31;
    const int warpM = wid >> 2, warpN = wid & 3;   // 2 x 4
    const int bn = blockIdx.x, bm = blockIdx.y;

    const bf16* Ab = A  + (size_t)bm * 128 * KD;
    const bf16* Bb = Bw + (size_t)bn * 128 * KD;

    const uint32_t smb = smem_u32(sm);

    const int aRow = (lane & 7) | (((lane >> 3) & 1) << 3);
    const int aK   = (lane >> 4) & 1;
    const int bRow = (lane & 7) | (((lane >> 4) & 1) << 3);
    const int bK   = (lane >> 3) & 1;

    float acc[4][4][4];
    #pragma unroll
    for (int i = 0; i < 4; i++)
        #pragma unroll
        for (int j = 0; j < 4; j++)
            #pragma unroll
            for (int q = 0; q < 4; q++) acc[i][j][q] = 0.0f;

    auto load_chunk = [&](int buf, int kbase){
        const uint32_t sa = smb + buf * STGB;
        const uint32_t sb = sa + BUFB;
        #pragma unroll
        for (int i = 0; i < 4; i++) {
            const int idx = tid + 256*i;
            const int row = idx >> 3, q = idx & 7;
            const uint32_t off = row*128 + ((q ^ (row & 7)) << 4);
            const size_t goff = (size_t)row*KD + kbase + q*8;
            asm volatile("cp.async.cg.shared.global [%0], [%1], 16;"
                         :: "r"(sa + off), "l"(Ab + goff));
            asm volatile("cp.async.cg.shared.global [%0], [%1], 16;"
                         :: "r"(sb + off), "l"(Bb + goff));
        }
        asm volatile("cp.async.commit_group;" ::: "memory");
    };

    constexpr int NC = KD / 64;
    load_chunk(0, 0);
    if (NC > 1) load_chunk(1, 64);

    for (int c = 0; c < NC; c++) {
        if (c + 1 < NC) asm volatile("cp.async.wait_group 1;" ::: "memory");
        else            asm volatile("cp.async.wait_group 0;" ::: "memory");
        __syncthreads();
        if (c + 2 < NC) load_chunk((c + 2) % 3, (c + 2) * 64);

        const uint32_t saA = smb + (c % 3) * STGB;
        const uint32_t saB = saA + BUFB;

        #pragma unroll
        for (int s = 0; s < 4; s++) {
            const int cch = s * 2;
            uint32_t a[4][4];
            #pragma unroll
            for (int mt = 0; mt < 4; mt++) {
                const int row = warpM*64 + mt*16 + aRow;
                const uint32_t off = row*128 + (((cch + aK) ^ (row & 7)) << 4);
                LDSM_X4(a[mt][0], a[mt][1], a[mt][2], a[mt][3], saA + off);
            }
            uint32_t b[4][2];
            #pragma unroll
            for (int p = 0; p < 2; p++) {
                const int row = warpN*32 + p*16 + bRow;
                const uint32_t off = row*128 + (((cch + bK) ^ (row & 7)) << 4);
                LDSM_X4(b[2*p][0], b[2*p][1], b[2*p+1][0], b[2*p+1][1], saB + off);
            }
            #pragma unroll
            for (int mt = 0; mt < 4; mt++)
                #pragma unroll
                for (int nt = 0; nt < 4; nt++)
                    mma_bf16(acc[mt][nt][0], acc[mt][nt][1],
                             acc[mt][nt][2], acc[mt][nt][3],
                             a[mt][0], a[mt][1], a[mt][2], a[mt][3],
                             b[nt][0], b[nt][1]);
        }
    }

    const int g = lane >> 2, t = lane & 3;
    #pragma unroll
    for (int mt = 0; mt < 4; mt++) {
        const int r0 = bm*128 + warpM*64 + mt*16 + g;
        #pragma unroll
        for (int nt = 0; nt < 4; nt++) {
            const int col = bn*128 + warpN*32 + nt*8 + t*2;
            const float2 bv = *(const float2*)&bias[col];
            epi_store<EPI>(C, Yres, N, r0,     col,
                           acc[mt][nt][0] + bv.x, acc[mt][nt][1] + bv.y);
            epi_store<EPI>(C, Yres, N, r0 + 8, col,
                           acc[mt][nt][2] + bv.x, acc[mt][nt][3] + bv.y);
        }
    }
}

// ---------------- fused proj GEMM + roll + residual + LN2 ---------------------
// CTA 128(M) x 256(N=full), 512 threads, 16 warps (2x8) of 64x32 warp tiles.
#define PSTG   49152                  // (128+256) rows * 128B per stage
#define PSUMS  (3*PSTG)               // float sums[128][8][2] = 8KB
#define PSMEM  (PSUMS + 8192 + 128)

__global__ void __launch_bounds__(512)
proj_ln2(const bf16* __restrict__ A, const bf16* __restrict__ Bw,
         const float* __restrict__ bias, const float* __restrict__ x,
         float* __restrict__ Y, bf16* __restrict__ XNh,
         const float* __restrict__ g2, const float* __restrict__ be2)
{
    extern __shared__ char smraw[];
    char* sm = (char*)(((uintptr_t)smraw + 127) & ~(uintptr_t)127);
    const uint32_t smb = smem_u32(sm);
    float* sums = (float*)(sm + PSUMS);

    const int tid = threadIdx.x;
    const int wid = tid >> 5, lane = tid & 31;
    const int warpM = wid >> 3, warpN = wid & 7;   // 2 x 8
    const int bm = blockIdx.x;
    constexpr int KD = 256;

    const bf16* Ab = A + (size_t)bm * 128 * KD;

    const int aRow = (lane & 7) | (((lane >> 3) & 1) << 3);
    const int aK   = (lane >> 4) & 1;
    const int bRow = (lane & 7) | (((lane >> 4) & 1) << 3);
    const int bK   = (lane >> 3) & 1;

    float acc[4][4][4];
    #pragma unroll
    for (int i = 0; i < 4; i++)
        #pragma unroll
        for (int j = 0; j < 4; j++)
            #pragma unroll
            for (int q = 0; q < 4; q++) acc[i][j][q] = 0.0f;

    auto load_chunk = [&](int buf, int kbase){
        const uint32_t sa = smb + buf * PSTG;
        #pragma unroll
        for (int i = 0; i < 6; i++) {          // 384 rows * 8 chunks / 512 thr
            const int idx = tid + 512*i;
            const int row = idx >> 3, q = idx & 7;
            if (row < 128) {
                const uint32_t off = row*128 + ((q ^ (row & 7)) << 4);
                asm volatile("cp.async.cg.shared.global [%0], [%1], 16;"
                             :: "r"(sa + off), "l"(Ab + (size_t)row*KD + kbase + q*8));
            } else {
                const int br = row - 128;
                const uint32_t off = 16384 + br*128 + ((q ^ (br & 7)) << 4);
                asm volatile("cp.async.cg.shared.global [%0], [%1], 16;"
                             :: "r"(sa + off), "l"(Bw + (size_t)br*KD + kbase + q*8));
            }
        }
        asm volatile("cp.async.commit_group;" ::: "memory");
    };

    load_chunk(0, 0);
    load_chunk(1, 64);

    for (int c = 0; c < 4; c++) {
        if (c < 3) asm volatile("cp.async.wait_group 1;" ::: "memory");
        else       asm volatile("cp.async.wait_group 0;" ::: "memory");
        __syncthreads();
        if (c + 2 < 4) load_chunk((c + 2) % 3, (c + 2) * 64);

        const uint32_t saA = smb + (c % 3) * PSTG;
        const uint32_t saB = saA + 16384;

        #pragma unroll
        for (int s = 0; s < 4; s++) {
            const int cch = s * 2;
            uint32_t a[4][4];
            #pragma unroll
            for (int mt = 0; mt < 4; mt++) {
                const int row = warpM*64 + mt*16 + aRow;
                const uint32_t off = row*128 + (((cch + aK) ^ (row & 7)) << 4);
                LDSM_X4(a[mt][0], a[mt][1], a[mt][2], a[mt][3], saA + off);
            }
            uint32_t b[4][2];
            #pragma unroll
            for (int p = 0; p < 2; p++) {
                const int row = warpN*32 + p*16 + bRow;
                const uint32_t off = row*128 + (((cch + bK) ^ (row & 7)) << 4);
                LDSM_X4(b[2*p][0], b[2*p][1], b[2*p+1][0], b[2*p+1][1], saB + off);
            }
            #pragma unroll
            for (int mt = 0; mt < 4; mt++)
                #pragma unroll
                for (int nt = 0; nt < 4; nt++)
                    mma_bf16(acc[mt][nt][0], acc[mt][nt][1],
                             acc[mt][nt][2], acc[mt][nt][3],
                             a[mt][0], a[mt][1], a[mt][2], a[mt][3],
                             b[nt][0], b[nt][1]);
        }
    }

    // ---- epilogue: bias + roll + residual, partial row sums ----
    const int g = lane >> 2, t4 = lane & 3;
    int mo[4][2];
    #pragma unroll
    for (int mt = 0; mt < 4; mt++) {
        const int lr0 = warpM*64 + mt*16 + g;
        #pragma unroll
        for (int half = 0; half < 2; half++) {
            const int m = bm*128 + lr0 + half*8;
            const int nw = m / WTOK, w = m - nw * WTOK;
            int w2 = w + 2; if (w2 >= WTOK) w2 -= WTOK;
            mo[mt][half] = nw * WTOK + w2;
        }
        float s0 = 0.f, q0 = 0.f, s1 = 0.f, q1 = 0.f;
        #pragma unroll
        for (int nt = 0; nt < 4; nt++) {
            const int col = warpN*32 + nt*8 + t4*2;
            const float2 bv = *(const float2*)&bias[col];
            const float2 x0 = *(const float2*)&x[(size_t)mo[mt][0]*256 + col];
            const float2 x1 = *(const float2*)&x[(size_t)mo[mt][1]*256 + col];
            float y00 = acc[mt][nt][0] + bv.x + x0.x;
            float y01 = acc[mt][nt][1] + bv.y + x0.y;
            float y10 = acc[mt][nt][2] + bv.x + x1.x;
            float y11 = acc[mt][nt][3] + bv.y + x1.y;
            acc[mt][nt][0] = y00; acc[mt][nt][1] = y01;
            acc[mt][nt][2] = y10; acc[mt][nt][3] = y11;
            s0 += y00 + y01; q0 += y00*y00 + y01*y01;
            s1 += y10 + y11; q1 += y10*y10 + y11*y11;
        }
        #pragma unroll
        for (int ofs = 1; ofs <= 2; ofs <<= 1) {
            s0 += __shfl_xor_sync(0xffffffffu, s0, ofs);
            q0 += __shfl_xor_sync(0xffffffffu, q0, ofs);
            s1 += __shfl_xor_sync(0xffffffffu, s1, ofs);
            q1 += __shfl_xor_sync(0xffffffffu, q1, ofs);
        }
        if (t4 == 0) {
            sums[(lr0*8     + warpN)*2    ] = s0;
            sums[(lr0*8     + warpN)*2 + 1] = q0;
            sums[((lr0+8)*8 + warpN)*2    ] = s1;
            sums[((lr0+8)*8 + warpN)*2 + 1] = q1;
        }
    }
    __syncthreads();

    // ---- finish LN per row, write Y + XNh ----
    #pragma unroll
    for (int mt = 0; mt < 4; mt++) {
        const int lr0 = warpM*64 + mt*16 + g;
        float s0 = 0.f, q0 = 0.f, s1 = 0.f, q1 = 0.f;
        #pragma unroll
        for (int wn = 0; wn < 8; wn++) {
            s0 += sums[(lr0*8     + wn)*2    ];
            q0 += sums[(lr0*8     + wn)*2 + 1];
            s1 += sums[((lr0+8)*8 + wn)*2    ];
            q1 += sums[((lr0+8)*8 + wn)*2 + 1];
        }
        const float mean0 = s0 * (1.0f/256.0f);
        const float var0  = q0 * (1.0f/256.0f) - mean0*mean0;
        const float rs0   = rsqrtf(var0 + 1e-5f);
        const float mean1 = s1 * (1.0f/256.0f);
        const float var1  = q1 * (1.0f/256.0f) - mean1*mean1;
        const float rs1   = rsqrtf(var1 + 1e-5f);
        #pragma unroll
        for (int nt = 0; nt < 4; nt++) {
            const int col = warpN*32 + nt*8 + t4*2;
            const float2 gv = *(const float2*)&g2[col];
            const float2 bv = *(const float2*)&be2[col];
            const float y00 = acc[mt][nt][0], y01 = acc[mt][nt][1];
            const float y10 = acc[mt][nt][2], y11 = acc[mt][nt][3];
            *(float2*)&Y[(size_t)mo[mt][0]*256 + col] = make_float2(y00, y01);
            *(float2*)&Y[(size_t)mo[mt][1]*256 + col] = make_float2(y10, y11);
            *(uint32_t*)(XNh + (size_t)mo[mt][0]*256 + col) =
                pk((y00-mean0)*rs0*gv.x + bv.x, (y01-mean0)*rs0*gv.y + bv.y);
            *(uint32_t*)(XNh + (size_t)mo[mt][1]*256 + col) =
                pk((y10-mean1)*rs1*gv.x + bv.x, (y11-mean1)*rs1*gv.y + bv.y);
        }
    }
}

// ---------------- tensor-core windowed attention ------------------------------
// Block = (window, head), 256 thr (8 warps, warp w = tile w, tile 7 idle).
// P (28.7 KB) ALIASES Q+K after the S-phase (block-wide __syncthreads barrier).
// smem: [0,14336) Q / later P rows 0..55 ; [14336,28672) K / later P rows 56..111
//       [28672,43008) V ; [43008,...) region ids.
#define SMK 14336
#define SMV 28672
#define SMRGN 43008
#define ATTN_SMEM (43008 + 512)

__global__ void __launch_bounds__(256, 3)
attn_kernel(const bf16* __restrict__ qkv,
            const float* __restrict__ eb,
            bf16* __restrict__ o)
{
    extern __shared__ char smraw[];
    const uint32_t smb = smem_u32(smraw);
    int* rgn = (int*)(smraw + SMRGN);

    const int n = blockIdx.x, h = blockIdx.y;
    const int tid = threadIdx.x, warp = tid >> 5, lane = tid & 31;
    const int f = n & 31;
    const size_t base = (size_t)n * WTOK * 768;

    // load Q(prescaled)/K/V bf16 -> swizzled smem; zero pad rows 108..111
    for (int idx = tid; idx < 112*8; idx += 256) {
        const int row = idx >> 3, q = idx & 7;
        const uint32_t off = row*128 + ((q ^ (row & 7)) << 4);
        uint4 uq = {0,0,0,0}, uk = {0,0,0,0}, uv = {0,0,0,0};
        if (row < WTOK) {
            const bf16* rp = qkv + base + (size_t)row * 768 + h*64 + q*8;
            uq = *(const uint4*)(rp);
            uk = *(const uint4*)(rp + 256);
            uv = *(const uint4*)(rp + 512);
        }
        *(uint4*)(smraw + off)       = uq;
        *(uint4*)(smraw + SMK + off) = uk;
        *(uint4*)(smraw + SMV + off) = uv;
    }
    for (int w = tid; w < 112; w += 256) {
        if (w < WTOK) {
            const int gf = f * 4 + w / 27;
            rgn[w] = (gf >= 126) ? 2 : ((gf >= 124) ? 1 : 0);
        } else rgn[w] = -1;
    }
    __syncthreads();

    const int aRow = (lane & 7) | (((lane >> 3) & 1) << 3);
    const int aK   = (lane >> 4) & 1;
    const int bRow = (lane & 7) | (((lane >> 4) & 1) << 3);
    const int bK   = (lane >> 3) & 1;
    const int g = lane >> 2, t4 = lane & 3;

    const int mt = warp;
    float sacc[14][4];

    // ---- S = Q @ K^T ----
    if (mt < 7) {
        #pragma unroll
        for (int nt = 0; nt < 14; nt++)
            #pragma unroll
            for (int q = 0; q < 4; q++) sacc[nt][q] = 0.0f;

        #pragma unroll
        for (int s = 0; s < 4; s++) {
            const int cch = 2*s;
            uint32_t a0,a1,a2,a3;
            {
                const int row = mt*16 + aRow;
                const uint32_t off = row*128 + (((cch + aK) ^ (row & 7)) << 4);
                LDSM_X4(a0,a1,a2,a3, smb + off);
            }
            uint32_t bq[14][2];
            #pragma unroll
            for (int p = 0; p < 7; p++) {
                const int row = p*16 + bRow;
                const uint32_t off = row*128 + (((cch + bK) ^ (row & 7)) << 4);
                LDSM_X4(bq[2*p][0], bq[2*p][1], bq[2*p+1][0], bq[2*p+1][1],
                        smb + SMK + off);
            }
            #pragma unroll
            for (int nt = 0; nt < 14; nt++)
                mma_bf16(sacc[nt][0], sacc[nt][1], sacc[nt][2], sacc[nt][3],
                         a0,a1,a2,a3, bq[nt][0], bq[nt][1]);
        }
    }
    __syncthreads();          // Q, K now dead -> P may alias them

    if (mt < 7) {
        // ---- softmax (reference quirks) ----
        const int r0 = mt*16 + g, r1 = r0 + 8;
        const int rq0 = rgn[r0], rq1 = rgn[r1];
        #pragma unroll
        for (int nt = 0; nt < 14; nt++) {
            const int j0 = nt*8 + t4*2;
            const bool jc = j0 < WTOK;
            float2 e0 = make_float2(0.f,0.f), e1 = make_float2(0.f,0.f);
            if (jc)              e0 = *(const float2*)(eb + r0*WTOK + j0);
            if (jc && r1 < WTOK) e1 = *(const float2*)(eb + r1*WTOK + j0);
            const int rj0 = rgn[j0], rj1 = rgn[j0+1];
            float av;
            av = (rj0==rq0) ? sacc[nt][0]*e0.x : 0.f;
            sacc[nt][0] = jc ? ((av==0.f) ? 10000.0f : -av) : -3.0e38f;
            av = (rj1==rq0) ? sacc[nt][1]*e0.y : 0.f;
            sacc[nt][1] = jc ? ((av==0.f) ? 10000.0f : -av) : -3.0e38f;
            av = (rj0==rq1) ? sacc[nt][2]*e1.x : 0.f;
            sacc[nt][2] = jc ? ((av==0.f) ? 10000.0f : -av) : -3.0e38f;
            av = (rj1==rq1) ? sacc[nt][3]*e1.y : 0.f;
            sacc[nt][3] = jc ? ((av==0.f) ? 10000.0f : -av) : -3.0e38f;
        }
        float m0 = -3.0e38f, m1 = -3.0e38f;
        #pragma unroll
        for (int nt = 0; nt < 14; nt++) {
            m0 = fmaxf(m0, fmaxf(sacc[nt][0], sacc[nt][1]));
            m1 = fmaxf(m1, fmaxf(sacc[nt][2], sacc[nt][3]));
        }
        #pragma unroll
        for (int ofs = 1; ofs <= 2; ofs <<= 1) {
            m0 = fmaxf(m0, __shfl_xor_sync(0xffffffffu, m0, ofs));
            m1 = fmaxf(m1, __shfl_xor_sync(0xffffffffu, m1, ofs));
        }
        float s0 = 0.f, s1 = 0.f;
        #pragma unroll
        for (int nt = 0; nt < 14; nt++) {
            sacc[nt][0] = expf(sacc[nt][0] - m0); s0 += sacc[nt][0];
            sacc[nt][1] = expf(sacc[nt][1] - m0); s0 += sacc[nt][1];
            sacc[nt][2] = expf(sacc[nt][2] - m1); s1 += sacc[nt][2];
            sacc[nt][3] = expf(sacc[nt][3] - m1); s1 += sacc[nt][3];
        }
        #pragma unroll
        for (int ofs = 1; ofs <= 2; ofs <<= 1) {
            s0 += __shfl_xor_sync(0xffffffffu, s0, ofs);
            s1 += __shfl_xor_sync(0xffffffffu, s1, ofs);
        }
        const float i0 = 1.0f / s0, i1 = 1.0f / s1;

        // store P (bf16) at base 0 (aliases dead Q/K); warp-private rows
        #pragma unroll
        for (int nt = 0; nt < 14; nt++) {
            const uint32_t chi = (uint32_t)(nt >> 3) << 7;
            const uint32_t a0off = r0*256 + chi + ((((uint32_t)nt & 7) ^ (r0 & 7)) << 4) + t4*4;
            const uint32_t a1off = r1*256 + chi + ((((uint32_t)nt & 7) ^ (r1 & 7)) << 4) + t4*4;
            *(uint32_t*)(smraw + a0off) = pk(sacc[nt][0]*i0, sacc[nt][1]*i0);
            *(uint32_t*)(smraw + a1off) = pk(sacc[nt][2]*i1, sacc[nt][3]*i1);
        }
        __syncwarp();

        // ---- O = P @ V ----
        float oacc[8][4];
        #pragma unroll
        for (int nt = 0; nt < 8; nt++)
            #pragma unroll
            for (int q = 0; q < 4; q++) oacc[nt][q] = 0.0f;

        #pragma unroll
        for (int sp = 0; sp < 7; sp++) {
            uint32_t a0,a1,a2,a3;
            {
                const int row = mt*16 + aRow;
                const int c = 2*sp + aK;
                const uint32_t off = row*256 + ((uint32_t)(c >> 3) << 7)
                                   + ((((uint32_t)c & 7) ^ (row & 7)) << 4);
                LDSM_X4(a0,a1,a2,a3, smb + off);
            }
            uint32_t bv[8][2];
            #pragma unroll
            for (int ntp = 0; ntp < 4; ntp++) {
                const int vrow = sp*16 + (lane & 7) + 8*((lane >> 3) & 1);
                const int ch = ntp*2 + ((lane >> 4) & 1);
                const uint32_t off = vrow*128 + (((uint32_t)ch ^ (vrow & 7)) << 4);
                LDSM_X4_T(bv[2*ntp][0], bv[2*ntp][1], bv[2*ntp+1][0], bv[2*ntp+1][1],
                          smb + SMV + off);
            }
            #pragma unroll
            for (int nt = 0; nt < 8; nt++)
                mma_bf16(oacc[nt][0], oacc[nt][1], oacc[nt][2], oacc[nt][3],
                         a0,a1,a2,a3, bv[nt][0], bv[nt][1]);
        }

        // ---- write O (bf16) ----
        bf16* ob = o + ((size_t)n * WTOK) * 256 + h*64;
        #pragma unroll
        for (int nt = 0; nt < 8; nt++) {
            const int col = nt*8 + t4*2;
            *(uint32_t*)(ob + (size_t)r0*256 + col) = pk(oacc[nt][0], oacc[nt][1]);
            if (r1 < WTOK)
                *(uint32_t*)(ob + (size_t)r1*256 + col) = pk(oacc[nt][2], oacc[nt][3]);
        }
    }
}

// ---------------- launch ------------------------------------------------------
extern "C" void kernel_launch(void* const* d_in, const int* in_sizes, int n_in,
                              void* d_out, int out_size)
{
    const float* x      = (const float*)d_in[0];
    const float* eb     = (const float*)d_in[1];
    const float* w_qkv  = (const float*)d_in[2];
    const float* b_qkv  = (const float*)d_in[3];
    const float* w_proj = (const float*)d_in[4];
    const float* b_proj = (const float*)d_in[5];
    const float* g1     = (const float*)d_in[6];
    const float* be1    = (const float*)d_in[7];
    const float* g2     = (const float*)d_in[8];
    const float* be2    = (const float*)d_in[9];
    const float* w_fc1  = (const float*)d_in[10];
    const float* b_fc1  = (const float*)d_in[11];
    const float* w_fc2  = (const float*)d_in[12];
    const float* b_fc2  = (const float*)d_in[13];
    float* out = (float*)d_out;

    float *Y;
    bf16 *QKVh, *XNh, *Oh, *H1h, *Wq, *Wp, *W1, *W2;
    cudaGetSymbolAddress((void**)&QKVh, g_QKVh);
    cudaGetSymbolAddress((void**)&Y,   g_Y);
    cudaGetSymbolAddress((void**)&XNh, g_XNh);
    cudaGetSymbolAddress((void**)&Oh,  g_Oh);
    cudaGetSymbolAddress((void**)&H1h, g_H1h);
    cudaGetSymbolAddress((void**)&Wq,  g_Wq);
    cudaGetSymbolAddress((void**)&Wp,  g_Wp);
    cudaGetSymbolAddress((void**)&W1,  g_W1);
    cudaGetSymbolAddress((void**)&W2,  g_W2);

    cudaFuncSetAttribute(attn_kernel,
                         cudaFuncAttributeMaxDynamicSharedMemorySize, ATTN_SMEM);
    cudaFuncSetAttribute(proj_ln2,
                         cudaFuncAttributeMaxDynamicSharedMemorySize, PSMEM);
    cudaFuncSetAttribute(hgemm<0,256>,  cudaFuncAttributeMaxDynamicSharedMemorySize, GSMEM);
    cudaFuncSetAttribute(hgemm<2,256>,  cudaFuncAttributeMaxDynamicSharedMemorySize, GSMEM);
    cudaFuncSetAttribute(hgemm<3,1024>, cudaFuncAttributeMaxDynamicSharedMemorySize, GSMEM);

    // 0) weights fp32 -> bf16 (single merged launch)
    f2bf_all<<<(WQ_N + WP_N + W1_N + W2_N) / 4 / 256, 256>>>(w_qkv, w_proj, w_fc1, w_fc2);

    // 1) shift + window + LN1 (bf16 out)
    ln1_kernel<<<NTOK / 8, 256>>>(x, g1, be1);
    // 2) QKV GEMM -> bf16 (q pre-scaled by 0.125 in epilogue)
    hgemm<0,256><<<dim3(6, NTOK/128), 256, GSMEM>>>(XNh, Wq, b_qkv, nullptr, QKVh, 768);
    // 3) attention (tensor cores, P aliases Q/K, 3 CTAs/SM)
    attn_kernel<<<dim3(NWIN, 4), 256, ATTN_SMEM>>>(QKVh, eb, Oh);
    // 4) fused proj + roll + residual + LN2 -> Y (fp32), XNh (bf16)
    proj_ln2<<<NTOK/128, 512, PSMEM>>>(Oh, Wp, b_proj, x, Y, XNh, g2, be2);
    // 5) FC1 + GELU
    hgemm<2,256><<<dim3(8, NTOK/128), 256, GSMEM>>>(XNh, W1, b_fc1, nullptr, H1h, 1024);
    // 6) FC2 + residual -> output
    hgemm<3,1024><<<dim3(2, NTOK/128), 256, GSMEM>>>(H1h, W2, b_fc2, Y, out, 256);
}

// round 15
// speedup vs baseline: 6.5624x; 1.0283x over previous
#include <cuda_runtime.h>
#include <cuda_bf16.h>
#include <math.h>
#include <stdint.h>

typedef __nv_bfloat16 bf16;

// Problem constants
#define NTOK   110592          // 1024 windows * 108 tokens
#define NWIN   1024
#define WTOK   108

// ---------------- scratch (static device globals; no allocation) -------------
__device__ bf16  g_QKVh[ (size_t)NTOK * 768 ];  // qkv (bf16, q pre-scaled)
__device__ float g_Y  [ (size_t)NTOK * 256 ];   // x + attn branch (residual base)
__device__ bf16  g_XNh[ (size_t)NTOK * 256 ];   // LN out (bf16, GEMM A input)
__device__ bf16  g_Oh [ (size_t)NTOK * 256 ];   // attention out (bf16)
__device__ bf16  g_H1h[ (size_t)NTOK * 1024 ];  // FC1+GELU out (bf16)
__device__ bf16  g_Wq [ 768 * 256 ];
__device__ bf16  g_Wp [ 256 * 256 ];
__device__ bf16  g_W1 [ 1024 * 256 ];
__device__ bf16  g_W2 [ 256 * 1024 ];

// ---------------- helpers ----------------------------------------------------
__device__ __forceinline__ float warp_sum(float v){
    #pragma unroll
    for (int o = 16; o; o >>= 1) v += __shfl_xor_sync(0xffffffffu, v, o);
    return v;
}
__device__ __forceinline__ uint32_t smem_u32(const void* p){
    uint32_t a;
    asm("{ .reg .u64 t; cvta.to.shared.u64 t, %1; cvt.u32.u64 %0, t; }"
        : "=r"(a) : "l"(p));
    return a;
}
__device__ __forceinline__ uint32_t pk(float a, float b){
    __nv_bfloat162 t = __floats2bfloat162_rn(a, b);
    return *(uint32_t*)&t;
}

#define LDSM_X4(r0,r1,r2,r3,addr) \
    asm volatile("ldmatrix.sync.aligned.m8n8.x4.shared.b16 {%0,%1,%2,%3}, [%4];" \
        : "=r"(r0), "=r"(r1), "=r"(r2), "=r"(r3) : "r"(addr))
#define LDSM_X4_T(r0,r1,r2,r3,addr) \
    asm volatile("ldmatrix.sync.aligned.m8n8.x4.trans.shared.b16 {%0,%1,%2,%3}, [%4];" \
        : "=r"(r0), "=r"(r1), "=r"(r2), "=r"(r3) : "r"(addr))

__device__ __forceinline__ void mma_bf16(float& c0, float& c1, float& c2, float& c3,
                                         uint32_t a0, uint32_t a1, uint32_t a2, uint32_t a3,
                                         uint32_t b0, uint32_t b1)
{
    asm volatile(
        "mma.sync.aligned.m16n8k16.row.col.f32.bf16.bf16.f32 "
        "{%0,%1,%2,%3}, {%4,%5,%6,%7}, {%8,%9}, {%0,%1,%2,%3};"
        : "+f"(c0), "+f"(c1), "+f"(c2), "+f"(c3)
        : "r"(a0), "r"(a1), "r"(a2), "r"(a3), "r"(b0), "r"(b1));
}

// ---------------- merged weight fp32 -> bf16 convert --------------------------
#define WQ_N (768*256)
#define WP_N (256*256)
#define W1_N (1024*256)
#define W2_N (256*1024)
__global__ void f2bf_all(const float* __restrict__ wq, const float* __restrict__ wp,
                         const float* __restrict__ w1, const float* __restrict__ w2)
{
    int i = (blockIdx.x * 256 + threadIdx.x) * 4;
    const float* s; bf16* d;
    if (i < WQ_N)                       { s = wq + i;  d = g_Wq + i; }
    else if ((i -= WQ_N) < WP_N)        { s = wp + i;  d = g_Wp + i; }
    else if ((i -= WP_N) < W1_N)        { s = w1 + i;  d = g_W1 + i; }
    else if ((i -= W1_N) < W2_N)        { s = w2 + i;  d = g_W2 + i; }
    else return;
    float4 v = *(const float4*)s;
    __nv_bfloat162* dp = (__nv_bfloat162*)d;
    dp[0] = __floats2bfloat162_rn(v.x, v.y);
    dp[1] = __floats2bfloat162_rn(v.z, v.w);
}

// ---------------- LN1 with shift + window gather (bf16 out) -------------------
__global__ void ln1_kernel(const float* __restrict__ x,
                           const float* __restrict__ g,
                           const float* __restrict__ be)
{
    const int warp = threadIdx.x >> 5, lane = threadIdx.x & 31;
    const int t = blockIdx.x * 8 + warp;
    const int n = t / WTOK, w = t - n * WTOK;
    const int b = n >> 5, f = n & 31;
    const int wf = w / 27;
    const int gf = f * 4 + wf;
    const int fr = (gf + 2) & 127;
    const int kp = w - wf * 27;
    const float* src = x + (size_t)((b * 128 + fr) * 27 + kp) * 256;

    float4 v0 = ((const float4*)src)[lane];
    float4 v1 = ((const float4*)src)[lane + 32];
    float s = v0.x+v0.y+v0.z+v0.w + v1.x+v1.y+v1.z+v1.w;
    float q = v0.x*v0.x+v0.y*v0.y+v0.z*v0.z+v0.w*v0.w
            + v1.x*v1.x+v1.y*v1.y+v1.z*v1.z+v1.w*v1.w;
    s = warp_sum(s); q = warp_sum(q);
    const float mean = s * (1.0f/256.0f);
    const float var  = q * (1.0f/256.0f) - mean*mean;
    const float rstd = rsqrtf(var + 1e-5f);

    __nv_bfloat162* dst = (__nv_bfloat162*)(g_XNh + (size_t)t * 256);
    const int c0 = lane*4, c1 = 128 + lane*4;
    dst[lane*2]        = __floats2bfloat162_rn((v0.x-mean)*rstd*g[c0+0] + be[c0+0],
                                               (v0.y-mean)*rstd*g[c0+1] + be[c0+1]);
    dst[lane*2+1]      = __floats2bfloat162_rn((v0.z-mean)*rstd*g[c0+2] + be[c0+2],
                                               (v0.w-mean)*rstd*g[c0+3] + be[c0+3]);
    dst[64 + lane*2]   = __floats2bfloat162_rn((v1.x-mean)*rstd*g[c1+0] + be[c1+0],
                                               (v1.y-mean)*rstd*g[c1+1] + be[c1+1]);
    dst[64 + lane*2+1] = __floats2bfloat162_rn((v1.z-mean)*rstd*g[c1+2] + be[c1+2],
                                               (v1.w-mean)*rstd*g[c1+3] + be[c1+3]);
}

// ---------------- bf16 mma.sync NT GEMM, 3-stage cp.async pipeline -----------
#define BUFB  16384
#define STGB  (2*BUFB)
#define GSMEM (3*STGB + 128)

template<int EPI>
__device__ __forceinline__ void epi_store(void* __restrict__ C,
                                          const float* __restrict__ Yres,
                                          int N, int m, int col,
                                          float v0, float v1)
{
    if (EPI == 0) {
        const float sc = (col < 256) ? 0.125f : 1.0f;
        *(__nv_bfloat162*)((bf16*)C + (size_t)m*N + col) =
            __floats2bfloat162_rn(v0*sc, v1*sc);
        return;
    }
    if (EPI == 2) {
        v0 = 0.5f*v0*(1.0f + erff(v0*0.70710678118654752f));
        v1 = 0.5f*v1*(1.0f + erff(v1*0.70710678118654752f));
        *(__nv_bfloat162*)((bf16*)C + (size_t)m*N + col) = __floats2bfloat162_rn(v0, v1);
        return;
    }
    if (EPI == 3) {
        const float2 yv = *(const float2*)&Yres[(size_t)m*N + col];
        v0 += yv.x; v1 += yv.y;
    }
    *(float2*)((float*)C + (size_t)m*N + col) = make_float2(v0, v1);
}

template<int EPI, int KD>
__global__ void __launch_bounds__(256)
hgemm(const bf16* __restrict__ A, const bf16* __restrict__ Bw,
      const float* __restrict__ bias, const float* __restrict__ Yres,
      void* __restrict__ C, int N)
{
    extern __shared__ char smraw[];
    char* sm = (char*)(((uintptr_t)smraw + 127) & ~(uintptr_t)127);

    const int tid = threadIdx.x;
    const int wid = tid >> 5, lane = tid & 31;
    const int warpM = wid >> 2, warpN = wid & 3;   // 2 x 4
    const int bn = blockIdx.x, bm = blockIdx.y;

    const bf16* Ab = A  + (size_t)bm * 128 * KD;
    const bf16* Bb = Bw + (size_t)bn * 128 * KD;

    const uint32_t smb = smem_u32(sm);

    const int aRow = (lane & 7) | (((lane >> 3) & 1) << 3);
    const int aK   = (lane >> 4) & 1;
    const int bRow = (lane & 7) | (((lane >> 4) & 1) << 3);
    const int bK   = (lane >> 3) & 1;

    float acc[4][4][4];
    #pragma unroll
    for (int i = 0; i < 4; i++)
        #pragma unroll
        for (int j = 0; j < 4; j++)
            #pragma unroll
            for (int q = 0; q < 4; q++) acc[i][j][q] = 0.0f;

    auto load_chunk = [&](int buf, int kbase){
        const uint32_t sa = smb + buf * STGB;
        const uint32_t sb = sa + BUFB;
        #pragma unroll
        for (int i = 0; i < 4; i++) {
            const int idx = tid + 256*i;
            const int row = idx >> 3, q = idx & 7;
            const uint32_t off = row*128 + ((q ^ (row & 7)) << 4);
            const size_t goff = (size_t)row*KD + kbase + q*8;
            asm volatile("cp.async.cg.shared.global [%0], [%1], 16;"
                         :: "r"(sa + off), "l"(Ab + goff));
            asm volatile("cp.async.cg.shared.global [%0], [%1], 16;"
                         :: "r"(sb + off), "l"(Bb + goff));
        }
        asm volatile("cp.async.commit_group;" ::: "memory");
    };

    constexpr int NC = KD / 64;
    load_chunk(0, 0);
    if (NC > 1) load_chunk(1, 64);

    for (int c = 0; c < NC; c++) {
        if (c + 1 < NC) asm volatile("cp.async.wait_group 1;" ::: "memory");
        else            asm volatile("cp.async.wait_group 0;" ::: "memory");
        __syncthreads();
        if (c + 2 < NC) load_chunk((c + 2) % 3, (c + 2) * 64);

        const uint32_t saA = smb + (c % 3) * STGB;
        const uint32_t saB = saA + BUFB;

        #pragma unroll
        for (int s = 0; s < 4; s++) {
            const int cch = s * 2;
            uint32_t a[4][4];
            #pragma unroll
            for (int mt = 0; mt < 4; mt++) {
                const int row = warpM*64 + mt*16 + aRow;
                const uint32_t off = row*128 + (((cch + aK) ^ (row & 7)) << 4);
                LDSM_X4(a[mt][0], a[mt][1], a[mt][2], a[mt][3], saA + off);
            }
            uint32_t b[4][2];
            #pragma unroll
            for (int p = 0; p < 2; p++) {
                const int row = warpN*32 + p*16 + bRow;
                const uint32_t off = row*128 + (((cch + bK) ^ (row & 7)) << 4);
                LDSM_X4(b[2*p][0], b[2*p][1], b[2*p+1][0], b[2*p+1][1], saB + off);
            }
            #pragma unroll
            for (int mt = 0; mt < 4; mt++)
                #pragma unroll
                for (int nt = 0; nt < 4; nt++)
                    mma_bf16(acc[mt][nt][0], acc[mt][nt][1],
                             acc[mt][nt][2], acc[mt][nt][3],
                             a[mt][0], a[mt][1], a[mt][2], a[mt][3],
                             b[nt][0], b[nt][1]);
        }
    }

    const int g = lane >> 2, t = lane & 3;
    #pragma unroll
    for (int mt = 0; mt < 4; mt++) {
        const int r0 = bm*128 + warpM*64 + mt*16 + g;
        #pragma unroll
        for (int nt = 0; nt < 4; nt++) {
            const int col = bn*128 + warpN*32 + nt*8 + t*2;
            const float2 bv = *(const float2*)&bias[col];
            epi_store<EPI>(C, Yres, N, r0,     col,
                           acc[mt][nt][0] + bv.x, acc[mt][nt][1] + bv.y);
            epi_store<EPI>(C, Yres, N, r0 + 8, col,
                           acc[mt][nt][2] + bv.x, acc[mt][nt][3] + bv.y);
        }
    }
}

// ---------------- fused proj GEMM + roll + residual + LN2 ---------------------
#define PSTG   49152
#define PSUMS  (3*PSTG)
#define PSMEM  (PSUMS + 8192 + 128)

__global__ void __launch_bounds__(512)
proj_ln2(const bf16* __restrict__ A, const bf16* __restrict__ Bw,
         const float* __restrict__ bias, const float* __restrict__ x,
         float* __restrict__ Y, bf16* __restrict__ XNh,
         const float* __restrict__ g2, const float* __restrict__ be2)
{
    extern __shared__ char smraw[];
    char* sm = (char*)(((uintptr_t)smraw + 127) & ~(uintptr_t)127);
    const uint32_t smb = smem_u32(sm);
    float* sums = (float*)(sm + PSUMS);

    const int tid = threadIdx.x;
    const int wid = tid >> 5, lane = tid & 31;
    const int warpM = wid >> 3, warpN = wid & 7;   // 2 x 8
    const int bm = blockIdx.x;
    constexpr int KD = 256;

    const bf16* Ab = A + (size_t)bm * 128 * KD;

    const int aRow = (lane & 7) | (((lane >> 3) & 1) << 3);
    const int aK   = (lane >> 4) & 1;
    const int bRow = (lane & 7) | (((lane >> 4) & 1) << 3);
    const int bK   = (lane >> 3) & 1;

    float acc[4][4][4];
    #pragma unroll
    for (int i = 0; i < 4; i++)
        #pragma unroll
        for (int j = 0; j < 4; j++)
            #pragma unroll
            for (int q = 0; q < 4; q++) acc[i][j][q] = 0.0f;

    auto load_chunk = [&](int buf, int kbase){
        const uint32_t sa = smb + buf * PSTG;
        #pragma unroll
        for (int i = 0; i < 6; i++) {
            const int idx = tid + 512*i;
            const int row = idx >> 3, q = idx & 7;
            if (row < 128) {
                const uint32_t off = row*128 + ((q ^ (row & 7)) << 4);
                asm volatile("cp.async.cg.shared.global [%0], [%1], 16;"
                             :: "r"(sa + off), "l"(Ab + (size_t)row*KD + kbase + q*8));
            } else {
                const int br = row - 128;
                const uint32_t off = 16384 + br*128 + ((q ^ (br & 7)) << 4);
                asm volatile("cp.async.cg.shared.global [%0], [%1], 16;"
                             :: "r"(sa + off), "l"(Bw + (size_t)br*KD + kbase + q*8));
            }
        }
        asm volatile("cp.async.commit_group;" ::: "memory");
    };

    load_chunk(0, 0);
    load_chunk(1, 64);

    for (int c = 0; c < 4; c++) {
        if (c < 3) asm volatile("cp.async.wait_group 1;" ::: "memory");
        else       asm volatile("cp.async.wait_group 0;" ::: "memory");
        __syncthreads();
        if (c + 2 < 4) load_chunk((c + 2) % 3, (c + 2) * 64);

        const uint32_t saA = smb + (c % 3) * PSTG;
        const uint32_t saB = saA + 16384;

        #pragma unroll
        for (int s = 0; s < 4; s++) {
            const int cch = s * 2;
            uint32_t a[4][4];
            #pragma unroll
            for (int mt = 0; mt < 4; mt++) {
                const int row = warpM*64 + mt*16 + aRow;
                const uint32_t off = row*128 + (((cch + aK) ^ (row & 7)) << 4);
                LDSM_X4(a[mt][0], a[mt][1], a[mt][2], a[mt][3], saA + off);
            }
            uint32_t b[4][2];
            #pragma unroll
            for (int p = 0; p < 2; p++) {
                const int row = warpN*32 + p*16 + bRow;
                const uint32_t off = row*128 + (((cch + bK) ^ (row & 7)) << 4);
                LDSM_X4(b[2*p][0], b[2*p][1], b[2*p+1][0], b[2*p+1][1], saB + off);
            }
            #pragma unroll
            for (int mt = 0; mt < 4; mt++)
                #pragma unroll
                for (int nt = 0; nt < 4; nt++)
                    mma_bf16(acc[mt][nt][0], acc[mt][nt][1],
                             acc[mt][nt][2], acc[mt][nt][3],
                             a[mt][0], a[mt][1], a[mt][2], a[mt][3],
                             b[nt][0], b[nt][1]);
        }
    }

    // ---- epilogue: bias + roll + residual, partial row sums ----
    const int g = lane >> 2, t4 = lane & 3;
    int mo[4][2];
    #pragma unroll
    for (int mt = 0; mt < 4; mt++) {
        const int lr0 = warpM*64 + mt*16 + g;
        #pragma unroll
        for (int half = 0; half < 2; half++) {
            const int m = bm*128 + lr0 + half*8;
            const int nw = m / WTOK, w = m - nw * WTOK;
            int w2 = w + 2; if (w2 >= WTOK) w2 -= WTOK;
            mo[mt][half] = nw * WTOK + w2;
        }
        float s0 = 0.f, q0 = 0.f, s1 = 0.f, q1 = 0.f;
        #pragma unroll
        for (int nt = 0; nt < 4; nt++) {
            const int col = warpN*32 + nt*8 + t4*2;
            const float2 bv = *(const float2*)&bias[col];
            const float2 x0 = *(const float2*)&x[(size_t)mo[mt][0]*256 + col];
            const float2 x1 = *(const float2*)&x[(size_t)mo[mt][1]*256 + col];
            float y00 = acc[mt][nt][0] + bv.x + x0.x;
            float y01 = acc[mt][nt][1] + bv.y + x0.y;
            float y10 = acc[mt][nt][2] + bv.x + x1.x;
            float y11 = acc[mt][nt][3] + bv.y + x1.y;
            acc[mt][nt][0] = y00; acc[mt][nt][1] = y01;
            acc[mt][nt][2] = y10; acc[mt][nt][3] = y11;
            s0 += y00 + y01; q0 += y00*y00 + y01*y01;
            s1 += y10 + y11; q1 += y10*y10 + y11*y11;
        }
        #pragma unroll
        for (int ofs = 1; ofs <= 2; ofs <<= 1) {
            s0 += __shfl_xor_sync(0xffffffffu, s0, ofs);
            q0 += __shfl_xor_sync(0xffffffffu, q0, ofs);
            s1 += __shfl_xor_sync(0xffffffffu, s1, ofs);
            q1 += __shfl_xor_sync(0xffffffffu, q1, ofs);
        }
        if (t4 == 0) {
            sums[(lr0*8     + warpN)*2    ] = s0;
            sums[(lr0*8     + warpN)*2 + 1] = q0;
            sums[((lr0+8)*8 + warpN)*2    ] = s1;
            sums[((lr0+8)*8 + warpN)*2 + 1] = q1;
        }
    }
    __syncthreads();

    // ---- finish LN per row, write Y + XNh ----
    #pragma unroll
    for (int mt = 0; mt < 4; mt++) {
        const int lr0 = warpM*64 + mt*16 + g;
        float s0 = 0.f, q0 = 0.f, s1 = 0.f, q1 = 0.f;
        #pragma unroll
        for (int wn = 0; wn < 8; wn++) {
            s0 += sums[(lr0*8     + wn)*2    ];
            q0 += sums[(lr0*8     + wn)*2 + 1];
            s1 += sums[((lr0+8)*8 + wn)*2    ];
            q1 += sums[((lr0+8)*8 + wn)*2 + 1];
        }
        const float mean0 = s0 * (1.0f/256.0f);
        const float var0  = q0 * (1.0f/256.0f) - mean0*mean0;
        const float rs0   = rsqrtf(var0 + 1e-5f);
        const float mean1 = s1 * (1.0f/256.0f);
        const float var1  = q1 * (1.0f/256.0f) - mean1*mean1;
        const float rs1   = rsqrtf(var1 + 1e-5f);
        #pragma unroll
        for (int nt = 0; nt < 4; nt++) {
            const int col = warpN*32 + nt*8 + t4*2;
            const float2 gv = *(const float2*)&g2[col];
            const float2 bv = *(const float2*)&be2[col];
            const float y00 = acc[mt][nt][0], y01 = acc[mt][nt][1];
            const float y10 = acc[mt][nt][2], y11 = acc[mt][nt][3];
            *(float2*)&Y[(size_t)mo[mt][0]*256 + col] = make_float2(y00, y01);
            *(float2*)&Y[(size_t)mo[mt][1]*256 + col] = make_float2(y10, y11);
            *(uint32_t*)(XNh + (size_t)mo[mt][0]*256 + col) =
                pk((y00-mean0)*rs0*gv.x + bv.x, (y01-mean0)*rs0*gv.y + bv.y);
            *(uint32_t*)(XNh + (size_t)mo[mt][1]*256 + col) =
                pk((y10-mean1)*rs1*gv.x + bv.x, (y11-mean1)*rs1*gv.y + bv.y);
        }
    }
}

// ---------------- tensor-core windowed attention ------------------------------
// Block = (window, head), 256 thr (8 warps, warp w = tile w, tile 7 idle).
// Q/K/V gathered via cp.async (global->smem direct). P aliases Q+K post S-phase.
#define SMK 14336
#define SMV 28672
#define SMRGN 43008
#define ATTN_SMEM (43008 + 512)

__global__ void __launch_bounds__(256, 3)
attn_kernel(const bf16* __restrict__ qkv,
            const float* __restrict__ eb,
            bf16* __restrict__ o)
{
    extern __shared__ char smraw[];
    const uint32_t smb = smem_u32(smraw);
    int* rgn = (int*)(smraw + SMRGN);

    const int n = blockIdx.x, h = blockIdx.y;
    const int tid = threadIdx.x, warp = tid >> 5, lane = tid & 31;
    const int f = n & 31;
    const size_t base = (size_t)n * WTOK * 768;

    // Q(prescaled)/K/V gather via cp.async; zero-pad rows 108..111 via STS
    for (int idx = tid; idx < WTOK*8; idx += 256) {
        const int row = idx >> 3, q = idx & 7;
        const uint32_t off = row*128 + ((q ^ (row & 7)) << 4);
        const bf16* rp = qkv + base + (size_t)row * 768 + h*64 + q*8;
        asm volatile("cp.async.cg.shared.global [%0], [%1], 16;"
                     :: "r"(smb + off), "l"(rp));
        asm volatile("cp.async.cg.shared.global [%0], [%1], 16;"
                     :: "r"(smb + SMK + off), "l"(rp + 256));
        asm volatile("cp.async.cg.shared.global [%0], [%1], 16;"
                     :: "r"(smb + SMV + off), "l"(rp + 512));
    }
    // pad rows 108..111 (4 rows * 8 chunks = 32 STS.128 of zeros)
    if (tid < 32) {
        const int row = WTOK + (tid >> 3), q = tid & 7;
        const uint32_t off = row*128 + ((q ^ (row & 7)) << 4);
        const uint4 z = {0,0,0,0};
        *(uint4*)(smraw + off)       = z;
        *(uint4*)(smraw + SMK + off) = z;
        *(uint4*)(smraw + SMV + off) = z;
    }
    for (int w = tid; w < 112; w += 256) {
        if (w < WTOK) {
            const int gf = f * 4 + w / 27;
            rgn[w] = (gf >= 126) ? 2 : ((gf >= 124) ? 1 : 0);
        } else rgn[w] = -1;
    }
    asm volatile("cp.async.commit_group;" ::: "memory");
    asm volatile("cp.async.wait_group 0;" ::: "memory");
    __syncthreads();

    const int aRow = (lane & 7) | (((lane >> 3) & 1) << 3);
    const int aK   = (lane >> 4) & 1;
    const int bRow = (lane & 7) | (((lane >> 4) & 1) << 3);
    const int bK   = (lane >> 3) & 1;
    const int g = lane >> 2, t4 = lane & 3;

    const int mt = warp;
    float sacc[14][4];

    // ---- S = Q @ K^T ----
    if (mt < 7) {
        #pragma unroll
        for (int nt = 0; nt < 14; nt++)
            #pragma unroll
            for (int q = 0; q < 4; q++) sacc[nt][q] = 0.0f;

        #pragma unroll
        for (int s = 0; s < 4; s++) {
            const int cch = 2*s;
            uint32_t a0,a1,a2,a3;
            {
                const int row = mt*16 + aRow;
                const uint32_t off = row*128 + (((cch + aK) ^ (row & 7)) << 4);
                LDSM_X4(a0,a1,a2,a3, smb + off);
            }
            uint32_t bq[14][2];
            #pragma unroll
            for (int p = 0; p < 7; p++) {
                const int row = p*16 + bRow;
                const uint32_t off = row*128 + (((cch + bK) ^ (row & 7)) << 4);
                LDSM_X4(bq[2*p][0], bq[2*p][1], bq[2*p+1][0], bq[2*p+1][1],
                        smb + SMK + off);
            }
            #pragma unroll
            for (int nt = 0; nt < 14; nt++)
                mma_bf16(sacc[nt][0], sacc[nt][1], sacc[nt][2], sacc[nt][3],
                         a0,a1,a2,a3, bq[nt][0], bq[nt][1]);
        }
    }
    __syncthreads();          // Q, K now dead -> P may alias them

    if (mt < 7) {
        // ---- softmax (reference quirks) ----
        const int r0 = mt*16 + g, r1 = r0 + 8;
        const int rq0 = rgn[r0], rq1 = rgn[r1];
        #pragma unroll
        for (int nt = 0; nt < 14; nt++) {
            const int j0 = nt*8 + t4*2;
            const bool jc = j0 < WTOK;
            float2 e0 = make_float2(0.f,0.f), e1 = make_float2(0.f,0.f);
            if (jc)              e0 = *(const float2*)(eb + r0*WTOK + j0);
            if (jc && r1 < WTOK) e1 = *(const float2*)(eb + r1*WTOK + j0);
            const int rj0 = rgn[j0], rj1 = rgn[j0+1];
            float av;
            av = (rj0==rq0) ? sacc[nt][0]*e0.x : 0.f;
            sacc[nt][0] = jc ? ((av==0.f) ? 10000.0f : -av) : -3.0e38f;
            av = (rj1==rq0) ? sacc[nt][1]*e0.y : 0.f;
            sacc[nt][1] = jc ? ((av==0.f) ? 10000.0f : -av) : -3.0e38f;
            av = (rj0==rq1) ? sacc[nt][2]*e1.x : 0.f;
            sacc[nt][2] = jc ? ((av==0.f) ? 10000.0f : -av) : -3.0e38f;
            av = (rj1==rq1) ? sacc[nt][3]*e1.y : 0.f;
            sacc[nt][3] = jc ? ((av==0.f) ? 10000.0f : -av) : -3.0e38f;
        }
        float m0 = -3.0e38f, m1 = -3.0e38f;
        #pragma unroll
        for (int nt = 0; nt < 14; nt++) {
            m0 = fmaxf(m0, fmaxf(sacc[nt][0], sacc[nt][1]));
            m1 = fmaxf(m1, fmaxf(sacc[nt][2], sacc[nt][3]));
        }
        #pragma unroll
        for (int ofs = 1; ofs <= 2; ofs <<= 1) {
            m0 = fmaxf(m0, __shfl_xor_sync(0xffffffffu, m0, ofs));
            m1 = fmaxf(m1, __shfl_xor_sync(0xffffffffu, m1, ofs));
        }
        float s0 = 0.f, s1 = 0.f;
        #pragma unroll
        for (int nt = 0; nt < 14; nt++) {
            sacc[nt][0] = expf(sacc[nt][0] - m0); s0 += sacc[nt][0];
            sacc[nt][1] = expf(sacc[nt][1] - m0); s0 += sacc[nt][1];
            sacc[nt][2] = expf(sacc[nt][2] - m1); s1 += sacc[nt][2];
            sacc[nt][3] = expf(sacc[nt][3] - m1); s1 += sacc[nt][3];
        }
        #pragma unroll
        for (int ofs = 1; ofs <= 2; ofs <<= 1) {
            s0 += __shfl_xor_sync(0xffffffffu, s0, ofs);
            s1 += __shfl_xor_sync(0xffffffffu, s1, ofs);
        }
        const float i0 = 1.0f / s0, i1 = 1.0f / s1;

        // store P (bf16) at base 0 (aliases dead Q/K); warp-private rows
        #pragma unroll
        for (int nt = 0; nt < 14; nt++) {
            const uint32_t chi = (uint32_t)(nt >> 3) << 7;
            const uint32_t a0off = r0*256 + chi + ((((uint32_t)nt & 7) ^ (r0 & 7)) << 4) + t4*4;
            const uint32_t a1off = r1*256 + chi + ((((uint32_t)nt & 7) ^ (r1 & 7)) << 4) + t4*4;
            *(uint32_t*)(smraw + a0off) = pk(sacc[nt][0]*i0, sacc[nt][1]*i0);
            *(uint32_t*)(smraw + a1off) = pk(sacc[nt][2]*i1, sacc[nt][3]*i1);
        }
        __syncwarp();

        // ---- O = P @ V ----
        float oacc[8][4];
        #pragma unroll
        for (int nt = 0; nt < 8; nt++)
            #pragma unroll
            for (int q = 0; q < 4; q++) oacc[nt][q] = 0.0f;

        #pragma unroll
        for (int sp = 0; sp < 7; sp++) {
            uint32_t a0,a1,a2,a3;
            {
                const int row = mt*16 + aRow;
                const int c = 2*sp + aK;
                const uint32_t off = row*256 + ((uint32_t)(c >> 3) << 7)
                                   + ((((uint32_t)c & 7) ^ (row & 7)) << 4);
                LDSM_X4(a0,a1,a2,a3, smb + off);
            }
            uint32_t bv[8][2];
            #pragma unroll
            for (int ntp = 0; ntp < 4; ntp++) {
                const int vrow = sp*16 + (lane & 7) + 8*((lane >> 3) & 1);
                const int ch = ntp*2 + ((lane >> 4) & 1);
                const uint32_t off = vrow*128 + (((uint32_t)ch ^ (vrow & 7)) << 4);
                LDSM_X4_T(bv[2*ntp][0], bv[2*ntp][1], bv[2*ntp+1][0], bv[2*ntp+1][1],
                          smb + SMV + off);
            }
            #pragma unroll
            for (int nt = 0; nt < 8; nt++)
                mma_bf16(oacc[nt][0], oacc[nt][1], oacc[nt][2], oacc[nt][3],
                         a0,a1,a2,a3, bv[nt][0], bv[nt][1]);
        }

        // ---- write O (bf16) ----
        bf16* ob = o + ((size_t)n * WTOK) * 256 + h*64;
        #pragma unroll
        for (int nt = 0; nt < 8; nt++) {
            const int col = nt*8 + t4*2;
            *(uint32_t*)(ob + (size_t)r0*256 + col) = pk(oacc[nt][0], oacc[nt][1]);
            if (r1 < WTOK)
                *(uint32_t*)(ob + (size_t)r1*256 + col) = pk(oacc[nt][2], oacc[nt][3]);
        }
    }
}

// ---------------- launch ------------------------------------------------------
extern "C" void kernel_launch(void* const* d_in, const int* in_sizes, int n_in,
                              void* d_out, int out_size)
{
    const float* x      = (const float*)d_in[0];
    const float* eb     = (const float*)d_in[1];
    const float* w_qkv  = (const float*)d_in[2];
    const float* b_qkv  = (const float*)d_in[3];
    const float* w_proj = (const float*)d_in[4];
    const float* b_proj = (const float*)d_in[5];
    const float* g1     = (const float*)d_in[6];
    const float* be1    = (const float*)d_in[7];
    const float* g2     = (const float*)d_in[8];
    const float* be2    = (const float*)d_in[9];
    const float* w_fc1  = (const float*)d_in[10];
    const float* b_fc1  = (const float*)d_in[11];
    const float* w_fc2  = (const float*)d_in[12];
    const float* b_fc2  = (const float*)d_in[13];
    float* out = (float*)d_out;

    float *Y;
    bf16 *QKVh, *XNh, *Oh, *H1h, *Wq, *Wp, *W1, *W2;
    cudaGetSymbolAddress((void**)&QKVh, g_QKVh);
    cudaGetSymbolAddress((void**)&Y,   g_Y);
    cudaGetSymbolAddress((void**)&XNh, g_XNh);
    cudaGetSymbolAddress((void**)&Oh,  g_Oh);
    cudaGetSymbolAddress((void**)&H1h, g_H1h);
    cudaGetSymbolAddress((void**)&Wq,  g_Wq);
    cudaGetSymbolAddress((void**)&Wp,  g_Wp);
    cudaGetSymbolAddress((void**)&W1,  g_W1);
    cudaGetSymbolAddress((void**)&W2,  g_W2);

    cudaFuncSetAttribute(attn_kernel,
                         cudaFuncAttributeMaxDynamicSharedMemorySize, ATTN_SMEM);
    cudaFuncSetAttribute(proj_ln2,
                         cudaFuncAttributeMaxDynamicSharedMemorySize, PSMEM);
    cudaFuncSetAttribute(hgemm<0,256>,  cudaFuncAttributeMaxDynamicSharedMemorySize, GSMEM);
    cudaFuncSetAttribute(hgemm<2,256>,  cudaFuncAttributeMaxDynamicSharedMemorySize, GSMEM);
    cudaFuncSetAttribute(hgemm<3,1024>, cudaFuncAttributeMaxDynamicSharedMemorySize, GSMEM);

    // 0) weights fp32 -> bf16 (single merged launch)
    f2bf_all<<<(WQ_N + WP_N + W1_N + W2_N) / 4 / 256, 256>>>(w_qkv, w_proj, w_fc1, w_fc2);

    // 1) shift + window + LN1 (bf16 out)
    ln1_kernel<<<NTOK / 8, 256>>>(x, g1, be1);
    // 2) QKV GEMM -> bf16 (q pre-scaled by 0.125 in epilogue)
    hgemm<0,256><<<dim3(6, NTOK/128), 256, GSMEM>>>(XNh, Wq, b_qkv, nullptr, QKVh, 768);
    // 3) attention (tensor cores, cp.async gather, P aliases Q/K)
    attn_kernel<<<dim3(NWIN, 4), 256, ATTN_SMEM>>>(QKVh, eb, Oh);
    // 4) fused proj + roll + residual + LN2 -> Y (fp32), XNh (bf16)
    proj_ln2<<<NTOK/128, 512, PSMEM>>>(Oh, Wp, b_proj, x, Y, XNh, g2, be2);
    // 5) FC1 + GELU
    hgemm<2,256><<<dim3(8, NTOK/128), 256, GSMEM>>>(XNh, W1, b_fc1, nullptr, H1h, 1024);
    // 6) FC2 + residual -> output
    hgemm<3,1024><<<dim3(2, NTOK/128), 256, GSMEM>>>(H1h, W2, b_fc2, Y, out, 256);
}

// round 17
// speedup vs baseline: 6.9188x; 1.0543x over previous
#include <cuda_runtime.h>
#include <cuda_bf16.h>
#include <math.h>
#include <stdint.h>

typedef __nv_bfloat16 bf16;

// Problem constants
#define NTOK   110592          // 1024 windows * 108 tokens
#define NWIN   1024
#define WTOK   108

// ---------------- scratch (static device globals; no allocation) -------------
__device__ bf16  g_QKVh[ (size_t)NTOK * 768 ];  // qkv (bf16, q pre-scaled)
__device__ float g_Y  [ (size_t)NTOK * 256 ];   // x + attn branch (residual base)
__device__ bf16  g_XNh[ (size_t)NTOK * 256 ];   // LN out (bf16, GEMM A input)
__device__ bf16  g_Oh [ (size_t)NTOK * 256 ];   // attention out (bf16)
__device__ bf16  g_H1h[ (size_t)NTOK * 1024 ];  // FC1+GELU out (bf16)
__device__ bf16  g_Wq [ 768 * 256 ];
__device__ bf16  g_Wp [ 256 * 256 ];
__device__ bf16  g_W1 [ 1024 * 256 ];
__device__ bf16  g_W2 [ 256 * 1024 ];

// ---------------- helpers ----------------------------------------------------
__device__ __forceinline__ float warp_sum(float v){
    #pragma unroll
    for (int o = 16; o; o >>= 1) v += __shfl_xor_sync(0xffffffffu, v, o);
    return v;
}
__device__ __forceinline__ uint32_t smem_u32(const void* p){
    uint32_t a;
    asm("{ .reg .u64 t; cvta.to.shared.u64 t, %1; cvt.u32.u64 %0, t; }"
        : "=r"(a) : "l"(p));
    return a;
}
__device__ __forceinline__ uint32_t pk(float a, float b){
    __nv_bfloat162 t = __floats2bfloat162_rn(a, b);
    return *(uint32_t*)&t;
}

#define LDSM_X4(r0,r1,r2,r3,addr) \
    asm volatile("ldmatrix.sync.aligned.m8n8.x4.shared.b16 {%0,%1,%2,%3}, [%4];" \
        : "=r"(r0), "=r"(r1), "=r"(r2), "=r"(r3) : "r"(addr))
#define LDSM_X4_T(r0,r1,r2,r3,addr) \
    asm volatile("ldmatrix.sync.aligned.m8n8.x4.trans.shared.b16 {%0,%1,%2,%3}, [%4];" \
        : "=r"(r0), "=r"(r1), "=r"(r2), "=r"(r3) : "r"(addr))

__device__ __forceinline__ void mma_bf16(float& c0, float& c1, float& c2, float& c3,
                                         uint32_t a0, uint32_t a1, uint32_t a2, uint32_t a3,
                                         uint32_t b0, uint32_t b1)
{
    asm volatile(
        "mma.sync.aligned.m16n8k16.row.col.f32.bf16.bf16.f32 "
        "{%0,%1,%2,%3}, {%4,%5,%6,%7}, {%8,%9}, {%0,%1,%2,%3};"
        : "+f"(c0), "+f"(c1), "+f"(c2), "+f"(c3)
        : "r"(a0), "r"(a1), "r"(a2), "r"(a3), "r"(b0), "r"(b1));
}

// ---------------- merged weight fp32 -> bf16 convert --------------------------
#define WQ_N (768*256)
#define WP_N (256*256)
#define W1_N (1024*256)
#define W2_N (256*1024)
__global__ void f2bf_all(const float* __restrict__ wq, const float* __restrict__ wp,
                         const float* __restrict__ w1, const float* __restrict__ w2)
{
    int i = (blockIdx.x * 256 + threadIdx.x) * 4;
    const float* s; bf16* d;
    if (i < WQ_N)                       { s = wq + i;  d = g_Wq + i; }
    else if ((i -= WQ_N) < WP_N)        { s = wp + i;  d = g_Wp + i; }
    else if ((i -= WP_N) < W1_N)        { s = w1 + i;  d = g_W1 + i; }
    else if ((i -= W1_N) < W2_N)        { s = w2 + i;  d = g_W2 + i; }
    else return;
    float4 v = *(const float4*)s;
    __nv_bfloat162* dp = (__nv_bfloat162*)d;
    dp[0] = __floats2bfloat162_rn(v.x, v.y);
    dp[1] = __floats2bfloat162_rn(v.z, v.w);
}

// ---------------- LN1 with shift + window gather (bf16 out) -------------------
__global__ void ln1_kernel(const float* __restrict__ x,
                           const float* __restrict__ g,
                           const float* __restrict__ be)
{
    const int warp = threadIdx.x >> 5, lane = threadIdx.x & 31;
    const int t = blockIdx.x * 8 + warp;
    const int n = t / WTOK, w = t - n * WTOK;
    const int b = n >> 5, f = n & 31;
    const int wf = w / 27;
    const int gf = f * 4 + wf;
    const int fr = (gf + 2) & 127;
    const int kp = w - wf * 27;
    const float* src = x + (size_t)((b * 128 + fr) * 27 + kp) * 256;

    float4 v0 = ((const float4*)src)[lane];
    float4 v1 = ((const float4*)src)[lane + 32];
    float s = v0.x+v0.y+v0.z+v0.w + v1.x+v1.y+v1.z+v1.w;
    float q = v0.x*v0.x+v0.y*v0.y+v0.z*v0.z+v0.w*v0.w
            + v1.x*v1.x+v1.y*v1.y+v1.z*v1.z+v1.w*v1.w;
    s = warp_sum(s); q = warp_sum(q);
    const float mean = s * (1.0f/256.0f);
    const float var  = q * (1.0f/256.0f) - mean*mean;
    const float rstd = rsqrtf(var + 1e-5f);

    __nv_bfloat162* dst = (__nv_bfloat162*)(g_XNh + (size_t)t * 256);
    const int c0 = lane*4, c1 = 128 + lane*4;
    dst[lane*2]        = __floats2bfloat162_rn((v0.x-mean)*rstd*g[c0+0] + be[c0+0],
                                               (v0.y-mean)*rstd*g[c0+1] + be[c0+1]);
    dst[lane*2+1]      = __floats2bfloat162_rn((v0.z-mean)*rstd*g[c0+2] + be[c0+2],
                                               (v0.w-mean)*rstd*g[c0+3] + be[c0+3]);
    dst[64 + lane*2]   = __floats2bfloat162_rn((v1.x-mean)*rstd*g[c1+0] + be[c1+0],
                                               (v1.y-mean)*rstd*g[c1+1] + be[c1+1]);
    dst[64 + lane*2+1] = __floats2bfloat162_rn((v1.z-mean)*rstd*g[c1+2] + be[c1+2],
                                               (v1.w-mean)*rstd*g[c1+3] + be[c1+3]);
}

// ---------------- bf16 mma.sync NT GEMM, 4 warps x 64x64 warp tile -----------
// CTA tile 128x128, 128 threads (2x2 warps), 3-stage cp.async pipeline.
// EPI: 0 = +bias, *0.125 for cols<256, bf16 out (QKV)
//      2 = +bias, exact GELU, bf16 out (FC1)
//      3 = +bias + Yres residual, fp32 out (FC2 -> final)
#define BUFB  16384
#define STGB  (2*BUFB)
#define GSMEM (3*STGB + 128)

template<int EPI>
__device__ __forceinline__ void epi_store(void* __restrict__ C,
                                          const float* __restrict__ Yres,
                                          int N, int m, int col,
                                          float v0, float v1)
{
    if (EPI == 0) {
        const float sc = (col < 256) ? 0.125f : 1.0f;
        *(__nv_bfloat162*)((bf16*)C + (size_t)m*N + col) =
            __floats2bfloat162_rn(v0*sc, v1*sc);
        return;
    }
    if (EPI == 2) {
        v0 = 0.5f*v0*(1.0f + erff(v0*0.70710678118654752f));
        v1 = 0.5f*v1*(1.0f + erff(v1*0.70710678118654752f));
        *(__nv_bfloat162*)((bf16*)C + (size_t)m*N + col) = __floats2bfloat162_rn(v0, v1);
        return;
    }
    if (EPI == 3) {
        const float2 yv = *(const float2*)&Yres[(size_t)m*N + col];
        v0 += yv.x; v1 += yv.y;
    }
    *(float2*)((float*)C + (size_t)m*N + col) = make_float2(v0, v1);
}

template<int EPI, int KD>
__global__ void __launch_bounds__(128, 2)
hgemm(const bf16* __restrict__ A, const bf16* __restrict__ Bw,
      const float* __restrict__ bias, const float* __restrict__ Yres,
      void* __restrict__ C, int N)
{
    extern __shared__ char smraw[];
    char* sm = (char*)(((uintptr_t)smraw + 127) & ~(uintptr_t)127);

    const int tid = threadIdx.x;
    const int wid = tid >> 5, lane = tid & 31;
    const int warpM = wid >> 1, warpN = wid & 1;   // 2 x 2, warp tile 64x64
    const int bn = blockIdx.x, bm = blockIdx.y;

    const bf16* Ab = A  + (size_t)bm * 128 * KD;
    const bf16* Bb = Bw + (size_t)bn * 128 * KD;

    const uint32_t smb = smem_u32(sm);

    const int aRow = (lane & 7) | (((lane >> 3) & 1) << 3);
    const int aK   = (lane >> 4) & 1;
    const int bRow = (lane & 7) | (((lane >> 4) & 1) << 3);
    const int bK   = (lane >> 3) & 1;

    float acc[4][8][4];
    #pragma unroll
    for (int i = 0; i < 4; i++)
        #pragma unroll
        for (int j = 0; j < 8; j++)
            #pragma unroll
            for (int q = 0; q < 4; q++) acc[i][j][q] = 0.0f;

    auto load_chunk = [&](int buf, int kbase){
        const uint32_t sa = smb + buf * STGB;
        const uint32_t sb = sa + BUFB;
        #pragma unroll
        for (int i = 0; i < 8; i++) {
            const int idx = tid + 128*i;
            const int row = idx >> 3, q = idx & 7;
            const uint32_t off = row*128 + ((q ^ (row & 7)) << 4);
            const size_t goff = (size_t)row*KD + kbase + q*8;
            asm volatile("cp.async.cg.shared.global [%0], [%1], 16;"
                         :: "r"(sa + off), "l"(Ab + goff));
            asm volatile("cp.async.cg.shared.global [%0], [%1], 16;"
                         :: "r"(sb + off), "l"(Bb + goff));
        }
        asm volatile("cp.async.commit_group;" ::: "memory");
    };

    constexpr int NC = KD / 64;
    load_chunk(0, 0);
    if (NC > 1) load_chunk(1, 64);

    for (int c = 0; c < NC; c++) {
        if (c + 1 < NC) asm volatile("cp.async.wait_group 1;" ::: "memory");
        else            asm volatile("cp.async.wait_group 0;" ::: "memory");
        __syncthreads();
        if (c + 2 < NC) load_chunk((c + 2) % 3, (c + 2) * 64);

        const uint32_t saA = smb + (c % 3) * STGB;
        const uint32_t saB = saA + BUFB;

        #pragma unroll
        for (int s = 0; s < 4; s++) {
            const int cch = s * 2;
            uint32_t a[4][4];
            #pragma unroll
            for (int mt = 0; mt < 4; mt++) {
                const int row = warpM*64 + mt*16 + aRow;
                const uint32_t off = row*128 + (((cch + aK) ^ (row & 7)) << 4);
                LDSM_X4(a[mt][0], a[mt][1], a[mt][2], a[mt][3], saA + off);
            }
            uint32_t b[8][2];
            #pragma unroll
            for (int p = 0; p < 4; p++) {
                const int row = warpN*64 + p*16 + bRow;
                const uint32_t off = row*128 + (((cch + bK) ^ (row & 7)) << 4);
                LDSM_X4(b[2*p][0], b[2*p][1], b[2*p+1][0], b[2*p+1][1], saB + off);
            }
            #pragma unroll
            for (int mt = 0; mt < 4; mt++)
                #pragma unroll
                for (int nt = 0; nt < 8; nt++)
                    mma_bf16(acc[mt][nt][0], acc[mt][nt][1],
                             acc[mt][nt][2], acc[mt][nt][3],
                             a[mt][0], a[mt][1], a[mt][2], a[mt][3],
                             b[nt][0], b[nt][1]);
        }
    }

    const int g = lane >> 2, t = lane & 3;
    #pragma unroll
    for (int mt = 0; mt < 4; mt++) {
        const int r0 = bm*128 + warpM*64 + mt*16 + g;
        #pragma unroll
        for (int nt = 0; nt < 8; nt++) {
            const int col = bn*128 + warpN*64 + nt*8 + t*2;
            const float2 bv = *(const float2*)&bias[col];
            epi_store<EPI>(C, Yres, N, r0,     col,
                           acc[mt][nt][0] + bv.x, acc[mt][nt][1] + bv.y);
            epi_store<EPI>(C, Yres, N, r0 + 8, col,
                           acc[mt][nt][2] + bv.x, acc[mt][nt][3] + bv.y);
        }
    }
}

// ---------------- fused proj GEMM + roll + residual + LN2 ---------------------
#define PSTG   49152
#define PSUMS  (3*PSTG)
#define PSMEM  (PSUMS + 8192 + 128)

__global__ void __launch_bounds__(512)
proj_ln2(const bf16* __restrict__ A, const bf16* __restrict__ Bw,
         const float* __restrict__ bias, const float* __restrict__ x,
         float* __restrict__ Y, bf16* __restrict__ XNh,
         const float* __restrict__ g2, const float* __restrict__ be2)
{
    extern __shared__ char smraw[];
    char* sm = (char*)(((uintptr_t)smraw + 127) & ~(uintptr_t)127);
    const uint32_t smb = smem_u32(sm);
    float* sums = (float*)(sm + PSUMS);

    const int tid = threadIdx.x;
    const int wid = tid >> 5, lane = tid & 31;
    const int warpM = wid >> 3, warpN = wid & 7;   // 2 x 8
    const int bm = blockIdx.x;
    constexpr int KD = 256;

    const bf16* Ab = A + (size_t)bm * 128 * KD;

    const int aRow = (lane & 7) | (((lane >> 3) & 1) << 3);
    const int aK   = (lane >> 4) & 1;
    const int bRow = (lane & 7) | (((lane >> 4) & 1) << 3);
    const int bK   = (lane >> 3) & 1;

    float acc[4][4][4];
    #pragma unroll
    for (int i = 0; i < 4; i++)
        #pragma unroll
        for (int j = 0; j < 4; j++)
            #pragma unroll
            for (int q = 0; q < 4; q++) acc[i][j][q] = 0.0f;

    auto load_chunk = [&](int buf, int kbase){
        const uint32_t sa = smb + buf * PSTG;
        #pragma unroll
        for (int i = 0; i < 6; i++) {
            const int idx = tid + 512*i;
            const int row = idx >> 3, q = idx & 7;
            if (row < 128) {
                const uint32_t off = row*128 + ((q ^ (row & 7)) << 4);
                asm volatile("cp.async.cg.shared.global [%0], [%1], 16;"
                             :: "r"(sa + off), "l"(Ab + (size_t)row*KD + kbase + q*8));
            } else {
                const int br = row - 128;
                const uint32_t off = 16384 + br*128 + ((q ^ (br & 7)) << 4);
                asm volatile("cp.async.cg.shared.global [%0], [%1], 16;"
                             :: "r"(sa + off), "l"(Bw + (size_t)br*KD + kbase + q*8));
            }
        }
        asm volatile("cp.async.commit_group;" ::: "memory");
    };

    load_chunk(0, 0);
    load_chunk(1, 64);

    for (int c = 0; c < 4; c++) {
        if (c < 3) asm volatile("cp.async.wait_group 1;" ::: "memory");
        else       asm volatile("cp.async.wait_group 0;" ::: "memory");
        __syncthreads();
        if (c + 2 < 4) load_chunk((c + 2) % 3, (c + 2) * 64);

        const uint32_t saA = smb + (c % 3) * PSTG;
        const uint32_t saB = saA + 16384;

        #pragma unroll
        for (int s = 0; s < 4; s++) {
            const int cch = s * 2;
            uint32_t a[4][4];
            #pragma unroll
            for (int mt = 0; mt < 4; mt++) {
                const int row = warpM*64 + mt*16 + aRow;
                const uint32_t off = row*128 + (((cch + aK) ^ (row & 7)) << 4);
                LDSM_X4(a[mt][0], a[mt][1], a[mt][2], a[mt][3], saA + off);
            }
            uint32_t b[4][2];
            #pragma unroll
            for (int p = 0; p < 2; p++) {
                const int row = warpN*32 + p*16 + bRow;
                const uint32_t off = row*128 + (((cch + bK) ^ (row & 7)) << 4);
                LDSM_X4(b[2*p][0], b[2*p][1], b[2*p+1][0], b[2*p+1][1], saB + off);
            }
            #pragma unroll
            for (int mt = 0; mt < 4; mt++)
                #pragma unroll
                for (int nt = 0; nt < 4; nt++)
                    mma_bf16(acc[mt][nt][0], acc[mt][nt][1],
                             acc[mt][nt][2], acc[mt][nt][3],
                             a[mt][0], a[mt][1], a[mt][2], a[mt][3],
                             b[nt][0], b[nt][1]);
        }
    }

    // ---- epilogue: bias + roll + residual, partial row sums ----
    const int g = lane >> 2, t4 = lane & 3;
    int mo[4][2];
    #pragma unroll
    for (int mt = 0; mt < 4; mt++) {
        const int lr0 = warpM*64 + mt*16 + g;
        #pragma unroll
        for (int half = 0; half < 2; half++) {
            const int m = bm*128 + lr0 + half*8;
            const int nw = m / WTOK, w = m - nw * WTOK;
            int w2 = w + 2; if (w2 >= WTOK) w2 -= WTOK;
            mo[mt][half] = nw * WTOK + w2;
        }
        float s0 = 0.f, q0 = 0.f, s1 = 0.f, q1 = 0.f;
        #pragma unroll
        for (int nt = 0; nt < 4; nt++) {
            const int col = warpN*32 + nt*8 + t4*2;
            const float2 bv = *(const float2*)&bias[col];
            const float2 x0 = *(const float2*)&x[(size_t)mo[mt][0]*256 + col];
            const float2 x1 = *(const float2*)&x[(size_t)mo[mt][1]*256 + col];
            float y00 = acc[mt][nt][0] + bv.x + x0.x;
            float y01 = acc[mt][nt][1] + bv.y + x0.y;
            float y10 = acc[mt][nt][2] + bv.x + x1.x;
            float y11 = acc[mt][nt][3] + bv.y + x1.y;
            acc[mt][nt][0] = y00; acc[mt][nt][1] = y01;
            acc[mt][nt][2] = y10; acc[mt][nt][3] = y11;
            s0 += y00 + y01; q0 += y00*y00 + y01*y01;
            s1 += y10 + y11; q1 += y10*y10 + y11*y11;
        }
        #pragma unroll
        for (int ofs = 1; ofs <= 2; ofs <<= 1) {
            s0 += __shfl_xor_sync(0xffffffffu, s0, ofs);
            q0 += __shfl_xor_sync(0xffffffffu, q0, ofs);
            s1 += __shfl_xor_sync(0xffffffffu, s1, ofs);
            q1 += __shfl_xor_sync(0xffffffffu, q1, ofs);
        }
        if (t4 == 0) {
            sums[(lr0*8     + warpN)*2    ] = s0;
            sums[(lr0*8     + warpN)*2 + 1] = q0;
            sums[((lr0+8)*8 + warpN)*2    ] = s1;
            sums[((lr0+8)*8 + warpN)*2 + 1] = q1;
        }
    }
    __syncthreads();

    // ---- finish LN per row, write Y + XNh ----
    #pragma unroll
    for (int mt = 0; mt < 4; mt++) {
        const int lr0 = warpM*64 + mt*16 + g;
        float s0 = 0.f, q0 = 0.f, s1 = 0.f, q1 = 0.f;
        #pragma unroll
        for (int wn = 0; wn < 8; wn++) {
            s0 += sums[(lr0*8     + wn)*2    ];
            q0 += sums[(lr0*8     + wn)*2 + 1];
            s1 += sums[((lr0+8)*8 + wn)*2    ];
            q1 += sums[((lr0+8)*8 + wn)*2 + 1];
        }
        const float mean0 = s0 * (1.0f/256.0f);
        const float var0  = q0 * (1.0f/256.0f) - mean0*mean0;
        const float rs0   = rsqrtf(var0 + 1e-5f);
        const float mean1 = s1 * (1.0f/256.0f);
        const float var1  = q1 * (1.0f/256.0f) - mean1*mean1;
        const float rs1   = rsqrtf(var1 + 1e-5f);
        #pragma unroll
        for (int nt = 0; nt < 4; nt++) {
            const int col = warpN*32 + nt*8 + t4*2;
            const float2 gv = *(const float2*)&g2[col];
            const float2 bv = *(const float2*)&be2[col];
            const float y00 = acc[mt][nt][0], y01 = acc[mt][nt][1];
            const float y10 = acc[mt][nt][2], y11 = acc[mt][nt][3];
            *(float2*)&Y[(size_t)mo[mt][0]*256 + col] = make_float2(y00, y01);
            *(float2*)&Y[(size_t)mo[mt][1]*256 + col] = make_float2(y10, y11);
            *(uint32_t*)(XNh + (size_t)mo[mt][0]*256 + col) =
                pk((y00-mean0)*rs0*gv.x + bv.x, (y01-mean0)*rs0*gv.y + bv.y);
            *(uint32_t*)(XNh + (size_t)mo[mt][1]*256 + col) =
                pk((y10-mean1)*rs1*gv.x + bv.x, (y11-mean1)*rs1*gv.y + bv.y);
        }
    }
}

// ---------------- tensor-core windowed attention ------------------------------
// Block = (window, head), 256 thr (8 warps, warp w = tile w, tile 7 idle).
// Q/K/V gathered via cp.async (global->smem direct). P aliases Q+K post S-phase.
#define SMK 14336
#define SMV 28672
#define SMRGN 43008
#define ATTN_SMEM (43008 + 512)

__global__ void __launch_bounds__(256, 3)
attn_kernel(const bf16* __restrict__ qkv,
            const float* __restrict__ eb,
            bf16* __restrict__ o)
{
    extern __shared__ char smraw[];
    const uint32_t smb = smem_u32(smraw);
    int* rgn = (int*)(smraw + SMRGN);

    const int n = blockIdx.x, h = blockIdx.y;
    const int tid = threadIdx.x, warp = tid >> 5, lane = tid & 31;
    const int f = n & 31;
    const size_t base = (size_t)n * WTOK * 768;

    // Q(prescaled)/K/V gather via cp.async; zero-pad rows 108..111 via STS
    for (int idx = tid; idx < WTOK*8; idx += 256) {
        const int row = idx >> 3, q = idx & 7;
        const uint32_t off = row*128 + ((q ^ (row & 7)) << 4);
        const bf16* rp = qkv + base + (size_t)row * 768 + h*64 + q*8;
        asm volatile("cp.async.cg.shared.global [%0], [%1], 16;"
                     :: "r"(smb + off), "l"(rp));
        asm volatile("cp.async.cg.shared.global [%0], [%1], 16;"
                     :: "r"(smb + SMK + off), "l"(rp + 256));
        asm volatile("cp.async.cg.shared.global [%0], [%1], 16;"
                     :: "r"(smb + SMV + off), "l"(rp + 512));
    }
    // pad rows 108..111
    if (tid < 32) {
        const int row = WTOK + (tid >> 3), q = tid & 7;
        const uint32_t off = row*128 + ((q ^ (row & 7)) << 4);
        const uint4 z = {0,0,0,0};
        *(uint4*)(smraw + off)       = z;
        *(uint4*)(smraw + SMK + off) = z;
        *(uint4*)(smraw + SMV + off) = z;
    }
    for (int w = tid; w < 112; w += 256) {
        if (w < WTOK) {
            const int gf = f * 4 + w / 27;
            rgn[w] = (gf >= 126) ? 2 : ((gf >= 124) ? 1 : 0);
        } else rgn[w] = -1;
    }
    asm volatile("cp.async.commit_group;" ::: "memory");
    asm volatile("cp.async.wait_group 0;" ::: "memory");
    __syncthreads();

    const int aRow = (lane & 7) | (((lane >> 3) & 1) << 3);
    const int aK   = (lane >> 4) & 1;
    const int bRow = (lane & 7) | (((lane >> 4) & 1) << 3);
    const int bK   = (lane >> 3) & 1;
    const int g = lane >> 2, t4 = lane & 3;

    const int mt = warp;
    float sacc[14][4];

    // ---- S = Q @ K^T ----
    if (mt < 7) {
        #pragma unroll
        for (int nt = 0; nt < 14; nt++)
            #pragma unroll
            for (int q = 0; q < 4; q++) sacc[nt][q] = 0.0f;

        #pragma unroll
        for (int s = 0; s < 4; s++) {
            const int cch = 2*s;
            uint32_t a0,a1,a2,a3;
            {
                const int row = mt*16 + aRow;
                const uint32_t off = row*128 + (((cch + aK) ^ (row & 7)) << 4);
                LDSM_X4(a0,a1,a2,a3, smb + off);
            }
            uint32_t bq[14][2];
            #pragma unroll
            for (int p = 0; p < 7; p++) {
                const int row = p*16 + bRow;
                const uint32_t off = row*128 + (((cch + bK) ^ (row & 7)) << 4);
                LDSM_X4(bq[2*p][0], bq[2*p][1], bq[2*p+1][0], bq[2*p+1][1],
                        smb + SMK + off);
            }
            #pragma unroll
            for (int nt = 0; nt < 14; nt++)
                mma_bf16(sacc[nt][0], sacc[nt][1], sacc[nt][2], sacc[nt][3],
                         a0,a1,a2,a3, bq[nt][0], bq[nt][1]);
        }
    }
    __syncthreads();          // Q, K now dead -> P may alias them

    if (mt < 7) {
        // ---- softmax (reference quirks) ----
        const int r0 = mt*16 + g, r1 = r0 + 8;
        const int rq0 = rgn[r0], rq1 = rgn[r1];
        #pragma unroll
        for (int nt = 0; nt < 14; nt++) {
            const int j0 = nt*8 + t4*2;
            const bool jc = j0 < WTOK;
            float2 e0 = make_float2(0.f,0.f), e1 = make_float2(0.f,0.f);
            if (jc)              e0 = *(const float2*)(eb + r0*WTOK + j0);
            if (jc && r1 < WTOK) e1 = *(const float2*)(eb + r1*WTOK + j0);
            const int rj0 = rgn[j0], rj1 = rgn[j0+1];
            float av;
            av = (rj0==rq0) ? sacc[nt][0]*e0.x : 0.f;
            sacc[nt][0] = jc ? ((av==0.f) ? 10000.0f : -av) : -3.0e38f;
            av = (rj1==rq0) ? sacc[nt][1]*e0.y : 0.f;
            sacc[nt][1] = jc ? ((av==0.f) ? 10000.0f : -av) : -3.0e38f;
            av = (rj0==rq1) ? sacc[nt][2]*e1.x : 0.f;
            sacc[nt][2] = jc ? ((av==0.f) ? 10000.0f : -av) : -3.0e38f;
            av = (rj1==rq1) ? sacc[nt][3]*e1.y : 0.f;
            sacc[nt][3] = jc ? ((av==0.f) ? 10000.0f : -av) : -3.0e38f;
        }
        float m0 = -3.0e38f, m1 = -3.0e38f;
        #pragma unroll
        for (int nt = 0; nt < 14; nt++) {
            m0 = fmaxf(m0, fmaxf(sacc[nt][0], sacc[nt][1]));
            m1 = fmaxf(m1, fmaxf(sacc[nt][2], sacc[nt][3]));
        }
        #pragma unroll
        for (int ofs = 1; ofs <= 2; ofs <<= 1) {
            m0 = fmaxf(m0, __shfl_xor_sync(0xffffffffu, m0, ofs));
            m1 = fmaxf(m1, __shfl_xor_sync(0xffffffffu, m1, ofs));
        }
        float s0 = 0.f, s1 = 0.f;
        #pragma unroll
        for (int nt = 0; nt < 14; nt++) {
            sacc[nt][0] = expf(sacc[nt][0] - m0); s0 += sacc[nt][0];
            sacc[nt][1] = expf(sacc[nt][1] - m0); s0 += sacc[nt][1];
            sacc[nt][2] = expf(sacc[nt][2] - m1); s1 += sacc[nt][2];
            sacc[nt][3] = expf(sacc[nt][3] - m1); s1 += sacc[nt][3];
        }
        #pragma unroll
        for (int ofs = 1; ofs <= 2; ofs <<= 1) {
            s0 += __shfl_xor_sync(0xffffffffu, s0, ofs);
            s1 += __shfl_xor_sync(0xffffffffu, s1, ofs);
        }
        const float i0 = 1.0f / s0, i1 = 1.0f / s1;

        // store P (bf16) at base 0 (aliases dead Q/K); warp-private rows
        #pragma unroll
        for (int nt = 0; nt < 14; nt++) {
            const uint32_t chi = (uint32_t)(nt >> 3) << 7;
            const uint32_t a0off = r0*256 + chi + ((((uint32_t)nt & 7) ^ (r0 & 7)) << 4) + t4*4;
            const uint32_t a1off = r1*256 + chi + ((((uint32_t)nt & 7) ^ (r1 & 7)) << 4) + t4*4;
            *(uint32_t*)(smraw + a0off) = pk(sacc[nt][0]*i0, sacc[nt][1]*i0);
            *(uint32_t*)(smraw + a1off) = pk(sacc[nt][2]*i1, sacc[nt][3]*i1);
        }
        __syncwarp();

        // ---- O = P @ V ----
        float oacc[8][4];
        #pragma unroll
        for (int nt = 0; nt < 8; nt++)
            #pragma unroll
            for (int q = 0; q < 4; q++) oacc[nt][q] = 0.0f;

        #pragma unroll
        for (int sp = 0; sp < 7; sp++) {
            uint32_t a0,a1,a2,a3;
            {
                const int row = mt*16 + aRow;
                const int c = 2*sp + aK;
                const uint32_t off = row*256 + ((uint32_t)(c >> 3) << 7)
                                   + ((((uint32_t)c & 7) ^ (row & 7)) << 4);
                LDSM_X4(a0,a1,a2,a3, smb + off);
            }
            uint32_t bv[8][2];
            #pragma unroll
            for (int ntp = 0; ntp < 4; ntp++) {
                const int vrow = sp*16 + (lane & 7) + 8*((lane >> 3) & 1);
                const int ch = ntp*2 + ((lane >> 4) & 1);
                const uint32_t off = vrow*128 + (((uint32_t)ch ^ (vrow & 7)) << 4);
                LDSM_X4_T(bv[2*ntp][0], bv[2*ntp][1], bv[2*ntp+1][0], bv[2*ntp+1][1],
                          smb + SMV + off);
            }
            #pragma unroll
            for (int nt = 0; nt < 8; nt++)
                mma_bf16(oacc[nt][0], oacc[nt][1], oacc[nt][2], oacc[nt][3],
                         a0,a1,a2,a3, bv[nt][0], bv[nt][1]);
        }

        // ---- write O (bf16) ----
        bf16* ob = o + ((size_t)n * WTOK) * 256 + h*64;
        #pragma unroll
        for (int nt = 0; nt < 8; nt++) {
            const int col = nt*8 + t4*2;
            *(uint32_t*)(ob + (size_t)r0*256 + col) = pk(oacc[nt][0], oacc[nt][1]);
            if (r1 < WTOK)
                *(uint32_t*)(ob + (size_t)r1*256 + col) = pk(oacc[nt][2], oacc[nt][3]);
        }
    }
}

// ---------------- launch ------------------------------------------------------
extern "C" void kernel_launch(void* const* d_in, const int* in_sizes, int n_in,
                              void* d_out, int out_size)
{
    const float* x      = (const float*)d_in[0];
    const float* eb     = (const float*)d_in[1];
    const float* w_qkv  = (const float*)d_in[2];
    const float* b_qkv  = (const float*)d_in[3];
    const float* w_proj = (const float*)d_in[4];
    const float* b_proj = (const float*)d_in[5];
    const float* g1     = (const float*)d_in[6];
    const float* be1    = (const float*)d_in[7];
    const float* g2     = (const float*)d_in[8];
    const float* be2    = (const float*)d_in[9];
    const float* w_fc1  = (const float*)d_in[10];
    const float* b_fc1  = (const float*)d_in[11];
    const float* w_fc2  = (const float*)d_in[12];
    const float* b_fc2  = (const float*)d_in[13];
    float* out = (float*)d_out;

    float *Y;
    bf16 *QKVh, *XNh, *Oh, *H1h, *Wq, *Wp, *W1, *W2;
    cudaGetSymbolAddress((void**)&QKVh, g_QKVh);
    cudaGetSymbolAddress((void**)&Y,   g_Y);
    cudaGetSymbolAddress((void**)&XNh, g_XNh);
    cudaGetSymbolAddress((void**)&Oh,  g_Oh);
    cudaGetSymbolAddress((void**)&H1h, g_H1h);
    cudaGetSymbolAddress((void**)&Wq,  g_Wq);
    cudaGetSymbolAddress((void**)&Wp,  g_Wp);
    cudaGetSymbolAddress((void**)&W1,  g_W1);
    cudaGetSymbolAddress((void**)&W2,  g_W2);

    cudaFuncSetAttribute(attn_kernel,
                         cudaFuncAttributeMaxDynamicSharedMemorySize, ATTN_SMEM);
    cudaFuncSetAttribute(proj_ln2,
                         cudaFuncAttributeMaxDynamicSharedMemorySize, PSMEM);
    cudaFuncSetAttribute(hgemm<0,256>,  cudaFuncAttributeMaxDynamicSharedMemorySize, GSMEM);
    cudaFuncSetAttribute(hgemm<2,256>,  cudaFuncAttributeMaxDynamicSharedMemorySize, GSMEM);
    cudaFuncSetAttribute(hgemm<3,1024>, cudaFuncAttributeMaxDynamicSharedMemorySize, GSMEM);

    // 0) weights fp32 -> bf16 (single merged launch)
    f2bf_all<<<(WQ_N + WP_N + W1_N + W2_N) / 4 / 256, 256>>>(w_qkv, w_proj, w_fc1, w_fc2);

    // 1) shift + window + LN1 (bf16 out)
    ln1_kernel<<<NTOK / 8, 256>>>(x, g1, be1);
    // 2) QKV GEMM -> bf16 (q pre-scaled by 0.125 in epilogue)
    hgemm<0,256><<<dim3(6, NTOK/128), 128, GSMEM>>>(XNh, Wq, b_qkv, nullptr, QKVh, 768);
    // 3) attention (tensor cores, cp.async gather, P aliases Q/K)
    attn_kernel<<<dim3(NWIN, 4), 256, ATTN_SMEM>>>(QKVh, eb, Oh);
    // 4) fused proj + roll + residual + LN2 -> Y (fp32), XNh (bf16)
    proj_ln2<<<NTOK/128, 512, PSMEM>>>(Oh, Wp, b_proj, x, Y, XNh, g2, be2);
    // 5) FC1 + GELU
    hgemm<2,256><<<dim3(8, NTOK/128), 128, GSMEM>>>(XNh, W1, b_fc1, nullptr, H1h, 1024);
    // 6) FC2 + residual -> output
    hgemm<3,1024><<<dim3(2, NTOK/128), 128, GSMEM>>>(H1h, W2, b_fc2, Y, out, 256);
}